// round 1
// baseline (speedup 1.0000x reference)
#include <cuda_runtime.h>
#include <cuda_bf16.h>
#include <math.h>

// ---------------- Problem constants ----------------
#define T_SEQ  2048
#define BATCH  2
#define NHEADS 16
#define NKVH   4
#define HD     128
#define DIM    2048
#define RANK   512
#define M_ROWS (BATCH * T_SEQ)         // 4096
#define EPS_F  1.1920928955078125e-07f
#define SCALE_F 0.08838834764831845f   // 1/sqrt(128)

// ---------------- Scratch (static device globals; no allocation) ----------------
__device__ float g_q  [(size_t)M_ROWS * DIM];    // x @ Wq^T
__device__ float g_lat[(size_t)M_ROWS * RANK];   // x @ Wdown^T
__device__ float g_kt [(size_t)M_ROWS * RANK];   // lat @ Wkup^T
__device__ float g_vt [(size_t)M_ROWS * RANK];   // lat @ Wvup^T  (read directly by attention)
__device__ float g_qa [(size_t)M_ROWS * DIM];    // q after rmsnorm+rope, layout [B,NH,T,HD]
__device__ float g_ka [(size_t)M_ROWS * RANK];   // k after rmsnorm+rope, layout [B,NKV,T,HD]
__device__ float g_y  [(size_t)M_ROWS * DIM];    // attention out, layout [B,T,DIM]

// ---------------- SGEMM: C[M,N] = A[M,K] @ W[N,K]^T  (both row-major, NT) ----------------
// 128x128 tile, BK=8, 256 threads, 8x8 per-thread register tile.
__global__ __launch_bounds__(256) void sgemm_nt(
    const float* __restrict__ A, const float* __restrict__ W,
    float* __restrict__ C, int M, int N, int K)
{
    __shared__ float As[8][128];
    __shared__ float Ws[8][128];
    const int tid = threadIdx.x;
    const int bm = blockIdx.y * 128;
    const int bn = blockIdx.x * 128;
    const int tr = (tid >> 4) << 3;   // row base within tile (0..120)
    const int tc = (tid & 15) << 3;   // col base within tile
    const int lr = tid >> 1;          // load row 0..127
    const int lk = (tid & 1) << 2;    // load k-offset 0 or 4

    const float* Aptr = A + (size_t)(bm + lr) * K + lk;
    const float* Wptr = W + (size_t)(bn + lr) * K + lk;

    float acc[8][8];
#pragma unroll
    for (int i = 0; i < 8; i++)
#pragma unroll
        for (int j = 0; j < 8; j++) acc[i][j] = 0.f;

    for (int k0 = 0; k0 < K; k0 += 8) {
        float4 av = *(const float4*)(Aptr + k0);
        float4 wv = *(const float4*)(Wptr + k0);
        As[lk + 0][lr] = av.x; As[lk + 1][lr] = av.y;
        As[lk + 2][lr] = av.z; As[lk + 3][lr] = av.w;
        Ws[lk + 0][lr] = wv.x; Ws[lk + 1][lr] = wv.y;
        Ws[lk + 2][lr] = wv.z; Ws[lk + 3][lr] = wv.w;
        __syncthreads();
#pragma unroll
        for (int kk = 0; kk < 8; kk++) {
            float a[8], w[8];
#pragma unroll
            for (int i = 0; i < 8; i++) a[i] = As[kk][tr + i];
#pragma unroll
            for (int j = 0; j < 8; j++) w[j] = Ws[kk][tc + j];
#pragma unroll
            for (int i = 0; i < 8; i++)
#pragma unroll
                for (int j = 0; j < 8; j++) acc[i][j] += a[i] * w[j];
        }
        __syncthreads();
    }
#pragma unroll
    for (int i = 0; i < 8; i++) {
        float4* Crow = (float4*)(C + (size_t)(bm + tr + i) * N + bn + tc);
        Crow[0] = make_float4(acc[i][0], acc[i][1], acc[i][2], acc[i][3]);
        Crow[1] = make_float4(acc[i][4], acc[i][5], acc[i][6], acc[i][7]);
    }
}

// ---------------- RMSNorm + RoPE (+gain) per (row, head) ----------------
// src: [M_ROWS, nheads*HD] row-major; dst: [B, nheads, T, HD]
__global__ void rms_rope_kernel(const float* __restrict__ src, float* __restrict__ dst,
                                const float* __restrict__ gain, int nheads)
{
    const int m = blockIdx.x;
    const int h = blockIdx.y;
    const int d = threadIdx.x;   // 0..127
    const int b = m / T_SEQ, t = m % T_SEQ;

    float x = src[(size_t)m * ((size_t)nheads * HD) + h * HD + d];
    float ss = x * x;
#pragma unroll
    for (int o = 16; o > 0; o >>= 1) ss += __shfl_xor_sync(0xffffffffu, ss, o);
    __shared__ float red[4];
    __shared__ float sv[HD];
    if ((d & 31) == 0) red[d >> 5] = ss;
    __syncthreads();
    float tot = red[0] + red[1] + red[2] + red[3];
    float r = rsqrtf(tot * (1.0f / HD) + EPS_F);
    sv[d] = x * r;
    __syncthreads();
    if (d < 64) {
        float x1 = sv[d], x2 = sv[d + 64];
        float fr = powf(10000.0f, -(float)d * (1.0f / 64.0f));
        float ang = (float)t * fr;
        float sn, cs;
        sincosf(ang, &sn, &cs);
        float g = gain ? gain[h] : 1.0f;
        size_t base = ((size_t)(b * nheads + h) * T_SEQ + t) * HD;
        dst[base + d]       = (x1 * cs + x2 * sn) * g;
        dst[base + 64 + d]  = (x2 * cs - x1 * sn) * g;
    }
}

// ---------------- Flash attention (fp32, causal, GQA) ----------------
// Q: [B,NH,T,HD], K: [B,NKV,T,HD], V: g_vt layout [B*T, RANK] (col = kvh*HD + d)
// Y: [B,T,DIM] (col = h*HD + d)
#define FA_BQ 64
#define FA_BK 64
#define FA_SMEM_FLOATS (3 * 64 * 132 + 64 * 68 + 3 * 64)
#define FA_SMEM_BYTES  (FA_SMEM_FLOATS * 4)

__global__ __launch_bounds__(256) void flash_kernel(
    const float* __restrict__ Q, const float* __restrict__ Kt,
    const float* __restrict__ Vt, float* __restrict__ Y)
{
    extern __shared__ float sm[];
    float (*Qs)[132] = (float(*)[132])sm;                    // 64 x 132
    float (*Ks)[132] = (float(*)[132])(sm + 64 * 132);
    float (*Vs)[132] = (float(*)[132])(sm + 2 * 64 * 132);   // swizzled by 16B-group transpose
    float (*Ss)[68]  = (float(*)[68])(sm + 3 * 64 * 132);
    float* mrow = sm + 3 * 64 * 132 + 64 * 68;
    float* lrow = mrow + 64;
    float* arow = lrow + 64;

    const int tid = threadIdx.x;
    const int qt = blockIdx.x, h = blockIdx.y, b = blockIdx.z;
    const int kh = h >> 2;                 // NH/NKV = 4
    const int q0 = qt * FA_BQ;

    const float* Qp    = Q  + ((size_t)(b * NHEADS + h) * T_SEQ + q0) * HD;
    const float* Kp    = Kt + ((size_t)(b * NKVH + kh) * T_SEQ) * HD;
    const float* Vbase = Vt + (size_t)b * T_SEQ * RANK + kh * HD;

    // Load Q tile (64x128 floats = 2048 float4)
    for (int i = tid; i < FA_BQ * HD / 4; i += 256) {
        float4 v = ((const float4*)Qp)[i];
        int r = i >> 5, c = (i & 31) << 2;
        *(float4*)&Qs[r][c] = v;
    }
    if (tid < 64) { mrow[tid] = -1e30f; lrow[tid] = 0.f; }

    float o[32];
#pragma unroll
    for (int j = 0; j < 32; j++) o[j] = 0.f;

    const int ro = tid >> 2;          // PV row (0..63)
    const int cq = tid & 3;           // PV col-group (cols cq*32 .. +31)
    const int sr = (tid >> 4) << 2;   // S row base
    const int sc = tid & 15;          // S col lane (cols sc + 16*j)

    __syncthreads();

    const int ntiles = qt + 1;
    for (int kt = 0; kt < ntiles; kt++) {
        const int k0 = kt * FA_BK;
        const float* Kpt = Kp + (size_t)k0 * HD;
        // K tile
        for (int i = tid; i < FA_BK * HD / 4; i += 256) {
            float4 v = ((const float4*)Kpt)[i];
            int r = i >> 5, c = (i & 31) << 2;
            *(float4*)&Ks[r][c] = v;
        }
        // V tile with 16B-group transpose swizzle: group g -> ((g&7)<<2)|(g>>3)
        for (int i = tid; i < FA_BK * HD / 4; i += 256) {
            int r = i >> 5, g = i & 31;
            float4 v = ((const float4*)(Vbase + (size_t)(k0 + r) * RANK))[g];
            int gs = ((g & 7) << 2) | (g >> 3);
            *(((float4*)&Vs[r][0]) + gs) = v;
        }
        __syncthreads();

        // S = Q K^T (64x64), per-thread 4x4
        float s[4][4];
#pragma unroll
        for (int i = 0; i < 4; i++)
#pragma unroll
            for (int j = 0; j < 4; j++) s[i][j] = 0.f;

        for (int d = 0; d < HD; d += 4) {
            float4 qv[4], kv[4];
#pragma unroll
            for (int i = 0; i < 4; i++) qv[i] = *(const float4*)&Qs[sr + i][d];
#pragma unroll
            for (int j = 0; j < 4; j++) kv[j] = *(const float4*)&Ks[sc + 16 * j][d];
#pragma unroll
            for (int i = 0; i < 4; i++)
#pragma unroll
                for (int j = 0; j < 4; j++)
                    s[i][j] += qv[i].x * kv[j].x + qv[i].y * kv[j].y
                             + qv[i].z * kv[j].z + qv[i].w * kv[j].w;
        }
#pragma unroll
        for (int i = 0; i < 4; i++)
#pragma unroll
            for (int j = 0; j < 4; j++) {
                float val = s[i][j] * SCALE_F;
                int qg = q0 + sr + i, kg = k0 + sc + 16 * j;
                if (kg > qg) val = -1e30f;
                Ss[sr + i][sc + 16 * j] = val;
            }
        __syncthreads();

        // Online softmax row pass (threads 0..63, one row each)
        if (tid < 64) {
            float mold = mrow[tid];
            float rmax = mold;
#pragma unroll 8
            for (int c = 0; c < FA_BK; c++) rmax = fmaxf(rmax, Ss[tid][c]);
            float alpha = __expf(mold - rmax);
            float rsum = 0.f;
#pragma unroll 8
            for (int c = 0; c < FA_BK; c++) {
                float p = __expf(Ss[tid][c] - rmax);
                Ss[tid][c] = p;
                rsum += p;
            }
            lrow[tid] = lrow[tid] * alpha + rsum;
            mrow[tid] = rmax;
            arow[tid] = alpha;
        }
        __syncthreads();

        // O += P V  (thread owns row ro, cols cq*32..+31)
        float alpha = arow[ro];
#pragma unroll
        for (int j = 0; j < 32; j++) o[j] *= alpha;
        for (int kk = 0; kk < FA_BK; kk++) {
            float p = Ss[ro][kk];
#pragma unroll
            for (int j4 = 0; j4 < 8; j4++) {
                float4 v = *(((const float4*)&Vs[kk][0]) + ((j4 << 2) | cq));
                o[4 * j4 + 0] += p * v.x;
                o[4 * j4 + 1] += p * v.y;
                o[4 * j4 + 2] += p * v.z;
                o[4 * j4 + 3] += p * v.w;
            }
        }
        __syncthreads();
    }

    // Epilogue: normalize + store to [B,T,DIM]
    float inv = 1.0f / lrow[ro];
    float* Yp = Y + ((size_t)(b * T_SEQ) + q0 + ro) * DIM + h * HD + cq * 32;
#pragma unroll
    for (int j4 = 0; j4 < 8; j4++) {
        *(float4*)&Yp[4 * j4] = make_float4(o[4 * j4 + 0] * inv, o[4 * j4 + 1] * inv,
                                            o[4 * j4 + 2] * inv, o[4 * j4 + 3] * inv);
    }
}

// ---------------- Launch ----------------
extern "C" void kernel_launch(void* const* d_in, const int* in_sizes, int n_in,
                              void* d_out, int out_size)
{
    (void)in_sizes; (void)n_in; (void)out_size;
    const float* x     = (const float*)d_in[0];
    const float* Wq    = (const float*)d_in[1];
    const float* Wdown = (const float*)d_in[2];
    const float* Wkup  = (const float*)d_in[3];
    const float* Wvup  = (const float*)d_in[4];
    const float* Wproj = (const float*)d_in[5];
    const float* qgain = (const float*)d_in[6];
    float* out = (float*)d_out;

    float *q, *lat, *kt, *vt, *qa, *ka, *y;
    cudaGetSymbolAddress((void**)&q,   g_q);
    cudaGetSymbolAddress((void**)&lat, g_lat);
    cudaGetSymbolAddress((void**)&kt,  g_kt);
    cudaGetSymbolAddress((void**)&vt,  g_vt);
    cudaGetSymbolAddress((void**)&qa,  g_qa);
    cudaGetSymbolAddress((void**)&ka,  g_ka);
    cudaGetSymbolAddress((void**)&y,   g_y);

    cudaFuncSetAttribute(flash_kernel, cudaFuncAttributeMaxDynamicSharedMemorySize,
                         FA_SMEM_BYTES);

    // lat = x @ Wdown^T
    sgemm_nt<<<dim3(RANK / 128, M_ROWS / 128), 256>>>(x, Wdown, lat, M_ROWS, RANK, DIM);
    // q = x @ Wq^T
    sgemm_nt<<<dim3(DIM / 128, M_ROWS / 128), 256>>>(x, Wq, q, M_ROWS, DIM, DIM);
    // k = lat @ Wkup^T ; v = lat @ Wvup^T
    sgemm_nt<<<dim3(RANK / 128, M_ROWS / 128), 256>>>(lat, Wkup, kt, M_ROWS, RANK, RANK);
    sgemm_nt<<<dim3(RANK / 128, M_ROWS / 128), 256>>>(lat, Wvup, vt, M_ROWS, RANK, RANK);
    // RMSNorm + RoPE (+gain for q)
    rms_rope_kernel<<<dim3(M_ROWS, NHEADS), 128>>>(q, qa, qgain, NHEADS);
    rms_rope_kernel<<<dim3(M_ROWS, NKVH), 128>>>(kt, ka, nullptr, NKVH);
    // Attention
    flash_kernel<<<dim3(T_SEQ / FA_BQ, NHEADS, BATCH), 256, FA_SMEM_BYTES>>>(qa, ka, vt, y);
    // out = y @ Wproj^T
    sgemm_nt<<<dim3(DIM / 128, M_ROWS / 128), 256>>>(y, Wproj, out, M_ROWS, DIM, DIM);
}

// round 4
// speedup vs baseline: 1.4306x; 1.4306x over previous
#include <cuda_runtime.h>
#include <cuda_bf16.h>
#include <mma.h>
#include <math.h>

// ---------------- Problem constants ----------------
#define T_SEQ  2048
#define BATCH  2
#define NHEADS 16
#define NKVH   4
#define HD     128
#define DIM    2048
#define RANK   512
#define M_ROWS (BATCH * T_SEQ)
#define EPS_F  1.1920928955078125e-07f
#define SCALE_F 0.08838834764831845f

#define NE_MD (M_ROWS * DIM)
#define NE_MR (M_ROWS * RANK)
#define NE_DD (DIM * DIM)
#define NE_RD (RANK * DIM)
#define NE_RR (RANK * RANK)

// ---------------- Scratch (static device globals; no allocation) ----------------
__device__ float g_q  [NE_MD];
__device__ float g_lat[NE_MR];
__device__ float g_kt [NE_MR];
__device__ float g_vt [NE_MR];
__device__ float g_qa [NE_MD];
__device__ float g_ka [NE_MR];
__device__ float g_y  [NE_MD];

__device__ __nv_bfloat16 g_xhi[NE_MD];
__device__ __nv_bfloat16 g_xlo[NE_MD];
__device__ __nv_bfloat16 g_lhi[NE_MR];
__device__ __nv_bfloat16 g_llo[NE_MR];
__device__ __nv_bfloat16 g_yhi[NE_MD];
__device__ __nv_bfloat16 g_ylo[NE_MD];
__device__ __nv_bfloat16 g_wqh[NE_DD];
__device__ __nv_bfloat16 g_wql[NE_DD];
__device__ __nv_bfloat16 g_wdh[NE_RD];
__device__ __nv_bfloat16 g_wdl[NE_RD];
__device__ __nv_bfloat16 g_wkh[NE_RR];
__device__ __nv_bfloat16 g_wkl[NE_RR];
__device__ __nv_bfloat16 g_wvh[NE_RR];
__device__ __nv_bfloat16 g_wvl[NE_RR];
__device__ __nv_bfloat16 g_wph[NE_DD];
__device__ __nv_bfloat16 g_wpl[NE_DD];

// ---------------- fp32 -> bf16 hi/lo split ----------------
__global__ void split_kernel(const float* __restrict__ x,
                             __nv_bfloat16* __restrict__ hi,
                             __nv_bfloat16* __restrict__ lo, int n)
{
    int i = blockIdx.x * blockDim.x + threadIdx.x;
    if (i < n) {
        float v = x[i];
        __nv_bfloat16 h = __float2bfloat16(v);
        hi[i] = h;
        lo[i] = __float2bfloat16(v - __bfloat162float(h));
    }
}

// ---------------- WMMA bf16x3 GEMM: C[M,N] = A[M,K] @ W[N,K]^T ----------------
// 128x128 block tile, BK=32, 256 threads = 8 warps (2 along M x 4 along N),
// warp tile 64x32 = 4x2 wmma 16x16x16 fragments. 3-pass hi/lo compensation.
#define GBM 128
#define GBN 128
#define GBK 32
#define GLDS 40

__global__ __launch_bounds__(256, 2) void gemm_wmma(
    const __nv_bfloat16* __restrict__ Ahi, const __nv_bfloat16* __restrict__ Alo,
    const __nv_bfloat16* __restrict__ Whi, const __nv_bfloat16* __restrict__ Wlo,
    float* __restrict__ C, int M, int N, int K)
{
    __shared__ __nv_bfloat16 sAh[GBM * GLDS];
    __shared__ __nv_bfloat16 sAl[GBM * GLDS];
    __shared__ __nv_bfloat16 sBh[GBN * GLDS];
    __shared__ __nv_bfloat16 sBl[GBN * GLDS];

    const int tid  = threadIdx.x;
    const int warp = tid / 32;
    const int wm   = (warp % 2) * 64;
    const int wn   = (warp / 2) * 32;
    const int bm   = blockIdx.y * GBM;
    const int bn   = blockIdx.x * GBN;

    nvcuda::wmma::fragment<nvcuda::wmma::accumulator, 16, 16, 16, float> acc[4][2];
    for (int i = 0; i < 4; i++) {
        for (int j = 0; j < 2; j++) {
            nvcuda::wmma::fill_fragment(acc[i][j], 0.0f);
        }
    }

    // Loader mapping: each thread stores 2 x uint4 (16B) per tile.
    // Tile is 128 rows x 32 bf16 cols = 512 uint4.
    const int lr0 = tid / 4;
    const int lc  = (tid % 4) * 8;
    const int lr1 = lr0 + 64;

    for (int k0 = 0; k0 < K; k0 += GBK) {
        const __nv_bfloat16* pAh = Ahi + (size_t)(bm + lr0) * K + k0 + lc;
        const __nv_bfloat16* pAl = Alo + (size_t)(bm + lr0) * K + k0 + lc;
        const __nv_bfloat16* pBh = Whi + (size_t)(bn + lr0) * K + k0 + lc;
        const __nv_bfloat16* pBl = Wlo + (size_t)(bn + lr0) * K + k0 + lc;
        const size_t rstep = (size_t)64 * K;

        *(uint4*)(sAh + lr0 * GLDS + lc) = *(const uint4*)(pAh);
        *(uint4*)(sAh + lr1 * GLDS + lc) = *(const uint4*)(pAh + rstep);
        *(uint4*)(sAl + lr0 * GLDS + lc) = *(const uint4*)(pAl);
        *(uint4*)(sAl + lr1 * GLDS + lc) = *(const uint4*)(pAl + rstep);
        *(uint4*)(sBh + lr0 * GLDS + lc) = *(const uint4*)(pBh);
        *(uint4*)(sBh + lr1 * GLDS + lc) = *(const uint4*)(pBh + rstep);
        *(uint4*)(sBl + lr0 * GLDS + lc) = *(const uint4*)(pBl);
        *(uint4*)(sBl + lr1 * GLDS + lc) = *(const uint4*)(pBl + rstep);
        __syncthreads();

        for (int ks = 0; ks < GBK; ks += 16) {
            nvcuda::wmma::fragment<nvcuda::wmma::matrix_a, 16, 16, 16,
                                   __nv_bfloat16, nvcuda::wmma::row_major> fah[4];
            nvcuda::wmma::fragment<nvcuda::wmma::matrix_a, 16, 16, 16,
                                   __nv_bfloat16, nvcuda::wmma::row_major> fal[4];
            nvcuda::wmma::fragment<nvcuda::wmma::matrix_b, 16, 16, 16,
                                   __nv_bfloat16, nvcuda::wmma::col_major> fbh[2];
            nvcuda::wmma::fragment<nvcuda::wmma::matrix_b, 16, 16, 16,
                                   __nv_bfloat16, nvcuda::wmma::col_major> fbl[2];
            for (int i = 0; i < 4; i++) {
                nvcuda::wmma::load_matrix_sync(fah[i], sAh + (wm + i * 16) * GLDS + ks, GLDS);
                nvcuda::wmma::load_matrix_sync(fal[i], sAl + (wm + i * 16) * GLDS + ks, GLDS);
            }
            for (int j = 0; j < 2; j++) {
                nvcuda::wmma::load_matrix_sync(fbh[j], sBh + (wn + j * 16) * GLDS + ks, GLDS);
                nvcuda::wmma::load_matrix_sync(fbl[j], sBl + (wn + j * 16) * GLDS + ks, GLDS);
            }
            for (int i = 0; i < 4; i++) {
                for (int j = 0; j < 2; j++) {
                    nvcuda::wmma::mma_sync(acc[i][j], fah[i], fbh[j], acc[i][j]);
                    nvcuda::wmma::mma_sync(acc[i][j], fah[i], fbl[j], acc[i][j]);
                    nvcuda::wmma::mma_sync(acc[i][j], fal[i], fbh[j], acc[i][j]);
                }
            }
        }
        __syncthreads();
    }

    for (int i = 0; i < 4; i++) {
        for (int j = 0; j < 2; j++) {
            float* cp = C + (size_t)(bm + wm + i * 16) * N + bn + wn + j * 16;
            nvcuda::wmma::store_matrix_sync(cp, acc[i][j], N, nvcuda::wmma::mem_row_major);
        }
    }
}

// ---------------- RMSNorm + RoPE (+gain) ----------------
__global__ void rms_rope_kernel(const float* __restrict__ src, float* __restrict__ dst,
                                const float* __restrict__ gain, int nheads)
{
    const int m = blockIdx.x;
    const int h = blockIdx.y;
    const int d = threadIdx.x;
    const int b = m / T_SEQ;
    const int t = m % T_SEQ;

    float x = src[(size_t)m * ((size_t)nheads * HD) + h * HD + d];
    float ss = x * x;
#pragma unroll
    for (int o = 16; o > 0; o >>= 1) ss += __shfl_xor_sync(0xffffffffu, ss, o);
    __shared__ float red[4];
    __shared__ float sv[HD];
    if ((d & 31) == 0) red[d >> 5] = ss;
    __syncthreads();
    float tot = red[0] + red[1] + red[2] + red[3];
    float r = rsqrtf(tot * (1.0f / HD) + EPS_F);
    sv[d] = x * r;
    __syncthreads();
    if (d < 64) {
        float x1 = sv[d];
        float x2 = sv[d + 64];
        float fr = powf(10000.0f, -(float)d * (1.0f / 64.0f));
        float ang = (float)t * fr;
        float sn, cs;
        sincosf(ang, &sn, &cs);
        float g = (gain != 0) ? gain[h] : 1.0f;
        size_t base = ((size_t)(b * nheads + h) * T_SEQ + t) * HD;
        dst[base + d]      = (x1 * cs + x2 * sn) * g;
        dst[base + 64 + d] = (x2 * cs - x1 * sn) * g;
    }
}

// ---------------- Flash attention (fp32, causal, GQA) ----------------
#define FA_BQ 64
#define FA_BK 64
#define FA_SMEM_FLOATS (3 * 64 * 132 + 64 * 68 + 3 * 64)
#define FA_SMEM_BYTES  (FA_SMEM_FLOATS * 4)

__global__ __launch_bounds__(256) void flash_kernel(
    const float* __restrict__ Q, const float* __restrict__ Kt,
    const float* __restrict__ Vt, float* __restrict__ Y)
{
    extern __shared__ float sm[];
    float (*Qs)[132] = (float(*)[132])sm;
    float (*Ks)[132] = (float(*)[132])(sm + 64 * 132);
    float (*Vs)[132] = (float(*)[132])(sm + 2 * 64 * 132);
    float (*Ss)[68]  = (float(*)[68])(sm + 3 * 64 * 132);
    float* mrow = sm + 3 * 64 * 132 + 64 * 68;
    float* lrow = mrow + 64;
    float* arow = lrow + 64;

    const int tid = threadIdx.x;
    const int qt = blockIdx.x;
    const int h  = blockIdx.y;
    const int b  = blockIdx.z;
    const int kh = h >> 2;
    const int q0 = qt * FA_BQ;

    const float* Qp    = Q  + ((size_t)(b * NHEADS + h) * T_SEQ + q0) * HD;
    const float* Kp    = Kt + ((size_t)(b * NKVH + kh) * T_SEQ) * HD;
    const float* Vbase = Vt + (size_t)b * T_SEQ * RANK + kh * HD;

    for (int i = tid; i < FA_BQ * HD / 4; i += 256) {
        float4 v = ((const float4*)Qp)[i];
        int r = i >> 5;
        int c = (i & 31) << 2;
        *(float4*)&Qs[r][c] = v;
    }
    if (tid < 64) {
        mrow[tid] = -1e30f;
        lrow[tid] = 0.f;
    }

    float o[32];
#pragma unroll
    for (int j = 0; j < 32; j++) o[j] = 0.f;

    const int ro = tid >> 2;
    const int cq = tid & 3;
    const int sr = (tid >> 4) << 2;
    const int sc = tid & 15;

    __syncthreads();

    const int ntiles = qt + 1;
    for (int kt = 0; kt < ntiles; kt++) {
        const int k0 = kt * FA_BK;
        const float* Kpt = Kp + (size_t)k0 * HD;
        for (int i = tid; i < FA_BK * HD / 4; i += 256) {
            float4 v = ((const float4*)Kpt)[i];
            int r = i >> 5;
            int c = (i & 31) << 2;
            *(float4*)&Ks[r][c] = v;
        }
        for (int i = tid; i < FA_BK * HD / 4; i += 256) {
            int r = i >> 5;
            int g = i & 31;
            float4 v = ((const float4*)(Vbase + (size_t)(k0 + r) * RANK))[g];
            int gs = ((g & 7) << 2) | (g >> 3);
            *(((float4*)&Vs[r][0]) + gs) = v;
        }
        __syncthreads();

        float s[4][4];
#pragma unroll
        for (int i = 0; i < 4; i++)
#pragma unroll
            for (int j = 0; j < 4; j++) s[i][j] = 0.f;

        for (int d = 0; d < HD; d += 4) {
            float4 qv[4];
            float4 kv[4];
#pragma unroll
            for (int i = 0; i < 4; i++) qv[i] = *(const float4*)&Qs[sr + i][d];
#pragma unroll
            for (int j = 0; j < 4; j++) kv[j] = *(const float4*)&Ks[sc + 16 * j][d];
#pragma unroll
            for (int i = 0; i < 4; i++)
#pragma unroll
                for (int j = 0; j < 4; j++)
                    s[i][j] += qv[i].x * kv[j].x + qv[i].y * kv[j].y
                             + qv[i].z * kv[j].z + qv[i].w * kv[j].w;
        }
#pragma unroll
        for (int i = 0; i < 4; i++)
#pragma unroll
            for (int j = 0; j < 4; j++) {
                float val = s[i][j] * SCALE_F;
                int qg = q0 + sr + i;
                int kg = k0 + sc + 16 * j;
                if (kg > qg) val = -1e30f;
                Ss[sr + i][sc + 16 * j] = val;
            }
        __syncthreads();

        if (tid < 64) {
            float mold = mrow[tid];
            float rmax = mold;
#pragma unroll 8
            for (int c = 0; c < FA_BK; c++) rmax = fmaxf(rmax, Ss[tid][c]);
            float alpha = __expf(mold - rmax);
            float rsum = 0.f;
#pragma unroll 8
            for (int c = 0; c < FA_BK; c++) {
                float p = __expf(Ss[tid][c] - rmax);
                Ss[tid][c] = p;
                rsum += p;
            }
            lrow[tid] = lrow[tid] * alpha + rsum;
            mrow[tid] = rmax;
            arow[tid] = alpha;
        }
        __syncthreads();

        float alpha = arow[ro];
#pragma unroll
        for (int j = 0; j < 32; j++) o[j] *= alpha;
        for (int kk = 0; kk < FA_BK; kk++) {
            float p = Ss[ro][kk];
#pragma unroll
            for (int j4 = 0; j4 < 8; j4++) {
                float4 v = *(((const float4*)&Vs[kk][0]) + ((j4 << 2) | cq));
                o[4 * j4 + 0] += p * v.x;
                o[4 * j4 + 1] += p * v.y;
                o[4 * j4 + 2] += p * v.z;
                o[4 * j4 + 3] += p * v.w;
            }
        }
        __syncthreads();
    }

    float inv = 1.0f / lrow[ro];
    float* Yp = Y + ((size_t)(b * T_SEQ) + q0 + ro) * DIM + h * HD + cq * 32;
#pragma unroll
    for (int j4 = 0; j4 < 8; j4++) {
        *(float4*)&Yp[4 * j4] = make_float4(o[4 * j4 + 0] * inv, o[4 * j4 + 1] * inv,
                                            o[4 * j4 + 2] * inv, o[4 * j4 + 3] * inv);
    }
}

// ---------------- Launch ----------------
extern "C" void kernel_launch(void* const* d_in, const int* in_sizes, int n_in,
                              void* d_out, int out_size)
{
    (void)in_sizes;
    (void)n_in;
    (void)out_size;
    const float* x     = (const float*)d_in[0];
    const float* Wq    = (const float*)d_in[1];
    const float* Wdown = (const float*)d_in[2];
    const float* Wkup  = (const float*)d_in[3];
    const float* Wvup  = (const float*)d_in[4];
    const float* Wproj = (const float*)d_in[5];
    const float* qgain = (const float*)d_in[6];
    float* out = (float*)d_out;

    float* q;
    float* lat;
    float* kt;
    float* vt;
    float* qa;
    float* ka;
    float* y;
    cudaGetSymbolAddress((void**)&q,   g_q);
    cudaGetSymbolAddress((void**)&lat, g_lat);
    cudaGetSymbolAddress((void**)&kt,  g_kt);
    cudaGetSymbolAddress((void**)&vt,  g_vt);
    cudaGetSymbolAddress((void**)&qa,  g_qa);
    cudaGetSymbolAddress((void**)&ka,  g_ka);
    cudaGetSymbolAddress((void**)&y,   g_y);

    __nv_bfloat16* xhi;
    __nv_bfloat16* xlo;
    __nv_bfloat16* lhi;
    __nv_bfloat16* llo;
    __nv_bfloat16* yhi;
    __nv_bfloat16* ylo;
    __nv_bfloat16* wqh;
    __nv_bfloat16* wql;
    __nv_bfloat16* wdh;
    __nv_bfloat16* wdl;
    __nv_bfloat16* wkh;
    __nv_bfloat16* wkl;
    __nv_bfloat16* wvh;
    __nv_bfloat16* wvl;
    __nv_bfloat16* wph;
    __nv_bfloat16* wpl;
    cudaGetSymbolAddress((void**)&xhi, g_xhi);
    cudaGetSymbolAddress((void**)&xlo, g_xlo);
    cudaGetSymbolAddress((void**)&lhi, g_lhi);
    cudaGetSymbolAddress((void**)&llo, g_llo);
    cudaGetSymbolAddress((void**)&yhi, g_yhi);
    cudaGetSymbolAddress((void**)&ylo, g_ylo);
    cudaGetSymbolAddress((void**)&wqh, g_wqh);
    cudaGetSymbolAddress((void**)&wql, g_wql);
    cudaGetSymbolAddress((void**)&wdh, g_wdh);
    cudaGetSymbolAddress((void**)&wdl, g_wdl);
    cudaGetSymbolAddress((void**)&wkh, g_wkh);
    cudaGetSymbolAddress((void**)&wkl, g_wkl);
    cudaGetSymbolAddress((void**)&wvh, g_wvh);
    cudaGetSymbolAddress((void**)&wvl, g_wvl);
    cudaGetSymbolAddress((void**)&wph, g_wph);
    cudaGetSymbolAddress((void**)&wpl, g_wpl);

    cudaFuncSetAttribute(flash_kernel, cudaFuncAttributeMaxDynamicSharedMemorySize,
                         FA_SMEM_BYTES);

    int n1 = NE_MD;
    int n2 = NE_DD;
    int n3 = NE_RD;
    int n4 = NE_RR;
    int n5 = NE_MR;
    split_kernel<<<(n1 + 255) / 256, 256>>>(x, xhi, xlo, n1);
    split_kernel<<<(n2 + 255) / 256, 256>>>(Wq, wqh, wql, n2);
    split_kernel<<<(n3 + 255) / 256, 256>>>(Wdown, wdh, wdl, n3);
    split_kernel<<<(n4 + 255) / 256, 256>>>(Wkup, wkh, wkl, n4);
    split_kernel<<<(n4 + 255) / 256, 256>>>(Wvup, wvh, wvl, n4);
    split_kernel<<<(n2 + 255) / 256, 256>>>(Wproj, wph, wpl, n2);

    gemm_wmma<<<dim3(RANK / GBN, M_ROWS / GBM), 256>>>(xhi, xlo, wdh, wdl, lat,
                                                       M_ROWS, RANK, DIM);
    gemm_wmma<<<dim3(DIM / GBN, M_ROWS / GBM), 256>>>(xhi, xlo, wqh, wql, q,
                                                      M_ROWS, DIM, DIM);
    split_kernel<<<(n5 + 255) / 256, 256>>>(lat, lhi, llo, n5);
    gemm_wmma<<<dim3(RANK / GBN, M_ROWS / GBM), 256>>>(lhi, llo, wkh, wkl, kt,
                                                       M_ROWS, RANK, RANK);
    gemm_wmma<<<dim3(RANK / GBN, M_ROWS / GBM), 256>>>(lhi, llo, wvh, wvl, vt,
                                                       M_ROWS, RANK, RANK);

    rms_rope_kernel<<<dim3(M_ROWS, NHEADS), 128>>>(q, qa, qgain, NHEADS);
    rms_rope_kernel<<<dim3(M_ROWS, NKVH), 128>>>(kt, ka, (const float*)0, NKVH);

    flash_kernel<<<dim3(T_SEQ / FA_BQ, NHEADS, BATCH), 256, FA_SMEM_BYTES>>>(qa, ka, vt, y);

    split_kernel<<<(n1 + 255) / 256, 256>>>(y, yhi, ylo, n1);
    gemm_wmma<<<dim3(DIM / GBN, M_ROWS / GBM), 256>>>(yhi, ylo, wph, wpl, out,
                                                      M_ROWS, DIM, DIM);
}

// round 5
// speedup vs baseline: 2.2186x; 1.5508x over previous
#include <cuda_runtime.h>
#include <cuda_bf16.h>
#include <mma.h>
#include <math.h>

// ---------------- Problem constants ----------------
#define T_SEQ  2048
#define BATCH  2
#define NHEADS 16
#define NKVH   4
#define HD     128
#define DIM    2048
#define RANK   512
#define M_ROWS (BATCH * T_SEQ)
#define EPS_F  1.1920928955078125e-07f
#define SCALE_F 0.08838834764831845f

#define NE_MD (M_ROWS * DIM)
#define NE_MR (M_ROWS * RANK)
#define NE_DD (DIM * DIM)
#define NE_RD (RANK * DIM)
#define NE_RR (RANK * RANK)

// ---------------- Scratch (static device globals; no allocation) ----------------
__device__ float g_q  [NE_MD];
__device__ float g_lat[NE_MR];
__device__ float g_kt [NE_MR];
__device__ float g_vt [NE_MR];
__device__ float g_y  [NE_MD];

__device__ __nv_bfloat16 g_xhi[NE_MD];
__device__ __nv_bfloat16 g_xlo[NE_MD];
__device__ __nv_bfloat16 g_lhi[NE_MR];
__device__ __nv_bfloat16 g_llo[NE_MR];
__device__ __nv_bfloat16 g_yhi[NE_MD];
__device__ __nv_bfloat16 g_ylo[NE_MD];
__device__ __nv_bfloat16 g_wqh[NE_DD];
__device__ __nv_bfloat16 g_wql[NE_DD];
__device__ __nv_bfloat16 g_wdh[NE_RD];
__device__ __nv_bfloat16 g_wdl[NE_RD];
__device__ __nv_bfloat16 g_wkh[NE_RR];
__device__ __nv_bfloat16 g_wkl[NE_RR];
__device__ __nv_bfloat16 g_wvh[NE_RR];
__device__ __nv_bfloat16 g_wvl[NE_RR];
__device__ __nv_bfloat16 g_wph[NE_DD];
__device__ __nv_bfloat16 g_wpl[NE_DD];

// attention operands (bf16 hi/lo)
__device__ __nv_bfloat16 g_qah[NE_MD];
__device__ __nv_bfloat16 g_qal[NE_MD];
__device__ __nv_bfloat16 g_kah[NE_MR];
__device__ __nv_bfloat16 g_kal[NE_MR];
__device__ __nv_bfloat16 g_vth[NE_MR];
__device__ __nv_bfloat16 g_vtl[NE_MR];

// ---------------- fp32 -> bf16 hi/lo split ----------------
__global__ void split_kernel(const float* __restrict__ x,
                             __nv_bfloat16* __restrict__ hi,
                             __nv_bfloat16* __restrict__ lo, int n)
{
    int i = blockIdx.x * blockDim.x + threadIdx.x;
    if (i < n) {
        float v = x[i];
        __nv_bfloat16 h = __float2bfloat16(v);
        hi[i] = h;
        lo[i] = __float2bfloat16(v - __bfloat162float(h));
    }
}

// ---------------- WMMA bf16x3 GEMM: C[M,N] = A[M,K] @ W[N,K]^T ----------------
#define GBM 128
#define GBN 128
#define GBK 32
#define GLDS 40

__global__ __launch_bounds__(256, 2) void gemm_wmma(
    const __nv_bfloat16* __restrict__ Ahi, const __nv_bfloat16* __restrict__ Alo,
    const __nv_bfloat16* __restrict__ Whi, const __nv_bfloat16* __restrict__ Wlo,
    float* __restrict__ C, int M, int N, int K)
{
    __shared__ __nv_bfloat16 sAh[GBM * GLDS];
    __shared__ __nv_bfloat16 sAl[GBM * GLDS];
    __shared__ __nv_bfloat16 sBh[GBN * GLDS];
    __shared__ __nv_bfloat16 sBl[GBN * GLDS];

    const int tid  = threadIdx.x;
    const int warp = tid / 32;
    const int wm   = (warp % 2) * 64;
    const int wn   = (warp / 2) * 32;
    const int bm   = blockIdx.y * GBM;
    const int bn   = blockIdx.x * GBN;

    nvcuda::wmma::fragment<nvcuda::wmma::accumulator, 16, 16, 16, float> acc[4][2];
    for (int i = 0; i < 4; i++) {
        for (int j = 0; j < 2; j++) {
            nvcuda::wmma::fill_fragment(acc[i][j], 0.0f);
        }
    }

    const int lr0 = tid / 4;
    const int lc  = (tid % 4) * 8;
    const int lr1 = lr0 + 64;

    for (int k0 = 0; k0 < K; k0 += GBK) {
        const __nv_bfloat16* pAh = Ahi + (size_t)(bm + lr0) * K + k0 + lc;
        const __nv_bfloat16* pAl = Alo + (size_t)(bm + lr0) * K + k0 + lc;
        const __nv_bfloat16* pBh = Whi + (size_t)(bn + lr0) * K + k0 + lc;
        const __nv_bfloat16* pBl = Wlo + (size_t)(bn + lr0) * K + k0 + lc;
        const size_t rstep = (size_t)64 * K;

        *(uint4*)(sAh + lr0 * GLDS + lc) = *(const uint4*)(pAh);
        *(uint4*)(sAh + lr1 * GLDS + lc) = *(const uint4*)(pAh + rstep);
        *(uint4*)(sAl + lr0 * GLDS + lc) = *(const uint4*)(pAl);
        *(uint4*)(sAl + lr1 * GLDS + lc) = *(const uint4*)(pAl + rstep);
        *(uint4*)(sBh + lr0 * GLDS + lc) = *(const uint4*)(pBh);
        *(uint4*)(sBh + lr1 * GLDS + lc) = *(const uint4*)(pBh + rstep);
        *(uint4*)(sBl + lr0 * GLDS + lc) = *(const uint4*)(pBl);
        *(uint4*)(sBl + lr1 * GLDS + lc) = *(const uint4*)(pBl + rstep);
        __syncthreads();

        for (int ks = 0; ks < GBK; ks += 16) {
            nvcuda::wmma::fragment<nvcuda::wmma::matrix_a, 16, 16, 16,
                                   __nv_bfloat16, nvcuda::wmma::row_major> fah[4];
            nvcuda::wmma::fragment<nvcuda::wmma::matrix_a, 16, 16, 16,
                                   __nv_bfloat16, nvcuda::wmma::row_major> fal[4];
            nvcuda::wmma::fragment<nvcuda::wmma::matrix_b, 16, 16, 16,
                                   __nv_bfloat16, nvcuda::wmma::col_major> fbh[2];
            nvcuda::wmma::fragment<nvcuda::wmma::matrix_b, 16, 16, 16,
                                   __nv_bfloat16, nvcuda::wmma::col_major> fbl[2];
            for (int i = 0; i < 4; i++) {
                nvcuda::wmma::load_matrix_sync(fah[i], sAh + (wm + i * 16) * GLDS + ks, GLDS);
                nvcuda::wmma::load_matrix_sync(fal[i], sAl + (wm + i * 16) * GLDS + ks, GLDS);
            }
            for (int j = 0; j < 2; j++) {
                nvcuda::wmma::load_matrix_sync(fbh[j], sBh + (wn + j * 16) * GLDS + ks, GLDS);
                nvcuda::wmma::load_matrix_sync(fbl[j], sBl + (wn + j * 16) * GLDS + ks, GLDS);
            }
            for (int i = 0; i < 4; i++) {
                for (int j = 0; j < 2; j++) {
                    nvcuda::wmma::mma_sync(acc[i][j], fah[i], fbh[j], acc[i][j]);
                    nvcuda::wmma::mma_sync(acc[i][j], fah[i], fbl[j], acc[i][j]);
                    nvcuda::wmma::mma_sync(acc[i][j], fal[i], fbh[j], acc[i][j]);
                }
            }
        }
        __syncthreads();
    }

    for (int i = 0; i < 4; i++) {
        for (int j = 0; j < 2; j++) {
            float* cp = C + (size_t)(bm + wm + i * 16) * N + bn + wn + j * 16;
            nvcuda::wmma::store_matrix_sync(cp, acc[i][j], N, nvcuda::wmma::mem_row_major);
        }
    }
}

// ---------------- RMSNorm + RoPE (+gain), output bf16 hi/lo ----------------
__global__ void rms_rope_kernel(const float* __restrict__ src,
                                __nv_bfloat16* __restrict__ dsth,
                                __nv_bfloat16* __restrict__ dstl,
                                const float* __restrict__ gain, int nheads)
{
    const int m = blockIdx.x;
    const int h = blockIdx.y;
    const int d = threadIdx.x;
    const int b = m / T_SEQ;
    const int t = m % T_SEQ;

    float x = src[(size_t)m * ((size_t)nheads * HD) + h * HD + d];
    float ss = x * x;
#pragma unroll
    for (int o = 16; o > 0; o >>= 1) ss += __shfl_xor_sync(0xffffffffu, ss, o);
    __shared__ float red[4];
    __shared__ float sv[HD];
    if ((d & 31) == 0) red[d >> 5] = ss;
    __syncthreads();
    float tot = red[0] + red[1] + red[2] + red[3];
    float r = rsqrtf(tot * (1.0f / HD) + EPS_F);
    sv[d] = x * r;
    __syncthreads();
    if (d < 64) {
        float x1 = sv[d];
        float x2 = sv[d + 64];
        float fr = powf(10000.0f, -(float)d * (1.0f / 64.0f));
        float ang = (float)t * fr;
        float sn, cs;
        sincosf(ang, &sn, &cs);
        float g = (gain != 0) ? gain[h] : 1.0f;
        float v1 = (x1 * cs + x2 * sn) * g;
        float v2 = (x2 * cs - x1 * sn) * g;
        size_t base = ((size_t)(b * nheads + h) * T_SEQ + t) * HD;
        __nv_bfloat16 h1 = __float2bfloat16(v1);
        __nv_bfloat16 h2 = __float2bfloat16(v2);
        dsth[base + d]      = h1;
        dsth[base + 64 + d] = h2;
        dstl[base + d]      = __float2bfloat16(v1 - __bfloat162float(h1));
        dstl[base + 64 + d] = __float2bfloat16(v2 - __bfloat162float(h2));
    }
}

// ---------------- Flash attention (WMMA bf16x3, fp32 softmax, causal, GQA) ----------------
#define FBQ 64
#define FBK 64
#define QLD 136
#define PLD 72
#define SLD 68

#define OQH 0
#define OQL (OQH + FBQ * QLD * 2)
#define OKH (OQL + FBQ * QLD * 2)
#define OKL (OKH + FBK * QLD * 2)
#define OVH (OKL + FBK * QLD * 2)
#define OVL (OVH + FBK * QLD * 2)
#define OPH (OVL + FBK * QLD * 2)
#define OPL (OPH + FBQ * PLD * 2)
#define OSF (OPL + FBQ * PLD * 2)
#define OMR (OSF + FBQ * 128 * 4)
#define OLR (OMR + 256)
#define OAR (OLR + 256)
#define FA2_SMEM (OAR + 256)

__global__ __launch_bounds__(256) void flash_mma(
    const __nv_bfloat16* __restrict__ Qhi, const __nv_bfloat16* __restrict__ Qlo,
    const __nv_bfloat16* __restrict__ Khi, const __nv_bfloat16* __restrict__ Klo,
    const __nv_bfloat16* __restrict__ Vhi, const __nv_bfloat16* __restrict__ Vlo,
    float* __restrict__ Y)
{
    extern __shared__ char smb[];
    __nv_bfloat16* sQh = (__nv_bfloat16*)(smb + OQH);
    __nv_bfloat16* sQl = (__nv_bfloat16*)(smb + OQL);
    __nv_bfloat16* sKh = (__nv_bfloat16*)(smb + OKH);
    __nv_bfloat16* sKl = (__nv_bfloat16*)(smb + OKL);
    __nv_bfloat16* sVh = (__nv_bfloat16*)(smb + OVH);
    __nv_bfloat16* sVl = (__nv_bfloat16*)(smb + OVL);
    __nv_bfloat16* sPh = (__nv_bfloat16*)(smb + OPH);
    __nv_bfloat16* sPl = (__nv_bfloat16*)(smb + OPL);
    float* sSf  = (float*)(smb + OSF);
    float* sOd  = (float*)(smb + OSF);
    float* mrow = (float*)(smb + OMR);
    float* lrow = (float*)(smb + OLR);
    float* arow = (float*)(smb + OAR);

    const int tid  = threadIdx.x;
    const int warp = tid / 32;
    const int qt = blockIdx.x;
    const int h  = blockIdx.y;
    const int b  = blockIdx.z;
    const int kh = h >> 2;
    const int q0 = qt * FBQ;

    const __nv_bfloat16* qsh = Qhi + ((size_t)(b * NHEADS + h) * T_SEQ + q0) * HD;
    const __nv_bfloat16* qsl = Qlo + ((size_t)(b * NHEADS + h) * T_SEQ + q0) * HD;
    for (int i = tid; i < FBQ * HD / 8; i += 256) {
        int r = i >> 4;
        int c = (i & 15) * 8;
        *(uint4*)(sQh + r * QLD + c) = *(const uint4*)(qsh + (size_t)r * HD + c);
        *(uint4*)(sQl + r * QLD + c) = *(const uint4*)(qsl + (size_t)r * HD + c);
    }
    if (tid < 64) {
        mrow[tid] = -1e30f;
        lrow[tid] = 0.f;
    }

    float o[32];
#pragma unroll
    for (int j = 0; j < 32; j++) o[j] = 0.f;

    const int ro = tid >> 2;
    const int cq = tid & 3;
    __syncthreads();

    for (int kt = 0; kt <= qt; kt++) {
        const int k0 = kt * FBK;
        const __nv_bfloat16* ksh = Khi + ((size_t)(b * NKVH + kh) * T_SEQ + k0) * HD;
        const __nv_bfloat16* ksl = Klo + ((size_t)(b * NKVH + kh) * T_SEQ + k0) * HD;
        const __nv_bfloat16* vsh = Vhi + ((size_t)(b * T_SEQ) + k0) * RANK + kh * HD;
        const __nv_bfloat16* vsl = Vlo + ((size_t)(b * T_SEQ) + k0) * RANK + kh * HD;
        for (int i = tid; i < FBK * HD / 8; i += 256) {
            int r = i >> 4;
            int c = (i & 15) * 8;
            *(uint4*)(sKh + r * QLD + c) = *(const uint4*)(ksh + (size_t)r * HD + c);
            *(uint4*)(sKl + r * QLD + c) = *(const uint4*)(ksl + (size_t)r * HD + c);
            *(uint4*)(sVh + r * QLD + c) = *(const uint4*)(vsh + (size_t)r * RANK + c);
            *(uint4*)(sVl + r * QLD + c) = *(const uint4*)(vsl + (size_t)r * RANK + c);
        }
        __syncthreads();

        // ---- S = Q K^T (bf16x3) ----
        {
            const int wm  = warp % 4;
            const int wc0 = (warp / 4) * 2;
            nvcuda::wmma::fragment<nvcuda::wmma::accumulator, 16, 16, 16, float> accs[2];
            for (int j = 0; j < 2; j++) nvcuda::wmma::fill_fragment(accs[j], 0.0f);
            for (int ks = 0; ks < HD; ks += 16) {
                nvcuda::wmma::fragment<nvcuda::wmma::matrix_a, 16, 16, 16,
                                       __nv_bfloat16, nvcuda::wmma::row_major> fah;
                nvcuda::wmma::fragment<nvcuda::wmma::matrix_a, 16, 16, 16,
                                       __nv_bfloat16, nvcuda::wmma::row_major> fal;
                nvcuda::wmma::load_matrix_sync(fah, sQh + (wm * 16) * QLD + ks, QLD);
                nvcuda::wmma::load_matrix_sync(fal, sQl + (wm * 16) * QLD + ks, QLD);
                for (int j = 0; j < 2; j++) {
                    nvcuda::wmma::fragment<nvcuda::wmma::matrix_b, 16, 16, 16,
                                           __nv_bfloat16, nvcuda::wmma::col_major> fbh;
                    nvcuda::wmma::fragment<nvcuda::wmma::matrix_b, 16, 16, 16,
                                           __nv_bfloat16, nvcuda::wmma::col_major> fbl;
                    nvcuda::wmma::load_matrix_sync(fbh, sKh + ((wc0 + j) * 16) * QLD + ks, QLD);
                    nvcuda::wmma::load_matrix_sync(fbl, sKl + ((wc0 + j) * 16) * QLD + ks, QLD);
                    nvcuda::wmma::mma_sync(accs[j], fah, fbh, accs[j]);
                    nvcuda::wmma::mma_sync(accs[j], fah, fbl, accs[j]);
                    nvcuda::wmma::mma_sync(accs[j], fal, fbh, accs[j]);
                }
            }
            for (int j = 0; j < 2; j++) {
                nvcuda::wmma::store_matrix_sync(sSf + (wm * 16) * SLD + (wc0 + j) * 16,
                                                accs[j], SLD, nvcuda::wmma::mem_row_major);
            }
        }
        __syncthreads();

        // ---- online softmax (4 threads per row) ----
        {
            const int r  = tid >> 2;
            const int qq = tid & 3;
            const int qg = q0 + r;
            float mold = mrow[r];
            float vals[16];
            float rmax = mold;
#pragma unroll
            for (int j = 0; j < 16; j++) {
                int c = qq + 4 * j;
                float v = sSf[r * SLD + c] * SCALE_F;
                if (k0 + c > qg) v = -1e30f;
                vals[j] = v;
                rmax = fmaxf(rmax, v);
            }
            rmax = fmaxf(rmax, __shfl_xor_sync(0xffffffffu, rmax, 1));
            rmax = fmaxf(rmax, __shfl_xor_sync(0xffffffffu, rmax, 2));
            float alpha = __expf(mold - rmax);
            float rsum = 0.f;
#pragma unroll
            for (int j = 0; j < 16; j++) {
                int c = qq + 4 * j;
                float p = __expf(vals[j] - rmax);
                __nv_bfloat16 ph = __float2bfloat16(p);
                sPh[r * PLD + c] = ph;
                sPl[r * PLD + c] = __float2bfloat16(p - __bfloat162float(ph));
                rsum += p;
            }
            rsum += __shfl_xor_sync(0xffffffffu, rsum, 1);
            rsum += __shfl_xor_sync(0xffffffffu, rsum, 2);
            if (qq == 0) {
                lrow[r] = lrow[r] * alpha + rsum;
                mrow[r] = rmax;
                arow[r] = alpha;
            }
        }
        __syncthreads();

        // ---- O_delta = P V (bf16x3) ----
        {
            const int wm  = warp % 4;
            const int wn0 = (warp / 4) * 4;
            nvcuda::wmma::fragment<nvcuda::wmma::accumulator, 16, 16, 16, float> accd[4];
            for (int j = 0; j < 4; j++) nvcuda::wmma::fill_fragment(accd[j], 0.0f);
            for (int kc = 0; kc < FBK; kc += 16) {
                nvcuda::wmma::fragment<nvcuda::wmma::matrix_a, 16, 16, 16,
                                       __nv_bfloat16, nvcuda::wmma::row_major> pah;
                nvcuda::wmma::fragment<nvcuda::wmma::matrix_a, 16, 16, 16,
                                       __nv_bfloat16, nvcuda::wmma::row_major> pal;
                nvcuda::wmma::load_matrix_sync(pah, sPh + (wm * 16) * PLD + kc, PLD);
                nvcuda::wmma::load_matrix_sync(pal, sPl + (wm * 16) * PLD + kc, PLD);
                for (int j = 0; j < 4; j++) {
                    nvcuda::wmma::fragment<nvcuda::wmma::matrix_b, 16, 16, 16,
                                           __nv_bfloat16, nvcuda::wmma::row_major> vbh;
                    nvcuda::wmma::fragment<nvcuda::wmma::matrix_b, 16, 16, 16,
                                           __nv_bfloat16, nvcuda::wmma::row_major> vbl;
                    nvcuda::wmma::load_matrix_sync(vbh, sVh + kc * QLD + (wn0 + j) * 16, QLD);
                    nvcuda::wmma::load_matrix_sync(vbl, sVl + kc * QLD + (wn0 + j) * 16, QLD);
                    nvcuda::wmma::mma_sync(accd[j], pah, vbh, accd[j]);
                    nvcuda::wmma::mma_sync(accd[j], pal, vbh, accd[j]);
                    nvcuda::wmma::mma_sync(accd[j], pah, vbl, accd[j]);
                }
            }
            for (int j = 0; j < 4; j++) {
                nvcuda::wmma::store_matrix_sync(sOd + (wm * 16) * 128 + (wn0 + j) * 16,
                                                accd[j], 128, nvcuda::wmma::mem_row_major);
            }
        }
        __syncthreads();

        // ---- o = o * alpha + O_delta ----
        {
            float alpha = arow[ro];
            const float* od = sOd + ro * 128 + cq * 32;
#pragma unroll
            for (int j = 0; j < 32; j++) o[j] = o[j] * alpha + od[j];
        }
        __syncthreads();
    }

    float inv = 1.0f / lrow[ro];
    float* Yp = Y + ((size_t)(b * T_SEQ) + q0 + ro) * DIM + h * HD + cq * 32;
#pragma unroll
    for (int j4 = 0; j4 < 8; j4++) {
        *(float4*)&Yp[4 * j4] = make_float4(o[4 * j4 + 0] * inv, o[4 * j4 + 1] * inv,
                                            o[4 * j4 + 2] * inv, o[4 * j4 + 3] * inv);
    }
}

// ---------------- Launch ----------------
extern "C" void kernel_launch(void* const* d_in, const int* in_sizes, int n_in,
                              void* d_out, int out_size)
{
    (void)in_sizes;
    (void)n_in;
    (void)out_size;
    const float* x     = (const float*)d_in[0];
    const float* Wq    = (const float*)d_in[1];
    const float* Wdown = (const float*)d_in[2];
    const float* Wkup  = (const float*)d_in[3];
    const float* Wvup  = (const float*)d_in[4];
    const float* Wproj = (const float*)d_in[5];
    const float* qgain = (const float*)d_in[6];
    float* out = (float*)d_out;

    float* q;
    float* lat;
    float* kt;
    float* vt;
    float* y;
    cudaGetSymbolAddress((void**)&q,   g_q);
    cudaGetSymbolAddress((void**)&lat, g_lat);
    cudaGetSymbolAddress((void**)&kt,  g_kt);
    cudaGetSymbolAddress((void**)&vt,  g_vt);
    cudaGetSymbolAddress((void**)&y,   g_y);

    __nv_bfloat16* xhi;
    __nv_bfloat16* xlo;
    __nv_bfloat16* lhi;
    __nv_bfloat16* llo;
    __nv_bfloat16* yhi;
    __nv_bfloat16* ylo;
    __nv_bfloat16* wqh;
    __nv_bfloat16* wql;
    __nv_bfloat16* wdh;
    __nv_bfloat16* wdl;
    __nv_bfloat16* wkh;
    __nv_bfloat16* wkl;
    __nv_bfloat16* wvh;
    __nv_bfloat16* wvl;
    __nv_bfloat16* wph;
    __nv_bfloat16* wpl;
    __nv_bfloat16* qah;
    __nv_bfloat16* qal;
    __nv_bfloat16* kah;
    __nv_bfloat16* kal;
    __nv_bfloat16* vth;
    __nv_bfloat16* vtl;
    cudaGetSymbolAddress((void**)&xhi, g_xhi);
    cudaGetSymbolAddress((void**)&xlo, g_xlo);
    cudaGetSymbolAddress((void**)&lhi, g_lhi);
    cudaGetSymbolAddress((void**)&llo, g_llo);
    cudaGetSymbolAddress((void**)&yhi, g_yhi);
    cudaGetSymbolAddress((void**)&ylo, g_ylo);
    cudaGetSymbolAddress((void**)&wqh, g_wqh);
    cudaGetSymbolAddress((void**)&wql, g_wql);
    cudaGetSymbolAddress((void**)&wdh, g_wdh);
    cudaGetSymbolAddress((void**)&wdl, g_wdl);
    cudaGetSymbolAddress((void**)&wkh, g_wkh);
    cudaGetSymbolAddress((void**)&wkl, g_wkl);
    cudaGetSymbolAddress((void**)&wvh, g_wvh);
    cudaGetSymbolAddress((void**)&wvl, g_wvl);
    cudaGetSymbolAddress((void**)&wph, g_wph);
    cudaGetSymbolAddress((void**)&wpl, g_wpl);
    cudaGetSymbolAddress((void**)&qah, g_qah);
    cudaGetSymbolAddress((void**)&qal, g_qal);
    cudaGetSymbolAddress((void**)&kah, g_kah);
    cudaGetSymbolAddress((void**)&kal, g_kal);
    cudaGetSymbolAddress((void**)&vth, g_vth);
    cudaGetSymbolAddress((void**)&vtl, g_vtl);

    cudaFuncSetAttribute(flash_mma, cudaFuncAttributeMaxDynamicSharedMemorySize,
                         FA2_SMEM);

    int n1 = NE_MD;
    int n2 = NE_DD;
    int n3 = NE_RD;
    int n4 = NE_RR;
    int n5 = NE_MR;
    split_kernel<<<(n1 + 255) / 256, 256>>>(x, xhi, xlo, n1);
    split_kernel<<<(n2 + 255) / 256, 256>>>(Wq, wqh, wql, n2);
    split_kernel<<<(n3 + 255) / 256, 256>>>(Wdown, wdh, wdl, n3);
    split_kernel<<<(n4 + 255) / 256, 256>>>(Wkup, wkh, wkl, n4);
    split_kernel<<<(n4 + 255) / 256, 256>>>(Wvup, wvh, wvl, n4);
    split_kernel<<<(n2 + 255) / 256, 256>>>(Wproj, wph, wpl, n2);

    gemm_wmma<<<dim3(RANK / GBN, M_ROWS / GBM), 256>>>(xhi, xlo, wdh, wdl, lat,
                                                       M_ROWS, RANK, DIM);
    gemm_wmma<<<dim3(DIM / GBN, M_ROWS / GBM), 256>>>(xhi, xlo, wqh, wql, q,
                                                      M_ROWS, DIM, DIM);
    split_kernel<<<(n5 + 255) / 256, 256>>>(lat, lhi, llo, n5);
    gemm_wmma<<<dim3(RANK / GBN, M_ROWS / GBM), 256>>>(lhi, llo, wkh, wkl, kt,
                                                       M_ROWS, RANK, RANK);
    gemm_wmma<<<dim3(RANK / GBN, M_ROWS / GBM), 256>>>(lhi, llo, wvh, wvl, vt,
                                                       M_ROWS, RANK, RANK);

    rms_rope_kernel<<<dim3(M_ROWS, NHEADS), 128>>>(q, qah, qal, qgain, NHEADS);
    rms_rope_kernel<<<dim3(M_ROWS, NKVH), 128>>>(kt, kah, kal, (const float*)0, NKVH);
    split_kernel<<<(n5 + 255) / 256, 256>>>(vt, vth, vtl, n5);

    flash_mma<<<dim3(T_SEQ / FBQ, NHEADS, BATCH), 256, FA2_SMEM>>>(qah, qal, kah, kal,
                                                                   vth, vtl, y);

    split_kernel<<<(n1 + 255) / 256, 256>>>(y, yhi, ylo, n1);
    gemm_wmma<<<dim3(DIM / GBN, M_ROWS / GBM), 256>>>(yhi, ylo, wph, wpl, out,
                                                      M_ROWS, DIM, DIM);
}

// round 6
// speedup vs baseline: 2.2533x; 1.0156x over previous
#include <cuda_runtime.h>
#include <cuda_bf16.h>
#include <cuda_pipeline.h>
#include <mma.h>
#include <math.h>

// ---------------- Problem constants ----------------
#define T_SEQ  2048
#define BATCH  2
#define NHEADS 16
#define NKVH   4
#define HD     128
#define DIM    2048
#define RANK   512
#define M_ROWS (BATCH * T_SEQ)
#define EPS_F  1.1920928955078125e-07f
#define SCALE_F 0.08838834764831845f

#define NE_MD (M_ROWS * DIM)
#define NE_MR (M_ROWS * RANK)
#define NE_DD (DIM * DIM)
#define NE_RD (RANK * DIM)
#define NE_RR (RANK * RANK)

// ---------------- Scratch (static device globals; no allocation) ----------------
__device__ float g_q  [NE_MD];
__device__ float g_lat[NE_MR];
__device__ float g_kt [NE_MR];
__device__ float g_vt [NE_MR];

__device__ __nv_bfloat16 g_xhi[NE_MD];
__device__ __nv_bfloat16 g_xlo[NE_MD];
__device__ __nv_bfloat16 g_lhi[NE_MR];
__device__ __nv_bfloat16 g_llo[NE_MR];
__device__ __nv_bfloat16 g_yhi[NE_MD];
__device__ __nv_bfloat16 g_ylo[NE_MD];
__device__ __nv_bfloat16 g_wqh[NE_DD];
__device__ __nv_bfloat16 g_wql[NE_DD];
__device__ __nv_bfloat16 g_wdh[NE_RD];
__device__ __nv_bfloat16 g_wdl[NE_RD];
__device__ __nv_bfloat16 g_wkh[NE_RR];
__device__ __nv_bfloat16 g_wkl[NE_RR];
__device__ __nv_bfloat16 g_wvh[NE_RR];
__device__ __nv_bfloat16 g_wvl[NE_RR];
__device__ __nv_bfloat16 g_wph[NE_DD];
__device__ __nv_bfloat16 g_wpl[NE_DD];

__device__ __nv_bfloat16 g_qah[NE_MD];
__device__ __nv_bfloat16 g_qal[NE_MD];
__device__ __nv_bfloat16 g_kah[NE_MR];
__device__ __nv_bfloat16 g_kal[NE_MR];
__device__ __nv_bfloat16 g_vth[NE_MR];
__device__ __nv_bfloat16 g_vtl[NE_MR];

// ---------------- fp32 -> bf16 hi/lo split ----------------
__global__ void split_kernel(const float* __restrict__ x,
                             __nv_bfloat16* __restrict__ hi,
                             __nv_bfloat16* __restrict__ lo, int n)
{
    int i = blockIdx.x * blockDim.x + threadIdx.x;
    if (i < n) {
        float v = x[i];
        __nv_bfloat16 h = __float2bfloat16(v);
        hi[i] = h;
        lo[i] = __float2bfloat16(v - __bfloat162float(h));
    }
}

// ---------------- WMMA bf16x3 GEMM, cp.async double-buffered ----------------
// C[M,N] = A[M,K] @ W[N,K]^T. 128x128x32 tile, 8 warps, 2-stage pipeline.
#define GBM 128
#define GBN 128
#define GBK 32
#define GLDS 40
#define GSTG (4 * GBM * GLDS)             // bf16 elems per stage
#define GSMEM_BYTES (2 * GSTG * 2)        // 81920

__device__ __forceinline__ void gemm_stage_load(
    __nv_bfloat16* s,
    const __nv_bfloat16* Ahi, const __nv_bfloat16* Alo,
    const __nv_bfloat16* Whi, const __nv_bfloat16* Wlo,
    int bm, int bn, int K, int k0, int lr0, int lr1, int lc)
{
    __nv_bfloat16* sAh = s;
    __nv_bfloat16* sAl = s + GBM * GLDS;
    __nv_bfloat16* sBh = s + 2 * GBM * GLDS;
    __nv_bfloat16* sBl = s + 3 * GBM * GLDS;
    __pipeline_memcpy_async(sAh + lr0 * GLDS + lc, Ahi + (size_t)(bm + lr0) * K + k0 + lc, 16);
    __pipeline_memcpy_async(sAh + lr1 * GLDS + lc, Ahi + (size_t)(bm + lr1) * K + k0 + lc, 16);
    __pipeline_memcpy_async(sAl + lr0 * GLDS + lc, Alo + (size_t)(bm + lr0) * K + k0 + lc, 16);
    __pipeline_memcpy_async(sAl + lr1 * GLDS + lc, Alo + (size_t)(bm + lr1) * K + k0 + lc, 16);
    __pipeline_memcpy_async(sBh + lr0 * GLDS + lc, Whi + (size_t)(bn + lr0) * K + k0 + lc, 16);
    __pipeline_memcpy_async(sBh + lr1 * GLDS + lc, Whi + (size_t)(bn + lr1) * K + k0 + lc, 16);
    __pipeline_memcpy_async(sBl + lr0 * GLDS + lc, Wlo + (size_t)(bn + lr0) * K + k0 + lc, 16);
    __pipeline_memcpy_async(sBl + lr1 * GLDS + lc, Wlo + (size_t)(bn + lr1) * K + k0 + lc, 16);
}

__global__ __launch_bounds__(256) void gemm_wmma(
    const __nv_bfloat16* __restrict__ Ahi, const __nv_bfloat16* __restrict__ Alo,
    const __nv_bfloat16* __restrict__ Whi, const __nv_bfloat16* __restrict__ Wlo,
    float* __restrict__ C, int M, int N, int K)
{
    extern __shared__ __nv_bfloat16 gsm[];

    const int tid  = threadIdx.x;
    const int warp = tid / 32;
    const int wm   = (warp % 2) * 64;
    const int wn   = (warp / 2) * 32;
    const int bm   = blockIdx.y * GBM;
    const int bn   = blockIdx.x * GBN;

    nvcuda::wmma::fragment<nvcuda::wmma::accumulator, 16, 16, 16, float> acc[4][2];
    for (int i = 0; i < 4; i++) {
        for (int j = 0; j < 2; j++) {
            nvcuda::wmma::fill_fragment(acc[i][j], 0.0f);
        }
    }

    const int lr0 = tid / 4;
    const int lc  = (tid % 4) * 8;
    const int lr1 = lr0 + 64;
    const int nk  = K / GBK;

    gemm_stage_load(gsm, Ahi, Alo, Whi, Wlo, bm, bn, K, 0, lr0, lr1, lc);
    __pipeline_commit();

    for (int it = 0; it < nk; it++) {
        if (it + 1 < nk) {
            gemm_stage_load(gsm + ((it + 1) & 1) * GSTG, Ahi, Alo, Whi, Wlo,
                            bm, bn, K, (it + 1) * GBK, lr0, lr1, lc);
            __pipeline_commit();
            __pipeline_wait_prior(1);
        } else {
            __pipeline_wait_prior(0);
        }
        __syncthreads();

        __nv_bfloat16* sAh = gsm + (it & 1) * GSTG;
        __nv_bfloat16* sAl = sAh + GBM * GLDS;
        __nv_bfloat16* sBh = sAh + 2 * GBM * GLDS;
        __nv_bfloat16* sBl = sAh + 3 * GBM * GLDS;

        for (int ks = 0; ks < GBK; ks += 16) {
            nvcuda::wmma::fragment<nvcuda::wmma::matrix_a, 16, 16, 16,
                                   __nv_bfloat16, nvcuda::wmma::row_major> fah[4];
            nvcuda::wmma::fragment<nvcuda::wmma::matrix_a, 16, 16, 16,
                                   __nv_bfloat16, nvcuda::wmma::row_major> fal[4];
            nvcuda::wmma::fragment<nvcuda::wmma::matrix_b, 16, 16, 16,
                                   __nv_bfloat16, nvcuda::wmma::col_major> fbh[2];
            nvcuda::wmma::fragment<nvcuda::wmma::matrix_b, 16, 16, 16,
                                   __nv_bfloat16, nvcuda::wmma::col_major> fbl[2];
            for (int i = 0; i < 4; i++) {
                nvcuda::wmma::load_matrix_sync(fah[i], sAh + (wm + i * 16) * GLDS + ks, GLDS);
                nvcuda::wmma::load_matrix_sync(fal[i], sAl + (wm + i * 16) * GLDS + ks, GLDS);
            }
            for (int j = 0; j < 2; j++) {
                nvcuda::wmma::load_matrix_sync(fbh[j], sBh + (wn + j * 16) * GLDS + ks, GLDS);
                nvcuda::wmma::load_matrix_sync(fbl[j], sBl + (wn + j * 16) * GLDS + ks, GLDS);
            }
            for (int i = 0; i < 4; i++) {
                for (int j = 0; j < 2; j++) {
                    nvcuda::wmma::mma_sync(acc[i][j], fah[i], fbh[j], acc[i][j]);
                    nvcuda::wmma::mma_sync(acc[i][j], fah[i], fbl[j], acc[i][j]);
                    nvcuda::wmma::mma_sync(acc[i][j], fal[i], fbh[j], acc[i][j]);
                }
            }
        }
        __syncthreads();
    }

    for (int i = 0; i < 4; i++) {
        for (int j = 0; j < 2; j++) {
            float* cp = C + (size_t)(bm + wm + i * 16) * N + bn + wn + j * 16;
            nvcuda::wmma::store_matrix_sync(cp, acc[i][j], N, nvcuda::wmma::mem_row_major);
        }
    }
}

// ---------------- RMSNorm + RoPE (+gain), output bf16 hi/lo ----------------
__global__ void rms_rope_kernel(const float* __restrict__ src,
                                __nv_bfloat16* __restrict__ dsth,
                                __nv_bfloat16* __restrict__ dstl,
                                const float* __restrict__ gain, int nheads)
{
    const int m = blockIdx.x;
    const int h = blockIdx.y;
    const int d = threadIdx.x;
    const int b = m / T_SEQ;
    const int t = m % T_SEQ;

    float x = src[(size_t)m * ((size_t)nheads * HD) + h * HD + d];
    float ss = x * x;
#pragma unroll
    for (int o = 16; o > 0; o >>= 1) ss += __shfl_xor_sync(0xffffffffu, ss, o);
    __shared__ float red[4];
    __shared__ float sv[HD];
    if ((d & 31) == 0) red[d >> 5] = ss;
    __syncthreads();
    float tot = red[0] + red[1] + red[2] + red[3];
    float r = rsqrtf(tot * (1.0f / HD) + EPS_F);
    sv[d] = x * r;
    __syncthreads();
    if (d < 64) {
        float x1 = sv[d];
        float x2 = sv[d + 64];
        float fr = powf(10000.0f, -(float)d * (1.0f / 64.0f));
        float ang = (float)t * fr;
        float sn, cs;
        sincosf(ang, &sn, &cs);
        float g = (gain != 0) ? gain[h] : 1.0f;
        float v1 = (x1 * cs + x2 * sn) * g;
        float v2 = (x2 * cs - x1 * sn) * g;
        size_t base = ((size_t)(b * nheads + h) * T_SEQ + t) * HD;
        __nv_bfloat16 h1 = __float2bfloat16(v1);
        __nv_bfloat16 h2 = __float2bfloat16(v2);
        dsth[base + d]      = h1;
        dsth[base + 64 + d] = h2;
        dstl[base + d]      = __float2bfloat16(v1 - __bfloat162float(h1));
        dstl[base + 64 + d] = __float2bfloat16(v2 - __bfloat162float(h2));
    }
}

// ---------------- Flash attention (WMMA bf16x3, fp32 softmax, causal, GQA) ----------------
#define FBQ 64
#define FBK 64
#define QLD 136
#define PLD 72
#define SLD 68

#define OQH 0
#define OQL (OQH + FBQ * QLD * 2)
#define OKH (OQL + FBQ * QLD * 2)
#define OKL (OKH + FBK * QLD * 2)
#define OVH (OKL + FBK * QLD * 2)
#define OVL (OVH + FBK * QLD * 2)
#define OPH (OVL + FBK * QLD * 2)
#define OPL (OPH + FBQ * PLD * 2)
#define OSF (OPL + FBQ * PLD * 2)
#define OMR (OSF + FBQ * 128 * 4)
#define OLR (OMR + 256)
#define OAR (OLR + 256)
#define FA2_SMEM (OAR + 256)

__global__ __launch_bounds__(256) void flash_mma(
    const __nv_bfloat16* __restrict__ Qhi, const __nv_bfloat16* __restrict__ Qlo,
    const __nv_bfloat16* __restrict__ Khi, const __nv_bfloat16* __restrict__ Klo,
    const __nv_bfloat16* __restrict__ Vhi, const __nv_bfloat16* __restrict__ Vlo,
    __nv_bfloat16* __restrict__ Yh, __nv_bfloat16* __restrict__ Yl)
{
    extern __shared__ char smb[];
    __nv_bfloat16* sQh = (__nv_bfloat16*)(smb + OQH);
    __nv_bfloat16* sQl = (__nv_bfloat16*)(smb + OQL);
    __nv_bfloat16* sKh = (__nv_bfloat16*)(smb + OKH);
    __nv_bfloat16* sKl = (__nv_bfloat16*)(smb + OKL);
    __nv_bfloat16* sVh = (__nv_bfloat16*)(smb + OVH);
    __nv_bfloat16* sVl = (__nv_bfloat16*)(smb + OVL);
    __nv_bfloat16* sPh = (__nv_bfloat16*)(smb + OPH);
    __nv_bfloat16* sPl = (__nv_bfloat16*)(smb + OPL);
    float* sSf  = (float*)(smb + OSF);
    float* sOd  = (float*)(smb + OSF);
    float* mrow = (float*)(smb + OMR);
    float* lrow = (float*)(smb + OLR);
    float* arow = (float*)(smb + OAR);

    const int tid  = threadIdx.x;
    const int warp = tid / 32;
    const int qt = blockIdx.x;
    const int h  = blockIdx.y;
    const int b  = blockIdx.z;
    const int kh = h >> 2;
    const int q0 = qt * FBQ;

    const __nv_bfloat16* qsh = Qhi + ((size_t)(b * NHEADS + h) * T_SEQ + q0) * HD;
    const __nv_bfloat16* qsl = Qlo + ((size_t)(b * NHEADS + h) * T_SEQ + q0) * HD;
    for (int i = tid; i < FBQ * HD / 8; i += 256) {
        int r = i >> 4;
        int c = (i & 15) * 8;
        *(uint4*)(sQh + r * QLD + c) = *(const uint4*)(qsh + (size_t)r * HD + c);
        *(uint4*)(sQl + r * QLD + c) = *(const uint4*)(qsl + (size_t)r * HD + c);
    }
    if (tid < 64) {
        mrow[tid] = -1e30f;
        lrow[tid] = 0.f;
    }

    float o[32];
#pragma unroll
    for (int j = 0; j < 32; j++) o[j] = 0.f;

    const int ro = tid >> 2;
    const int cq = tid & 3;
    __syncthreads();

    for (int kt = 0; kt <= qt; kt++) {
        const int k0 = kt * FBK;
        const __nv_bfloat16* ksh = Khi + ((size_t)(b * NKVH + kh) * T_SEQ + k0) * HD;
        const __nv_bfloat16* ksl = Klo + ((size_t)(b * NKVH + kh) * T_SEQ + k0) * HD;
        const __nv_bfloat16* vsh = Vhi + ((size_t)(b * T_SEQ) + k0) * RANK + kh * HD;
        const __nv_bfloat16* vsl = Vlo + ((size_t)(b * T_SEQ) + k0) * RANK + kh * HD;
        for (int i = tid; i < FBK * HD / 8; i += 256) {
            int r = i >> 4;
            int c = (i & 15) * 8;
            *(uint4*)(sKh + r * QLD + c) = *(const uint4*)(ksh + (size_t)r * HD + c);
            *(uint4*)(sKl + r * QLD + c) = *(const uint4*)(ksl + (size_t)r * HD + c);
            *(uint4*)(sVh + r * QLD + c) = *(const uint4*)(vsh + (size_t)r * RANK + c);
            *(uint4*)(sVl + r * QLD + c) = *(const uint4*)(vsl + (size_t)r * RANK + c);
        }
        __syncthreads();

        // ---- S = Q K^T (bf16x3) ----
        {
            const int wm  = warp % 4;
            const int wc0 = (warp / 4) * 2;
            nvcuda::wmma::fragment<nvcuda::wmma::accumulator, 16, 16, 16, float> accs[2];
            for (int j = 0; j < 2; j++) nvcuda::wmma::fill_fragment(accs[j], 0.0f);
            for (int ks = 0; ks < HD; ks += 16) {
                nvcuda::wmma::fragment<nvcuda::wmma::matrix_a, 16, 16, 16,
                                       __nv_bfloat16, nvcuda::wmma::row_major> fah;
                nvcuda::wmma::fragment<nvcuda::wmma::matrix_a, 16, 16, 16,
                                       __nv_bfloat16, nvcuda::wmma::row_major> fal;
                nvcuda::wmma::load_matrix_sync(fah, sQh + (wm * 16) * QLD + ks, QLD);
                nvcuda::wmma::load_matrix_sync(fal, sQl + (wm * 16) * QLD + ks, QLD);
                for (int j = 0; j < 2; j++) {
                    nvcuda::wmma::fragment<nvcuda::wmma::matrix_b, 16, 16, 16,
                                           __nv_bfloat16, nvcuda::wmma::col_major> fbh;
                    nvcuda::wmma::fragment<nvcuda::wmma::matrix_b, 16, 16, 16,
                                           __nv_bfloat16, nvcuda::wmma::col_major> fbl;
                    nvcuda::wmma::load_matrix_sync(fbh, sKh + ((wc0 + j) * 16) * QLD + ks, QLD);
                    nvcuda::wmma::load_matrix_sync(fbl, sKl + ((wc0 + j) * 16) * QLD + ks, QLD);
                    nvcuda::wmma::mma_sync(accs[j], fah, fbh, accs[j]);
                    nvcuda::wmma::mma_sync(accs[j], fah, fbl, accs[j]);
                    nvcuda::wmma::mma_sync(accs[j], fal, fbh, accs[j]);
                }
            }
            for (int j = 0; j < 2; j++) {
                nvcuda::wmma::store_matrix_sync(sSf + (wm * 16) * SLD + (wc0 + j) * 16,
                                                accs[j], SLD, nvcuda::wmma::mem_row_major);
            }
        }
        __syncthreads();

        // ---- online softmax (4 threads per row) ----
        {
            const int r  = tid >> 2;
            const int qq = tid & 3;
            const int qg = q0 + r;
            float mold = mrow[r];
            float vals[16];
            float rmax = mold;
#pragma unroll
            for (int j = 0; j < 16; j++) {
                int c = qq + 4 * j;
                float v = sSf[r * SLD + c] * SCALE_F;
                if (k0 + c > qg) v = -1e30f;
                vals[j] = v;
                rmax = fmaxf(rmax, v);
            }
            rmax = fmaxf(rmax, __shfl_xor_sync(0xffffffffu, rmax, 1));
            rmax = fmaxf(rmax, __shfl_xor_sync(0xffffffffu, rmax, 2));
            float alpha = __expf(mold - rmax);
            float rsum = 0.f;
#pragma unroll
            for (int j = 0; j < 16; j++) {
                int c = qq + 4 * j;
                float p = __expf(vals[j] - rmax);
                __nv_bfloat16 ph = __float2bfloat16(p);
                sPh[r * PLD + c] = ph;
                sPl[r * PLD + c] = __float2bfloat16(p - __bfloat162float(ph));
                rsum += p;
            }
            rsum += __shfl_xor_sync(0xffffffffu, rsum, 1);
            rsum += __shfl_xor_sync(0xffffffffu, rsum, 2);
            if (qq == 0) {
                lrow[r] = lrow[r] * alpha + rsum;
                mrow[r] = rmax;
                arow[r] = alpha;
            }
        }
        __syncthreads();

        // ---- O_delta = P V (bf16x3) ----
        {
            const int wm  = warp % 4;
            const int wn0 = (warp / 4) * 4;
            nvcuda::wmma::fragment<nvcuda::wmma::accumulator, 16, 16, 16, float> accd[4];
            for (int j = 0; j < 4; j++) nvcuda::wmma::fill_fragment(accd[j], 0.0f);
            for (int kc = 0; kc < FBK; kc += 16) {
                nvcuda::wmma::fragment<nvcuda::wmma::matrix_a, 16, 16, 16,
                                       __nv_bfloat16, nvcuda::wmma::row_major> pah;
                nvcuda::wmma::fragment<nvcuda::wmma::matrix_a, 16, 16, 16,
                                       __nv_bfloat16, nvcuda::wmma::row_major> pal;
                nvcuda::wmma::load_matrix_sync(pah, sPh + (wm * 16) * PLD + kc, PLD);
                nvcuda::wmma::load_matrix_sync(pal, sPl + (wm * 16) * PLD + kc, PLD);
                for (int j = 0; j < 4; j++) {
                    nvcuda::wmma::fragment<nvcuda::wmma::matrix_b, 16, 16, 16,
                                           __nv_bfloat16, nvcuda::wmma::row_major> vbh;
                    nvcuda::wmma::fragment<nvcuda::wmma::matrix_b, 16, 16, 16,
                                           __nv_bfloat16, nvcuda::wmma::row_major> vbl;
                    nvcuda::wmma::load_matrix_sync(vbh, sVh + kc * QLD + (wn0 + j) * 16, QLD);
                    nvcuda::wmma::load_matrix_sync(vbl, sVl + kc * QLD + (wn0 + j) * 16, QLD);
                    nvcuda::wmma::mma_sync(accd[j], pah, vbh, accd[j]);
                    nvcuda::wmma::mma_sync(accd[j], pal, vbh, accd[j]);
                    nvcuda::wmma::mma_sync(accd[j], pah, vbl, accd[j]);
                }
            }
            for (int j = 0; j < 4; j++) {
                nvcuda::wmma::store_matrix_sync(sOd + (wm * 16) * 128 + (wn0 + j) * 16,
                                                accd[j], 128, nvcuda::wmma::mem_row_major);
            }
        }
        __syncthreads();

        // ---- o = o * alpha + O_delta ----
        {
            float alpha = arow[ro];
            const float* od = sOd + ro * 128 + cq * 32;
#pragma unroll
            for (int j = 0; j < 32; j++) o[j] = o[j] * alpha + od[j];
        }
        __syncthreads();
    }

    // epilogue: normalize, write bf16 hi/lo directly
    float inv = 1.0f / lrow[ro];
    size_t yb = ((size_t)(b * T_SEQ) + q0 + ro) * DIM + h * HD + cq * 32;
#pragma unroll
    for (int j = 0; j < 32; j++) {
        float v = o[j] * inv;
        __nv_bfloat16 hv = __float2bfloat16(v);
        Yh[yb + j] = hv;
        Yl[yb + j] = __float2bfloat16(v - __bfloat162float(hv));
    }
}

// ---------------- Launch ----------------
extern "C" void kernel_launch(void* const* d_in, const int* in_sizes, int n_in,
                              void* d_out, int out_size)
{
    (void)in_sizes;
    (void)n_in;
    (void)out_size;
    const float* x     = (const float*)d_in[0];
    const float* Wq    = (const float*)d_in[1];
    const float* Wdown = (const float*)d_in[2];
    const float* Wkup  = (const float*)d_in[3];
    const float* Wvup  = (const float*)d_in[4];
    const float* Wproj = (const float*)d_in[5];
    const float* qgain = (const float*)d_in[6];
    float* out = (float*)d_out;

    float* q;
    float* lat;
    float* kt;
    float* vt;
    cudaGetSymbolAddress((void**)&q,   g_q);
    cudaGetSymbolAddress((void**)&lat, g_lat);
    cudaGetSymbolAddress((void**)&kt,  g_kt);
    cudaGetSymbolAddress((void**)&vt,  g_vt);

    __nv_bfloat16* xhi;
    __nv_bfloat16* xlo;
    __nv_bfloat16* lhi;
    __nv_bfloat16* llo;
    __nv_bfloat16* yhi;
    __nv_bfloat16* ylo;
    __nv_bfloat16* wqh;
    __nv_bfloat16* wql;
    __nv_bfloat16* wdh;
    __nv_bfloat16* wdl;
    __nv_bfloat16* wkh;
    __nv_bfloat16* wkl;
    __nv_bfloat16* wvh;
    __nv_bfloat16* wvl;
    __nv_bfloat16* wph;
    __nv_bfloat16* wpl;
    __nv_bfloat16* qah;
    __nv_bfloat16* qal;
    __nv_bfloat16* kah;
    __nv_bfloat16* kal;
    __nv_bfloat16* vth;
    __nv_bfloat16* vtl;
    cudaGetSymbolAddress((void**)&xhi, g_xhi);
    cudaGetSymbolAddress((void**)&xlo, g_xlo);
    cudaGetSymbolAddress((void**)&lhi, g_lhi);
    cudaGetSymbolAddress((void**)&llo, g_llo);
    cudaGetSymbolAddress((void**)&yhi, g_yhi);
    cudaGetSymbolAddress((void**)&ylo, g_ylo);
    cudaGetSymbolAddress((void**)&wqh, g_wqh);
    cudaGetSymbolAddress((void**)&wql, g_wql);
    cudaGetSymbolAddress((void**)&wdh, g_wdh);
    cudaGetSymbolAddress((void**)&wdl, g_wdl);
    cudaGetSymbolAddress((void**)&wkh, g_wkh);
    cudaGetSymbolAddress((void**)&wkl, g_wkl);
    cudaGetSymbolAddress((void**)&wvh, g_wvh);
    cudaGetSymbolAddress((void**)&wvl, g_wvl);
    cudaGetSymbolAddress((void**)&wph, g_wph);
    cudaGetSymbolAddress((void**)&wpl, g_wpl);
    cudaGetSymbolAddress((void**)&qah, g_qah);
    cudaGetSymbolAddress((void**)&qal, g_qal);
    cudaGetSymbolAddress((void**)&kah, g_kah);
    cudaGetSymbolAddress((void**)&kal, g_kal);
    cudaGetSymbolAddress((void**)&vth, g_vth);
    cudaGetSymbolAddress((void**)&vtl, g_vtl);

    cudaFuncSetAttribute(gemm_wmma, cudaFuncAttributeMaxDynamicSharedMemorySize,
                         GSMEM_BYTES);
    cudaFuncSetAttribute(flash_mma, cudaFuncAttributeMaxDynamicSharedMemorySize,
                         FA2_SMEM);

    int n1 = NE_MD;
    int n2 = NE_DD;
    int n3 = NE_RD;
    int n4 = NE_RR;
    int n5 = NE_MR;
    split_kernel<<<(n1 + 255) / 256, 256>>>(x, xhi, xlo, n1);
    split_kernel<<<(n2 + 255) / 256, 256>>>(Wq, wqh, wql, n2);
    split_kernel<<<(n3 + 255) / 256, 256>>>(Wdown, wdh, wdl, n3);
    split_kernel<<<(n4 + 255) / 256, 256>>>(Wkup, wkh, wkl, n4);
    split_kernel<<<(n4 + 255) / 256, 256>>>(Wvup, wvh, wvl, n4);
    split_kernel<<<(n2 + 255) / 256, 256>>>(Wproj, wph, wpl, n2);

    gemm_wmma<<<dim3(RANK / GBN, M_ROWS / GBM), 256, GSMEM_BYTES>>>(
        xhi, xlo, wdh, wdl, lat, M_ROWS, RANK, DIM);
    gemm_wmma<<<dim3(DIM / GBN, M_ROWS / GBM), 256, GSMEM_BYTES>>>(
        xhi, xlo, wqh, wql, q, M_ROWS, DIM, DIM);
    split_kernel<<<(n5 + 255) / 256, 256>>>(lat, lhi, llo, n5);
    gemm_wmma<<<dim3(RANK / GBN, M_ROWS / GBM), 256, GSMEM_BYTES>>>(
        lhi, llo, wkh, wkl, kt, M_ROWS, RANK, RANK);
    gemm_wmma<<<dim3(RANK / GBN, M_ROWS / GBM), 256, GSMEM_BYTES>>>(
        lhi, llo, wvh, wvl, vt, M_ROWS, RANK, RANK);

    rms_rope_kernel<<<dim3(M_ROWS, NHEADS), 128>>>(q, qah, qal, qgain, NHEADS);
    rms_rope_kernel<<<dim3(M_ROWS, NKVH), 128>>>(kt, kah, kal, (const float*)0, NKVH);
    split_kernel<<<(n5 + 255) / 256, 256>>>(vt, vth, vtl, n5);

    flash_mma<<<dim3(T_SEQ / FBQ, NHEADS, BATCH), 256, FA2_SMEM>>>(qah, qal, kah, kal,
                                                                   vth, vtl, yhi, ylo);

    gemm_wmma<<<dim3(DIM / GBN, M_ROWS / GBM), 256, GSMEM_BYTES>>>(
        yhi, ylo, wph, wpl, out, M_ROWS, DIM, DIM);
}

// round 8
// speedup vs baseline: 2.7404x; 1.2162x over previous
#include <cuda_runtime.h>
#include <cuda_bf16.h>
#include <cuda_fp16.h>
#include <cuda_pipeline.h>
#include <mma.h>
#include <math.h>

// ---------------- Problem constants ----------------
#define T_SEQ  2048
#define BATCH  2
#define NHEADS 16
#define NKVH   4
#define HD     128
#define DIM    2048
#define RANK   512
#define M_ROWS (BATCH * T_SEQ)
#define EPS_F  1.1920928955078125e-07f
#define SCALE_F 0.08838834764831845f

#define NE_MD (M_ROWS * DIM)
#define NE_MR (M_ROWS * RANK)
#define NE_DD (DIM * DIM)
#define NE_RD (RANK * DIM)
#define NE_RR (RANK * RANK)

// ---------------- Scratch (static device globals; no allocation) ----------------
__device__ float g_q  [NE_MD];
__device__ float g_lat[NE_MR];
__device__ float g_kt [NE_MR];
__device__ float g_vt [NE_MR];

// fp16 GEMM operands
__device__ __half g_xhi[NE_MD];
__device__ __half g_xlo[NE_MD];
__device__ __half g_lhi[NE_MR];
__device__ __half g_llo[NE_MR];
__device__ __half g_yhi[NE_MD];
__device__ __half g_ylo[NE_MD];
__device__ __half g_wqh[NE_DD];
__device__ __half g_wdh[NE_RD];
__device__ __half g_wkh[NE_RR];
__device__ __half g_wvh[NE_RR];
__device__ __half g_wph[NE_DD];

// flash operands (bf16 hi/lo, unchanged precision path)
__device__ __nv_bfloat16 g_qah[NE_MD];
__device__ __nv_bfloat16 g_qal[NE_MD];
__device__ __nv_bfloat16 g_kah[NE_MR];
__device__ __nv_bfloat16 g_kal[NE_MR];
__device__ __nv_bfloat16 g_vth[NE_MR];
__device__ __nv_bfloat16 g_vtl[NE_MR];

// ---------------- conversions ----------------
__global__ void split_kernel_bf(const float* __restrict__ x,
                                __nv_bfloat16* __restrict__ hi,
                                __nv_bfloat16* __restrict__ lo, int n)
{
    int i = blockIdx.x * blockDim.x + threadIdx.x;
    if (i < n) {
        float v = x[i];
        __nv_bfloat16 h = __float2bfloat16(v);
        hi[i] = h;
        lo[i] = __float2bfloat16(v - __bfloat162float(h));
    }
}

__global__ void split_kernel_h(const float* __restrict__ x,
                               __half* __restrict__ hi,
                               __half* __restrict__ lo, int n)
{
    int i = blockIdx.x * blockDim.x + threadIdx.x;
    if (i < n) {
        float v = x[i];
        __half h = __float2half(v);
        hi[i] = h;
        lo[i] = __float2half(v - __half2float(h));
    }
}

__global__ void conv_kernel_h(const float* __restrict__ x,
                              __half* __restrict__ hi, int n)
{
    int i = blockIdx.x * blockDim.x + threadIdx.x;
    if (i < n) {
        hi[i] = __float2half(x[i]);
    }
}

// ---------------- WMMA fp16x2 GEMM, cp.async double-buffered ----------------
// C[M,N] = (Ah+Al)[M,K] @ Bh[N,K]^T. 128x128x32 tile, 8 warps, 2 MMA passes.
#define GBM 128
#define GBN 128
#define GBK 32
#define GLDS 40
#define GTILE (GBM * GLDS)                  // half elems per operand tile
#define GSTG (3 * GTILE)                    // Ah, Al, Bh
#define GSMEM_BYTES (2 * GSTG * 2)          // 61440

__device__ __forceinline__ void gemm_stage_load_h(
    __half* s,
    const __half* Ah, const __half* Al, const __half* Bh,
    int bm, int bn, int K, int k0, int tid)
{
    __half* sAh = s;
    __half* sAl = s + GTILE;
    __half* sBh = s + 2 * GTILE;
    for (int i = 0; i < 2; i++) {
        int idx = tid + 256 * i;
        int row = idx >> 2;
        int c8  = (idx & 3) * 8;
        __pipeline_memcpy_async(sAh + row * GLDS + c8,
                                Ah + (size_t)(bm + row) * K + k0 + c8, 16);
        __pipeline_memcpy_async(sAl + row * GLDS + c8,
                                Al + (size_t)(bm + row) * K + k0 + c8, 16);
        __pipeline_memcpy_async(sBh + row * GLDS + c8,
                                Bh + (size_t)(bn + row) * K + k0 + c8, 16);
    }
}

__global__ __launch_bounds__(256) void gemm_h(
    const __half* __restrict__ Ah, const __half* __restrict__ Al,
    const __half* __restrict__ Bh,
    float* __restrict__ C, int M, int N, int K)
{
    extern __shared__ __half gsm[];

    const int tid  = threadIdx.x;
    const int warp = tid / 32;
    const int wm   = (warp % 2) * 64;
    const int wn   = (warp / 2) * 32;
    const int bm   = blockIdx.y * GBM;
    const int bn   = blockIdx.x * GBN;

    nvcuda::wmma::fragment<nvcuda::wmma::accumulator, 16, 16, 16, float> acc[4][2];
    for (int i = 0; i < 4; i++) {
        for (int j = 0; j < 2; j++) {
            nvcuda::wmma::fill_fragment(acc[i][j], 0.0f);
        }
    }

    const int nk = K / GBK;

    gemm_stage_load_h(gsm, Ah, Al, Bh, bm, bn, K, 0, tid);
    __pipeline_commit();

    for (int it = 0; it < nk; it++) {
        if (it + 1 < nk) {
            gemm_stage_load_h(gsm + ((it + 1) & 1) * GSTG, Ah, Al, Bh,
                              bm, bn, K, (it + 1) * GBK, tid);
            __pipeline_commit();
            __pipeline_wait_prior(1);
        } else {
            __pipeline_wait_prior(0);
        }
        __syncthreads();

        __half* sAh = gsm + (it & 1) * GSTG;
        __half* sAl = sAh + GTILE;
        __half* sBh = sAh + 2 * GTILE;

        for (int ks = 0; ks < GBK; ks += 16) {
            nvcuda::wmma::fragment<nvcuda::wmma::matrix_a, 16, 16, 16,
                                   __half, nvcuda::wmma::row_major> fah[4];
            nvcuda::wmma::fragment<nvcuda::wmma::matrix_a, 16, 16, 16,
                                   __half, nvcuda::wmma::row_major> fal[4];
            nvcuda::wmma::fragment<nvcuda::wmma::matrix_b, 16, 16, 16,
                                   __half, nvcuda::wmma::col_major> fbh[2];
            for (int i = 0; i < 4; i++) {
                nvcuda::wmma::load_matrix_sync(fah[i], sAh + (wm + i * 16) * GLDS + ks, GLDS);
                nvcuda::wmma::load_matrix_sync(fal[i], sAl + (wm + i * 16) * GLDS + ks, GLDS);
            }
            for (int j = 0; j < 2; j++) {
                nvcuda::wmma::load_matrix_sync(fbh[j], sBh + (wn + j * 16) * GLDS + ks, GLDS);
            }
            for (int i = 0; i < 4; i++) {
                for (int j = 0; j < 2; j++) {
                    nvcuda::wmma::mma_sync(acc[i][j], fah[i], fbh[j], acc[i][j]);
                    nvcuda::wmma::mma_sync(acc[i][j], fal[i], fbh[j], acc[i][j]);
                }
            }
        }
        __syncthreads();
    }

    for (int i = 0; i < 4; i++) {
        for (int j = 0; j < 2; j++) {
            float* cp = C + (size_t)(bm + wm + i * 16) * N + bn + wn + j * 16;
            nvcuda::wmma::store_matrix_sync(cp, acc[i][j], N, nvcuda::wmma::mem_row_major);
        }
    }
}

// ---------------- RMSNorm + RoPE (+gain), output bf16 hi/lo ----------------
__global__ void rms_rope_kernel(const float* __restrict__ src,
                                __nv_bfloat16* __restrict__ dsth,
                                __nv_bfloat16* __restrict__ dstl,
                                const float* __restrict__ gain, int nheads)
{
    const int m = blockIdx.x;
    const int h = blockIdx.y;
    const int d = threadIdx.x;
    const int b = m / T_SEQ;
    const int t = m % T_SEQ;

    float x = src[(size_t)m * ((size_t)nheads * HD) + h * HD + d];
    float ss = x * x;
#pragma unroll
    for (int o = 16; o > 0; o >>= 1) ss += __shfl_xor_sync(0xffffffffu, ss, o);
    __shared__ float red[4];
    __shared__ float sv[HD];
    if ((d & 31) == 0) red[d >> 5] = ss;
    __syncthreads();
    float tot = red[0] + red[1] + red[2] + red[3];
    float r = rsqrtf(tot * (1.0f / HD) + EPS_F);
    sv[d] = x * r;
    __syncthreads();
    if (d < 64) {
        float x1 = sv[d];
        float x2 = sv[d + 64];
        float fr = powf(10000.0f, -(float)d * (1.0f / 64.0f));
        float ang = (float)t * fr;
        float sn, cs;
        sincosf(ang, &sn, &cs);
        float g = (gain != 0) ? gain[h] : 1.0f;
        float v1 = (x1 * cs + x2 * sn) * g;
        float v2 = (x2 * cs - x1 * sn) * g;
        size_t base = ((size_t)(b * nheads + h) * T_SEQ + t) * HD;
        __nv_bfloat16 h1 = __float2bfloat16(v1);
        __nv_bfloat16 h2 = __float2bfloat16(v2);
        dsth[base + d]      = h1;
        dsth[base + 64 + d] = h2;
        dstl[base + d]      = __float2bfloat16(v1 - __bfloat162float(h1));
        dstl[base + 64 + d] = __float2bfloat16(v2 - __bfloat162float(h2));
    }
}

// ---------------- Flash attention (WMMA bf16x3, fp32 softmax, causal, GQA) ----------------
#define FBQ 64
#define FBK 64
#define QLD 136
#define PLD 72
#define SLD 68

#define OQH 0
#define OQL (OQH + FBQ * QLD * 2)
#define OKH (OQL + FBQ * QLD * 2)
#define OKL (OKH + FBK * QLD * 2)
#define OVH (OKL + FBK * QLD * 2)
#define OVL (OVH + FBK * QLD * 2)
#define OPH (OVL + FBK * QLD * 2)
#define OPL (OPH + FBQ * PLD * 2)
#define OSF (OPL + FBQ * PLD * 2)
#define OMR (OSF + FBQ * 128 * 4)
#define OLR (OMR + 256)
#define OAR (OLR + 256)
#define FA2_SMEM (OAR + 256)

__global__ __launch_bounds__(256) void flash_mma(
    const __nv_bfloat16* __restrict__ Qhi, const __nv_bfloat16* __restrict__ Qlo,
    const __nv_bfloat16* __restrict__ Khi, const __nv_bfloat16* __restrict__ Klo,
    const __nv_bfloat16* __restrict__ Vhi, const __nv_bfloat16* __restrict__ Vlo,
    __half* __restrict__ Yh, __half* __restrict__ Yl)
{
    extern __shared__ char smb[];
    __nv_bfloat16* sQh = (__nv_bfloat16*)(smb + OQH);
    __nv_bfloat16* sQl = (__nv_bfloat16*)(smb + OQL);
    __nv_bfloat16* sKh = (__nv_bfloat16*)(smb + OKH);
    __nv_bfloat16* sKl = (__nv_bfloat16*)(smb + OKL);
    __nv_bfloat16* sVh = (__nv_bfloat16*)(smb + OVH);
    __nv_bfloat16* sVl = (__nv_bfloat16*)(smb + OVL);
    __nv_bfloat16* sPh = (__nv_bfloat16*)(smb + OPH);
    __nv_bfloat16* sPl = (__nv_bfloat16*)(smb + OPL);
    float* sSf  = (float*)(smb + OSF);
    float* sOd  = (float*)(smb + OSF);
    float* mrow = (float*)(smb + OMR);
    float* lrow = (float*)(smb + OLR);
    float* arow = (float*)(smb + OAR);

    const int tid  = threadIdx.x;
    const int warp = tid / 32;
    const int qt = blockIdx.x;
    const int h  = blockIdx.y;
    const int b  = blockIdx.z;
    const int kh = h >> 2;
    const int q0 = qt * FBQ;

    const __nv_bfloat16* qsh = Qhi + ((size_t)(b * NHEADS + h) * T_SEQ + q0) * HD;
    const __nv_bfloat16* qsl = Qlo + ((size_t)(b * NHEADS + h) * T_SEQ + q0) * HD;
    for (int i = tid; i < FBQ * HD / 8; i += 256) {
        int r = i >> 4;
        int c = (i & 15) * 8;
        *(uint4*)(sQh + r * QLD + c) = *(const uint4*)(qsh + (size_t)r * HD + c);
        *(uint4*)(sQl + r * QLD + c) = *(const uint4*)(qsl + (size_t)r * HD + c);
    }
    if (tid < 64) {
        mrow[tid] = -1e30f;
        lrow[tid] = 0.f;
    }

    float o[32];
#pragma unroll
    for (int j = 0; j < 32; j++) o[j] = 0.f;

    const int ro = tid >> 2;
    const int cq = tid & 3;
    __syncthreads();

    for (int kt = 0; kt <= qt; kt++) {
        const int k0 = kt * FBK;
        const __nv_bfloat16* ksh = Khi + ((size_t)(b * NKVH + kh) * T_SEQ + k0) * HD;
        const __nv_bfloat16* ksl = Klo + ((size_t)(b * NKVH + kh) * T_SEQ + k0) * HD;
        const __nv_bfloat16* vsh = Vhi + ((size_t)(b * T_SEQ) + k0) * RANK + kh * HD;
        const __nv_bfloat16* vsl = Vlo + ((size_t)(b * T_SEQ) + k0) * RANK + kh * HD;
        for (int i = tid; i < FBK * HD / 8; i += 256) {
            int r = i >> 4;
            int c = (i & 15) * 8;
            *(uint4*)(sKh + r * QLD + c) = *(const uint4*)(ksh + (size_t)r * HD + c);
            *(uint4*)(sKl + r * QLD + c) = *(const uint4*)(ksl + (size_t)r * HD + c);
            *(uint4*)(sVh + r * QLD + c) = *(const uint4*)(vsh + (size_t)r * RANK + c);
            *(uint4*)(sVl + r * QLD + c) = *(const uint4*)(vsl + (size_t)r * RANK + c);
        }
        __syncthreads();

        // ---- S = Q K^T (bf16x3) ----
        {
            const int wm  = warp % 4;
            const int wc0 = (warp / 4) * 2;
            nvcuda::wmma::fragment<nvcuda::wmma::accumulator, 16, 16, 16, float> accs[2];
            for (int j = 0; j < 2; j++) nvcuda::wmma::fill_fragment(accs[j], 0.0f);
            for (int ks = 0; ks < HD; ks += 16) {
                nvcuda::wmma::fragment<nvcuda::wmma::matrix_a, 16, 16, 16,
                                       __nv_bfloat16, nvcuda::wmma::row_major> fah;
                nvcuda::wmma::fragment<nvcuda::wmma::matrix_a, 16, 16, 16,
                                       __nv_bfloat16, nvcuda::wmma::row_major> fal;
                nvcuda::wmma::load_matrix_sync(fah, sQh + (wm * 16) * QLD + ks, QLD);
                nvcuda::wmma::load_matrix_sync(fal, sQl + (wm * 16) * QLD + ks, QLD);
                for (int j = 0; j < 2; j++) {
                    nvcuda::wmma::fragment<nvcuda::wmma::matrix_b, 16, 16, 16,
                                           __nv_bfloat16, nvcuda::wmma::col_major> fbh;
                    nvcuda::wmma::fragment<nvcuda::wmma::matrix_b, 16, 16, 16,
                                           __nv_bfloat16, nvcuda::wmma::col_major> fbl;
                    nvcuda::wmma::load_matrix_sync(fbh, sKh + ((wc0 + j) * 16) * QLD + ks, QLD);
                    nvcuda::wmma::load_matrix_sync(fbl, sKl + ((wc0 + j) * 16) * QLD + ks, QLD);
                    nvcuda::wmma::mma_sync(accs[j], fah, fbh, accs[j]);
                    nvcuda::wmma::mma_sync(accs[j], fah, fbl, accs[j]);
                    nvcuda::wmma::mma_sync(accs[j], fal, fbh, accs[j]);
                }
            }
            for (int j = 0; j < 2; j++) {
                nvcuda::wmma::store_matrix_sync(sSf + (wm * 16) * SLD + (wc0 + j) * 16,
                                                accs[j], SLD, nvcuda::wmma::mem_row_major);
            }
        }
        __syncthreads();

        // ---- online softmax (4 threads per row) ----
        {
            const int r  = tid >> 2;
            const int qq = tid & 3;
            const int qg = q0 + r;
            float mold = mrow[r];
            float vals[16];
            float rmax = mold;
#pragma unroll
            for (int j = 0; j < 16; j++) {
                int c = qq + 4 * j;
                float v = sSf[r * SLD + c] * SCALE_F;
                if (k0 + c > qg) v = -1e30f;
                vals[j] = v;
                rmax = fmaxf(rmax, v);
            }
            rmax = fmaxf(rmax, __shfl_xor_sync(0xffffffffu, rmax, 1));
            rmax = fmaxf(rmax, __shfl_xor_sync(0xffffffffu, rmax, 2));
            float alpha = __expf(mold - rmax);
            float rsum = 0.f;
#pragma unroll
            for (int j = 0; j < 16; j++) {
                int c = qq + 4 * j;
                float p = __expf(vals[j] - rmax);
                __nv_bfloat16 ph = __float2bfloat16(p);
                sPh[r * PLD + c] = ph;
                sPl[r * PLD + c] = __float2bfloat16(p - __bfloat162float(ph));
                rsum += p;
            }
            rsum += __shfl_xor_sync(0xffffffffu, rsum, 1);
            rsum += __shfl_xor_sync(0xffffffffu, rsum, 2);
            if (qq == 0) {
                lrow[r] = lrow[r] * alpha + rsum;
                mrow[r] = rmax;
                arow[r] = alpha;
            }
        }
        __syncthreads();

        // ---- O_delta = P V (bf16x3) ----
        {
            const int wm  = warp % 4;
            const int wn0 = (warp / 4) * 4;
            nvcuda::wmma::fragment<nvcuda::wmma::accumulator, 16, 16, 16, float> accd[4];
            for (int j = 0; j < 4; j++) nvcuda::wmma::fill_fragment(accd[j], 0.0f);
            for (int kc = 0; kc < FBK; kc += 16) {
                nvcuda::wmma::fragment<nvcuda::wmma::matrix_a, 16, 16, 16,
                                       __nv_bfloat16, nvcuda::wmma::row_major> pah;
                nvcuda::wmma::fragment<nvcuda::wmma::matrix_a, 16, 16, 16,
                                       __nv_bfloat16, nvcuda::wmma::row_major> pal;
                nvcuda::wmma::load_matrix_sync(pah, sPh + (wm * 16) * PLD + kc, PLD);
                nvcuda::wmma::load_matrix_sync(pal, sPl + (wm * 16) * PLD + kc, PLD);
                for (int j = 0; j < 4; j++) {
                    nvcuda::wmma::fragment<nvcuda::wmma::matrix_b, 16, 16, 16,
                                           __nv_bfloat16, nvcuda::wmma::row_major> vbh;
                    nvcuda::wmma::fragment<nvcuda::wmma::matrix_b, 16, 16, 16,
                                           __nv_bfloat16, nvcuda::wmma::row_major> vbl;
                    nvcuda::wmma::load_matrix_sync(vbh, sVh + kc * QLD + (wn0 + j) * 16, QLD);
                    nvcuda::wmma::load_matrix_sync(vbl, sVl + kc * QLD + (wn0 + j) * 16, QLD);
                    nvcuda::wmma::mma_sync(accd[j], pah, vbh, accd[j]);
                    nvcuda::wmma::mma_sync(accd[j], pal, vbh, accd[j]);
                    nvcuda::wmma::mma_sync(accd[j], pah, vbl, accd[j]);
                }
            }
            for (int j = 0; j < 4; j++) {
                nvcuda::wmma::store_matrix_sync(sOd + (wm * 16) * 128 + (wn0 + j) * 16,
                                                accd[j], 128, nvcuda::wmma::mem_row_major);
            }
        }
        __syncthreads();

        // ---- o = o * alpha + O_delta ----
        {
            float alpha = arow[ro];
            const float* od = sOd + ro * 128 + cq * 32;
#pragma unroll
            for (int j = 0; j < 32; j++) o[j] = o[j] * alpha + od[j];
        }
        __syncthreads();
    }

    // epilogue: normalize, write fp16 hi/lo for the Wproj GEMM
    float inv = 1.0f / lrow[ro];
    size_t yb = ((size_t)(b * T_SEQ) + q0 + ro) * DIM + h * HD + cq * 32;
#pragma unroll
    for (int j = 0; j < 32; j++) {
        float v = o[j] * inv;
        __half hv = __float2half(v);
        Yh[yb + j] = hv;
        Yl[yb + j] = __float2half(v - __half2float(hv));
    }
}

// ---------------- Launch ----------------
extern "C" void kernel_launch(void* const* d_in, const int* in_sizes, int n_in,
                              void* d_out, int out_size)
{
    (void)in_sizes;
    (void)n_in;
    (void)out_size;
    const float* x     = (const float*)d_in[0];
    const float* Wq    = (const float*)d_in[1];
    const float* Wdown = (const float*)d_in[2];
    const float* Wkup  = (const float*)d_in[3];
    const float* Wvup  = (const float*)d_in[4];
    const float* Wproj = (const float*)d_in[5];
    const float* qgain = (const float*)d_in[6];
    float* out = (float*)d_out;

    float* q;
    float* lat;
    float* kt;
    float* vt;
    cudaGetSymbolAddress((void**)&q,   g_q);
    cudaGetSymbolAddress((void**)&lat, g_lat);
    cudaGetSymbolAddress((void**)&kt,  g_kt);
    cudaGetSymbolAddress((void**)&vt,  g_vt);

    __half* xhi;
    __half* xlo;
    __half* lhi;
    __half* llo;
    __half* yhi;
    __half* ylo;
    __half* wqh;
    __half* wdh;
    __half* wkh;
    __half* wvh;
    __half* wph;
    cudaGetSymbolAddress((void**)&xhi, g_xhi);
    cudaGetSymbolAddress((void**)&xlo, g_xlo);
    cudaGetSymbolAddress((void**)&lhi, g_lhi);
    cudaGetSymbolAddress((void**)&llo, g_llo);
    cudaGetSymbolAddress((void**)&yhi, g_yhi);
    cudaGetSymbolAddress((void**)&ylo, g_ylo);
    cudaGetSymbolAddress((void**)&wqh, g_wqh);
    cudaGetSymbolAddress((void**)&wdh, g_wdh);
    cudaGetSymbolAddress((void**)&wkh, g_wkh);
    cudaGetSymbolAddress((void**)&wvh, g_wvh);
    cudaGetSymbolAddress((void**)&wph, g_wph);

    __nv_bfloat16* qah;
    __nv_bfloat16* qal;
    __nv_bfloat16* kah;
    __nv_bfloat16* kal;
    __nv_bfloat16* vth;
    __nv_bfloat16* vtl;
    cudaGetSymbolAddress((void**)&qah, g_qah);
    cudaGetSymbolAddress((void**)&qal, g_qal);
    cudaGetSymbolAddress((void**)&kah, g_kah);
    cudaGetSymbolAddress((void**)&kal, g_kal);
    cudaGetSymbolAddress((void**)&vth, g_vth);
    cudaGetSymbolAddress((void**)&vtl, g_vtl);

    cudaFuncSetAttribute(gemm_h, cudaFuncAttributeMaxDynamicSharedMemorySize,
                         GSMEM_BYTES);
    cudaFuncSetAttribute(flash_mma, cudaFuncAttributeMaxDynamicSharedMemorySize,
                         FA2_SMEM);

    int n1 = NE_MD;
    int n2 = NE_DD;
    int n3 = NE_RD;
    int n4 = NE_RR;
    int n5 = NE_MR;
    split_kernel_h<<<(n1 + 255) / 256, 256>>>(x, xhi, xlo, n1);
    conv_kernel_h<<<(n2 + 255) / 256, 256>>>(Wq, wqh, n2);
    conv_kernel_h<<<(n3 + 255) / 256, 256>>>(Wdown, wdh, n3);
    conv_kernel_h<<<(n4 + 255) / 256, 256>>>(Wkup, wkh, n4);
    conv_kernel_h<<<(n4 + 255) / 256, 256>>>(Wvup, wvh, n4);
    conv_kernel_h<<<(n2 + 255) / 256, 256>>>(Wproj, wph, n2);

    gemm_h<<<dim3(RANK / GBN, M_ROWS / GBM), 256, GSMEM_BYTES>>>(
        xhi, xlo, wdh, lat, M_ROWS, RANK, DIM);
    gemm_h<<<dim3(DIM / GBN, M_ROWS / GBM), 256, GSMEM_BYTES>>>(
        xhi, xlo, wqh, q, M_ROWS, DIM, DIM);
    split_kernel_h<<<(n5 + 255) / 256, 256>>>(lat, lhi, llo, n5);
    gemm_h<<<dim3(RANK / GBN, M_ROWS / GBM), 256, GSMEM_BYTES>>>(
        lhi, llo, wkh, kt, M_ROWS, RANK, RANK);
    gemm_h<<<dim3(RANK / GBN, M_ROWS / GBM), 256, GSMEM_BYTES>>>(
        lhi, llo, wvh, vt, M_ROWS, RANK, RANK);

    rms_rope_kernel<<<dim3(M_ROWS, NHEADS), 128>>>(q, qah, qal, qgain, NHEADS);
    rms_rope_kernel<<<dim3(M_ROWS, NKVH), 128>>>(kt, kah, kal, (const float*)0, NKVH);
    split_kernel_bf<<<(n5 + 255) / 256, 256>>>(vt, vth, vtl, n5);

    flash_mma<<<dim3(T_SEQ / FBQ, NHEADS, BATCH), 256, FA2_SMEM>>>(qah, qal, kah, kal,
                                                                   vth, vtl, yhi, ylo);

    gemm_h<<<dim3(DIM / GBN, M_ROWS / GBM), 256, GSMEM_BYTES>>>(
        yhi, ylo, wph, out, M_ROWS, DIM, DIM);
}

// round 9
// speedup vs baseline: 2.8528x; 1.0410x over previous
#include <cuda_runtime.h>
#include <cuda_bf16.h>
#include <cuda_fp16.h>
#include <cuda_pipeline.h>
#include <mma.h>
#include <math.h>

// ---------------- Problem constants ----------------
#define T_SEQ  2048
#define BATCH  2
#define NHEADS 16
#define NKVH   4
#define HD     128
#define DIM    2048
#define RANK   512
#define M_ROWS (BATCH * T_SEQ)
#define EPS_F  1.1920928955078125e-07f
#define SCALE_F 0.08838834764831845f

#define NE_MD (M_ROWS * DIM)
#define NE_MR (M_ROWS * RANK)
#define NE_DD (DIM * DIM)
#define NE_RD (RANK * DIM)
#define NE_RR (RANK * RANK)

// ---------------- Scratch (static device globals; no allocation) ----------------
__device__ float g_q  [NE_MD];
__device__ float g_kt [NE_MR];
__device__ float g_vt [NE_MR];

// fp16 GEMM operands
__device__ __half g_xhi[NE_MD];
__device__ __half g_xlo[NE_MD];
__device__ __half g_lhi[NE_MR];
__device__ __half g_llo[NE_MR];
__device__ __half g_yhi[NE_MD];
__device__ __half g_ylo[NE_MD];
__device__ __half g_wqh[NE_DD];
__device__ __half g_wdh[NE_RD];
__device__ __half g_wkh[NE_RR];
__device__ __half g_wvh[NE_RR];
__device__ __half g_wph[NE_DD];

// flash operands (bf16 hi/lo)
__device__ __nv_bfloat16 g_qah[NE_MD];
__device__ __nv_bfloat16 g_qal[NE_MD];
__device__ __nv_bfloat16 g_kah[NE_MR];
__device__ __nv_bfloat16 g_kal[NE_MR];
__device__ __nv_bfloat16 g_vth[NE_MR];
__device__ __nv_bfloat16 g_vtl[NE_MR];

// ---------------- conversions ----------------
__global__ void split_kernel_bf(const float* __restrict__ x,
                                __nv_bfloat16* __restrict__ hi,
                                __nv_bfloat16* __restrict__ lo, int n)
{
    int i = blockIdx.x * blockDim.x + threadIdx.x;
    if (i < n) {
        float v = x[i];
        __nv_bfloat16 h = __float2bfloat16(v);
        hi[i] = h;
        lo[i] = __float2bfloat16(v - __bfloat162float(h));
    }
}

__global__ void split_kernel_h(const float* __restrict__ x,
                               __half* __restrict__ hi,
                               __half* __restrict__ lo, int n)
{
    int i = blockIdx.x * blockDim.x + threadIdx.x;
    if (i < n) {
        float v = x[i];
        __half h = __float2half(v);
        hi[i] = h;
        lo[i] = __float2half(v - __half2float(h));
    }
}

__global__ void conv_kernel_h(const float* __restrict__ x,
                              __half* __restrict__ hi, int n)
{
    int i = blockIdx.x * blockDim.x + threadIdx.x;
    if (i < n) {
        hi[i] = __float2half(x[i]);
    }
}

// ---------------- WMMA fp16x2 GEMM, cp.async 3-stage ----------------
#define GBM 128
#define GBN 128
#define GBK 32
#define GLDS 40
#define GTILE (GBM * GLDS)
#define GSTG (3 * GTILE)
#define GSMEM_BYTES (3 * GSTG * 2)          // 92160

__device__ __forceinline__ void gemm_stage_load_h(
    __half* s,
    const __half* Ah, const __half* Al, const __half* Bh,
    int bm, int bn, int K, int k0, int tid)
{
    __half* sAh = s;
    __half* sAl = s + GTILE;
    __half* sBh = s + 2 * GTILE;
    for (int i = 0; i < 2; i++) {
        int idx = tid + 256 * i;
        int row = idx >> 2;
        int c8  = (idx & 3) * 8;
        __pipeline_memcpy_async(sAh + row * GLDS + c8,
                                Ah + (size_t)(bm + row) * K + k0 + c8, 16);
        __pipeline_memcpy_async(sAl + row * GLDS + c8,
                                Al + (size_t)(bm + row) * K + k0 + c8, 16);
        __pipeline_memcpy_async(sBh + row * GLDS + c8,
                                Bh + (size_t)(bn + row) * K + k0 + c8, 16);
    }
}

// shared mainloop body as a macro-free pattern: two kernels share structure.
__global__ __launch_bounds__(256) void gemm_h(
    const __half* __restrict__ Ah, const __half* __restrict__ Al,
    const __half* __restrict__ Bh,
    float* __restrict__ C, int M, int N, int K)
{
    extern __shared__ __half gsm[];

    const int tid  = threadIdx.x;
    const int warp = tid / 32;
    const int wm   = (warp % 2) * 64;
    const int wn   = (warp / 2) * 32;
    const int bm   = blockIdx.y * GBM;
    const int bn   = blockIdx.x * GBN;

    nvcuda::wmma::fragment<nvcuda::wmma::accumulator, 16, 16, 16, float> acc[4][2];
    for (int i = 0; i < 4; i++) {
        for (int j = 0; j < 2; j++) {
            nvcuda::wmma::fill_fragment(acc[i][j], 0.0f);
        }
    }

    const int nk = K / GBK;

    gemm_stage_load_h(gsm, Ah, Al, Bh, bm, bn, K, 0, tid);
    __pipeline_commit();
    gemm_stage_load_h(gsm + GSTG, Ah, Al, Bh, bm, bn, K, GBK, tid);
    __pipeline_commit();

    for (int it = 0; it < nk; it++) {
        if (it + 2 < nk) {
            int st = (it + 2) % 3;
            gemm_stage_load_h(gsm + st * GSTG, Ah, Al, Bh, bm, bn, K,
                              (it + 2) * GBK, tid);
            __pipeline_commit();
            __pipeline_wait_prior(2);
        } else if (it + 1 < nk) {
            __pipeline_wait_prior(1);
        } else {
            __pipeline_wait_prior(0);
        }
        __syncthreads();

        __half* sAh = gsm + (it % 3) * GSTG;
        __half* sAl = sAh + GTILE;
        __half* sBh = sAh + 2 * GTILE;

        for (int ks = 0; ks < GBK; ks += 16) {
            nvcuda::wmma::fragment<nvcuda::wmma::matrix_a, 16, 16, 16,
                                   __half, nvcuda::wmma::row_major> fah[4];
            nvcuda::wmma::fragment<nvcuda::wmma::matrix_a, 16, 16, 16,
                                   __half, nvcuda::wmma::row_major> fal[4];
            nvcuda::wmma::fragment<nvcuda::wmma::matrix_b, 16, 16, 16,
                                   __half, nvcuda::wmma::col_major> fbh[2];
            for (int i = 0; i < 4; i++) {
                nvcuda::wmma::load_matrix_sync(fah[i], sAh + (wm + i * 16) * GLDS + ks, GLDS);
                nvcuda::wmma::load_matrix_sync(fal[i], sAl + (wm + i * 16) * GLDS + ks, GLDS);
            }
            for (int j = 0; j < 2; j++) {
                nvcuda::wmma::load_matrix_sync(fbh[j], sBh + (wn + j * 16) * GLDS + ks, GLDS);
            }
            for (int i = 0; i < 4; i++) {
                for (int j = 0; j < 2; j++) {
                    nvcuda::wmma::mma_sync(acc[i][j], fah[i], fbh[j], acc[i][j]);
                    nvcuda::wmma::mma_sync(acc[i][j], fal[i], fbh[j], acc[i][j]);
                }
            }
        }
        __syncthreads();
    }

    for (int i = 0; i < 4; i++) {
        for (int j = 0; j < 2; j++) {
            float* cp = C + (size_t)(bm + wm + i * 16) * N + bn + wn + j * 16;
            nvcuda::wmma::store_matrix_sync(cp, acc[i][j], N, nvcuda::wmma::mem_row_major);
        }
    }
}

// same GEMM but epilogue writes fp16 hi/lo (for the latent path)
__global__ __launch_bounds__(256) void gemm_h_sp16(
    const __half* __restrict__ Ah, const __half* __restrict__ Al,
    const __half* __restrict__ Bh,
    __half* __restrict__ Chi, __half* __restrict__ Clo, int M, int N, int K)
{
    extern __shared__ __half gsm[];

    const int tid  = threadIdx.x;
    const int warp = tid / 32;
    const int wm   = (warp % 2) * 64;
    const int wn   = (warp / 2) * 32;
    const int bm   = blockIdx.y * GBM;
    const int bn   = blockIdx.x * GBN;

    nvcuda::wmma::fragment<nvcuda::wmma::accumulator, 16, 16, 16, float> acc[4][2];
    for (int i = 0; i < 4; i++) {
        for (int j = 0; j < 2; j++) {
            nvcuda::wmma::fill_fragment(acc[i][j], 0.0f);
        }
    }

    const int nk = K / GBK;

    gemm_stage_load_h(gsm, Ah, Al, Bh, bm, bn, K, 0, tid);
    __pipeline_commit();
    gemm_stage_load_h(gsm + GSTG, Ah, Al, Bh, bm, bn, K, GBK, tid);
    __pipeline_commit();

    for (int it = 0; it < nk; it++) {
        if (it + 2 < nk) {
            int st = (it + 2) % 3;
            gemm_stage_load_h(gsm + st * GSTG, Ah, Al, Bh, bm, bn, K,
                              (it + 2) * GBK, tid);
            __pipeline_commit();
            __pipeline_wait_prior(2);
        } else if (it + 1 < nk) {
            __pipeline_wait_prior(1);
        } else {
            __pipeline_wait_prior(0);
        }
        __syncthreads();

        __half* sAh = gsm + (it % 3) * GSTG;
        __half* sAl = sAh + GTILE;
        __half* sBh = sAh + 2 * GTILE;

        for (int ks = 0; ks < GBK; ks += 16) {
            nvcuda::wmma::fragment<nvcuda::wmma::matrix_a, 16, 16, 16,
                                   __half, nvcuda::wmma::row_major> fah[4];
            nvcuda::wmma::fragment<nvcuda::wmma::matrix_a, 16, 16, 16,
                                   __half, nvcuda::wmma::row_major> fal[4];
            nvcuda::wmma::fragment<nvcuda::wmma::matrix_b, 16, 16, 16,
                                   __half, nvcuda::wmma::col_major> fbh[2];
            for (int i = 0; i < 4; i++) {
                nvcuda::wmma::load_matrix_sync(fah[i], sAh + (wm + i * 16) * GLDS + ks, GLDS);
                nvcuda::wmma::load_matrix_sync(fal[i], sAl + (wm + i * 16) * GLDS + ks, GLDS);
            }
            for (int j = 0; j < 2; j++) {
                nvcuda::wmma::load_matrix_sync(fbh[j], sBh + (wn + j * 16) * GLDS + ks, GLDS);
            }
            for (int i = 0; i < 4; i++) {
                for (int j = 0; j < 2; j++) {
                    nvcuda::wmma::mma_sync(acc[i][j], fah[i], fbh[j], acc[i][j]);
                    nvcuda::wmma::mma_sync(acc[i][j], fal[i], fbh[j], acc[i][j]);
                }
            }
        }
        __syncthreads();
    }

    // epilogue: stage fp32 through smem, emit fp16 hi/lo
    float* stage = (float*)gsm;
    for (int i = 0; i < 4; i++) {
        for (int j = 0; j < 2; j++) {
            nvcuda::wmma::store_matrix_sync(stage + (wm + i * 16) * 128 + wn + j * 16,
                                            acc[i][j], 128, nvcuda::wmma::mem_row_major);
        }
    }
    __syncthreads();
    for (int t = tid; t < GBM * GBN; t += 256) {
        int r = t >> 7;
        int c = t & 127;
        float v = stage[t];
        __half hv = __float2half(v);
        size_t gi = (size_t)(bm + r) * N + bn + c;
        Chi[gi] = hv;
        Clo[gi] = __float2half(v - __half2float(hv));
    }
}

// ---------------- RMSNorm + RoPE (+gain), output bf16 hi/lo ----------------
__global__ void rms_rope_kernel(const float* __restrict__ src,
                                __nv_bfloat16* __restrict__ dsth,
                                __nv_bfloat16* __restrict__ dstl,
                                const float* __restrict__ gain, int nheads)
{
    const int m = blockIdx.x;
    const int h = blockIdx.y;
    const int d = threadIdx.x;
    const int b = m / T_SEQ;
    const int t = m % T_SEQ;

    float x = src[(size_t)m * ((size_t)nheads * HD) + h * HD + d];
    float ss = x * x;
#pragma unroll
    for (int o = 16; o > 0; o >>= 1) ss += __shfl_xor_sync(0xffffffffu, ss, o);
    __shared__ float red[4];
    __shared__ float sv[HD];
    if ((d & 31) == 0) red[d >> 5] = ss;
    __syncthreads();
    float tot = red[0] + red[1] + red[2] + red[3];
    float r = rsqrtf(tot * (1.0f / HD) + EPS_F);
    sv[d] = x * r;
    __syncthreads();
    if (d < 64) {
        float x1 = sv[d];
        float x2 = sv[d + 64];
        float fr = powf(10000.0f, -(float)d * (1.0f / 64.0f));
        float ang = (float)t * fr;
        float sn, cs;
        sincosf(ang, &sn, &cs);
        float g = (gain != 0) ? gain[h] : 1.0f;
        float v1 = (x1 * cs + x2 * sn) * g;
        float v2 = (x2 * cs - x1 * sn) * g;
        size_t base = ((size_t)(b * nheads + h) * T_SEQ + t) * HD;
        __nv_bfloat16 h1 = __float2bfloat16(v1);
        __nv_bfloat16 h2 = __float2bfloat16(v2);
        dsth[base + d]      = h1;
        dsth[base + 64 + d] = h2;
        dstl[base + d]      = __float2bfloat16(v1 - __bfloat162float(h1));
        dstl[base + 64 + d] = __float2bfloat16(v2 - __bfloat162float(h2));
    }
}

// ---------------- Flash attention (WMMA bf16x3, K/V double-buffered) ----------------
#define FBQ 64
#define FBK 64
#define QLD 136
#define PLD 72
#define SLD 68

#define OQH 0
#define OQL (OQH + FBQ * QLD * 2)
#define OKV (OQL + FBQ * QLD * 2)
#define KVTILE (FBK * QLD * 2)
#define KVSTG (4 * KVTILE)
#define OPH (OKV + 2 * KVSTG)
#define OPL (OPH + FBQ * PLD * 2)
#define OSF (OPL + FBQ * PLD * 2)
#define OMR (OSF + FBQ * 128 * 4)
#define OLR (OMR + 256)
#define OAR (OLR + 256)
#define FA3_SMEM (OAR + 256)

__device__ __forceinline__ void fa_stage_load(
    char* smb, int s,
    const __nv_bfloat16* ksh, const __nv_bfloat16* ksl,
    const __nv_bfloat16* vsh, const __nv_bfloat16* vsl, int tid)
{
    char* st = smb + OKV + s * KVSTG;
    __nv_bfloat16* sKh = (__nv_bfloat16*)st;
    __nv_bfloat16* sKl = (__nv_bfloat16*)(st + KVTILE);
    __nv_bfloat16* sVh = (__nv_bfloat16*)(st + 2 * KVTILE);
    __nv_bfloat16* sVl = (__nv_bfloat16*)(st + 3 * KVTILE);
    for (int i = 0; i < 4; i++) {
        int idx = tid + 256 * i;
        int r = idx >> 4;
        int c = (idx & 15) * 8;
        __pipeline_memcpy_async(sKh + r * QLD + c, ksh + (size_t)r * HD + c, 16);
        __pipeline_memcpy_async(sKl + r * QLD + c, ksl + (size_t)r * HD + c, 16);
        __pipeline_memcpy_async(sVh + r * QLD + c, vsh + (size_t)r * RANK + c, 16);
        __pipeline_memcpy_async(sVl + r * QLD + c, vsl + (size_t)r * RANK + c, 16);
    }
}

__global__ __launch_bounds__(256) void flash_mma(
    const __nv_bfloat16* __restrict__ Qhi, const __nv_bfloat16* __restrict__ Qlo,
    const __nv_bfloat16* __restrict__ Khi, const __nv_bfloat16* __restrict__ Klo,
    const __nv_bfloat16* __restrict__ Vhi, const __nv_bfloat16* __restrict__ Vlo,
    __half* __restrict__ Yh, __half* __restrict__ Yl)
{
    extern __shared__ char smb[];
    __nv_bfloat16* sQh = (__nv_bfloat16*)(smb + OQH);
    __nv_bfloat16* sQl = (__nv_bfloat16*)(smb + OQL);
    __nv_bfloat16* sPh = (__nv_bfloat16*)(smb + OPH);
    __nv_bfloat16* sPl = (__nv_bfloat16*)(smb + OPL);
    float* sSf  = (float*)(smb + OSF);
    float* sOd  = (float*)(smb + OSF);
    float* mrow = (float*)(smb + OMR);
    float* lrow = (float*)(smb + OLR);
    float* arow = (float*)(smb + OAR);

    const int tid  = threadIdx.x;
    const int warp = tid / 32;
    const int qt = (int)(gridDim.x - 1 - blockIdx.x);   // longest CTAs first
    const int h  = blockIdx.y;
    const int b  = blockIdx.z;
    const int kh = h >> 2;
    const int q0 = qt * FBQ;

    const __nv_bfloat16* Kh0 = Khi + ((size_t)(b * NKVH + kh) * T_SEQ) * HD;
    const __nv_bfloat16* Kl0 = Klo + ((size_t)(b * NKVH + kh) * T_SEQ) * HD;
    const __nv_bfloat16* Vh0 = Vhi + (size_t)b * T_SEQ * RANK + kh * HD;
    const __nv_bfloat16* Vl0 = Vlo + (size_t)b * T_SEQ * RANK + kh * HD;

    const __nv_bfloat16* qsh = Qhi + ((size_t)(b * NHEADS + h) * T_SEQ + q0) * HD;
    const __nv_bfloat16* qsl = Qlo + ((size_t)(b * NHEADS + h) * T_SEQ + q0) * HD;
    for (int i = tid; i < FBQ * HD / 8; i += 256) {
        int r = i >> 4;
        int c = (i & 15) * 8;
        *(uint4*)(sQh + r * QLD + c) = *(const uint4*)(qsh + (size_t)r * HD + c);
        *(uint4*)(sQl + r * QLD + c) = *(const uint4*)(qsl + (size_t)r * HD + c);
    }
    if (tid < 64) {
        mrow[tid] = -1e30f;
        lrow[tid] = 0.f;
    }

    float o[32];
#pragma unroll
    for (int j = 0; j < 32; j++) o[j] = 0.f;

    const int ro = tid >> 2;
    const int cq = tid & 3;

    fa_stage_load(smb, 0, Kh0, Kl0, Vh0, Vl0, tid);
    __pipeline_commit();
    __syncthreads();

    for (int kt = 0; kt <= qt; kt++) {
        const int k0 = kt * FBK;
        if (kt < qt) {
            int k1 = (kt + 1) * FBK;
            fa_stage_load(smb, (kt + 1) & 1,
                          Kh0 + (size_t)k1 * HD, Kl0 + (size_t)k1 * HD,
                          Vh0 + (size_t)k1 * RANK, Vl0 + (size_t)k1 * RANK, tid);
            __pipeline_commit();
            __pipeline_wait_prior(1);
        } else {
            __pipeline_wait_prior(0);
        }
        __syncthreads();

        char* stg = smb + OKV + (size_t)(kt & 1) * KVSTG;
        __nv_bfloat16* sKh = (__nv_bfloat16*)stg;
        __nv_bfloat16* sKl = (__nv_bfloat16*)(stg + KVTILE);
        __nv_bfloat16* sVh = (__nv_bfloat16*)(stg + 2 * KVTILE);
        __nv_bfloat16* sVl = (__nv_bfloat16*)(stg + 3 * KVTILE);

        // ---- S = Q K^T (bf16x3) ----
        {
            const int wm  = warp % 4;
            const int wc0 = (warp / 4) * 2;
            nvcuda::wmma::fragment<nvcuda::wmma::accumulator, 16, 16, 16, float> accs[2];
            for (int j = 0; j < 2; j++) nvcuda::wmma::fill_fragment(accs[j], 0.0f);
            for (int ks = 0; ks < HD; ks += 16) {
                nvcuda::wmma::fragment<nvcuda::wmma::matrix_a, 16, 16, 16,
                                       __nv_bfloat16, nvcuda::wmma::row_major> fah;
                nvcuda::wmma::fragment<nvcuda::wmma::matrix_a, 16, 16, 16,
                                       __nv_bfloat16, nvcuda::wmma::row_major> fal;
                nvcuda::wmma::load_matrix_sync(fah, sQh + (wm * 16) * QLD + ks, QLD);
                nvcuda::wmma::load_matrix_sync(fal, sQl + (wm * 16) * QLD + ks, QLD);
                for (int j = 0; j < 2; j++) {
                    nvcuda::wmma::fragment<nvcuda::wmma::matrix_b, 16, 16, 16,
                                           __nv_bfloat16, nvcuda::wmma::col_major> fbh;
                    nvcuda::wmma::fragment<nvcuda::wmma::matrix_b, 16, 16, 16,
                                           __nv_bfloat16, nvcuda::wmma::col_major> fbl;
                    nvcuda::wmma::load_matrix_sync(fbh, sKh + ((wc0 + j) * 16) * QLD + ks, QLD);
                    nvcuda::wmma::load_matrix_sync(fbl, sKl + ((wc0 + j) * 16) * QLD + ks, QLD);
                    nvcuda::wmma::mma_sync(accs[j], fah, fbh, accs[j]);
                    nvcuda::wmma::mma_sync(accs[j], fah, fbl, accs[j]);
                    nvcuda::wmma::mma_sync(accs[j], fal, fbh, accs[j]);
                }
            }
            for (int j = 0; j < 2; j++) {
                nvcuda::wmma::store_matrix_sync(sSf + (wm * 16) * SLD + (wc0 + j) * 16,
                                                accs[j], SLD, nvcuda::wmma::mem_row_major);
            }
        }
        __syncthreads();

        // ---- online softmax ----
        {
            const int r  = tid >> 2;
            const int qq = tid & 3;
            const int qg = q0 + r;
            float mold = mrow[r];
            float vals[16];
            float rmax = mold;
#pragma unroll
            for (int j = 0; j < 16; j++) {
                int c = qq + 4 * j;
                float v = sSf[r * SLD + c] * SCALE_F;
                if (k0 + c > qg) v = -1e30f;
                vals[j] = v;
                rmax = fmaxf(rmax, v);
            }
            rmax = fmaxf(rmax, __shfl_xor_sync(0xffffffffu, rmax, 1));
            rmax = fmaxf(rmax, __shfl_xor_sync(0xffffffffu, rmax, 2));
            float alpha = __expf(mold - rmax);
            float rsum = 0.f;
#pragma unroll
            for (int j = 0; j < 16; j++) {
                int c = qq + 4 * j;
                float p = __expf(vals[j] - rmax);
                __nv_bfloat16 ph = __float2bfloat16(p);
                sPh[r * PLD + c] = ph;
                sPl[r * PLD + c] = __float2bfloat16(p - __bfloat162float(ph));
                rsum += p;
            }
            rsum += __shfl_xor_sync(0xffffffffu, rsum, 1);
            rsum += __shfl_xor_sync(0xffffffffu, rsum, 2);
            if (qq == 0) {
                lrow[r] = lrow[r] * alpha + rsum;
                mrow[r] = rmax;
                arow[r] = alpha;
            }
        }
        __syncthreads();

        // ---- O_delta = P V (bf16x3) ----
        {
            const int wm  = warp % 4;
            const int wn0 = (warp / 4) * 4;
            nvcuda::wmma::fragment<nvcuda::wmma::accumulator, 16, 16, 16, float> accd[4];
            for (int j = 0; j < 4; j++) nvcuda::wmma::fill_fragment(accd[j], 0.0f);
            for (int kc = 0; kc < FBK; kc += 16) {
                nvcuda::wmma::fragment<nvcuda::wmma::matrix_a, 16, 16, 16,
                                       __nv_bfloat16, nvcuda::wmma::row_major> pah;
                nvcuda::wmma::fragment<nvcuda::wmma::matrix_a, 16, 16, 16,
                                       __nv_bfloat16, nvcuda::wmma::row_major> pal;
                nvcuda::wmma::load_matrix_sync(pah, sPh + (wm * 16) * PLD + kc, PLD);
                nvcuda::wmma::load_matrix_sync(pal, sPl + (wm * 16) * PLD + kc, PLD);
                for (int j = 0; j < 4; j++) {
                    nvcuda::wmma::fragment<nvcuda::wmma::matrix_b, 16, 16, 16,
                                           __nv_bfloat16, nvcuda::wmma::row_major> vbh;
                    nvcuda::wmma::fragment<nvcuda::wmma::matrix_b, 16, 16, 16,
                                           __nv_bfloat16, nvcuda::wmma::row_major> vbl;
                    nvcuda::wmma::load_matrix_sync(vbh, sVh + kc * QLD + (wn0 + j) * 16, QLD);
                    nvcuda::wmma::load_matrix_sync(vbl, sVl + kc * QLD + (wn0 + j) * 16, QLD);
                    nvcuda::wmma::mma_sync(accd[j], pah, vbh, accd[j]);
                    nvcuda::wmma::mma_sync(accd[j], pal, vbh, accd[j]);
                    nvcuda::wmma::mma_sync(accd[j], pah, vbl, accd[j]);
                }
            }
            for (int j = 0; j < 4; j++) {
                nvcuda::wmma::store_matrix_sync(sOd + (wm * 16) * 128 + (wn0 + j) * 16,
                                                accd[j], 128, nvcuda::wmma::mem_row_major);
            }
        }
        __syncthreads();

        // ---- o = o * alpha + O_delta ----
        {
            float alpha = arow[ro];
            const float* od = sOd + ro * 128 + cq * 32;
#pragma unroll
            for (int j = 0; j < 32; j++) o[j] = o[j] * alpha + od[j];
        }
        __syncthreads();
    }

    float inv = 1.0f / lrow[ro];
    size_t yb = ((size_t)(b * T_SEQ) + q0 + ro) * DIM + h * HD + cq * 32;
#pragma unroll
    for (int j = 0; j < 32; j++) {
        float v = o[j] * inv;
        __half hv = __float2half(v);
        Yh[yb + j] = hv;
        Yl[yb + j] = __float2half(v - __half2float(hv));
    }
}

// ---------------- Launch ----------------
extern "C" void kernel_launch(void* const* d_in, const int* in_sizes, int n_in,
                              void* d_out, int out_size)
{
    (void)in_sizes;
    (void)n_in;
    (void)out_size;
    const float* x     = (const float*)d_in[0];
    const float* Wq    = (const float*)d_in[1];
    const float* Wdown = (const float*)d_in[2];
    const float* Wkup  = (const float*)d_in[3];
    const float* Wvup  = (const float*)d_in[4];
    const float* Wproj = (const float*)d_in[5];
    const float* qgain = (const float*)d_in[6];
    float* out = (float*)d_out;

    float* q;
    float* kt;
    float* vt;
    cudaGetSymbolAddress((void**)&q,  g_q);
    cudaGetSymbolAddress((void**)&kt, g_kt);
    cudaGetSymbolAddress((void**)&vt, g_vt);

    __half* xhi;
    __half* xlo;
    __half* lhi;
    __half* llo;
    __half* yhi;
    __half* ylo;
    __half* wqh;
    __half* wdh;
    __half* wkh;
    __half* wvh;
    __half* wph;
    cudaGetSymbolAddress((void**)&xhi, g_xhi);
    cudaGetSymbolAddress((void**)&xlo, g_xlo);
    cudaGetSymbolAddress((void**)&lhi, g_lhi);
    cudaGetSymbolAddress((void**)&llo, g_llo);
    cudaGetSymbolAddress((void**)&yhi, g_yhi);
    cudaGetSymbolAddress((void**)&ylo, g_ylo);
    cudaGetSymbolAddress((void**)&wqh, g_wqh);
    cudaGetSymbolAddress((void**)&wdh, g_wdh);
    cudaGetSymbolAddress((void**)&wkh, g_wkh);
    cudaGetSymbolAddress((void**)&wvh, g_wvh);
    cudaGetSymbolAddress((void**)&wph, g_wph);

    __nv_bfloat16* qah;
    __nv_bfloat16* qal;
    __nv_bfloat16* kah;
    __nv_bfloat16* kal;
    __nv_bfloat16* vth;
    __nv_bfloat16* vtl;
    cudaGetSymbolAddress((void**)&qah, g_qah);
    cudaGetSymbolAddress((void**)&qal, g_qal);
    cudaGetSymbolAddress((void**)&kah, g_kah);
    cudaGetSymbolAddress((void**)&kal, g_kal);
    cudaGetSymbolAddress((void**)&vth, g_vth);
    cudaGetSymbolAddress((void**)&vtl, g_vtl);

    cudaFuncSetAttribute(gemm_h, cudaFuncAttributeMaxDynamicSharedMemorySize,
                         GSMEM_BYTES);
    cudaFuncSetAttribute(gemm_h_sp16, cudaFuncAttributeMaxDynamicSharedMemorySize,
                         GSMEM_BYTES);
    cudaFuncSetAttribute(flash_mma, cudaFuncAttributeMaxDynamicSharedMemorySize,
                         FA3_SMEM);

    int n1 = NE_MD;
    int n2 = NE_DD;
    int n3 = NE_RD;
    int n4 = NE_RR;
    int n5 = NE_MR;
    split_kernel_h<<<(n1 + 255) / 256, 256>>>(x, xhi, xlo, n1);
    conv_kernel_h<<<(n2 + 255) / 256, 256>>>(Wq, wqh, n2);
    conv_kernel_h<<<(n3 + 255) / 256, 256>>>(Wdown, wdh, n3);
    conv_kernel_h<<<(n4 + 255) / 256, 256>>>(Wkup, wkh, n4);
    conv_kernel_h<<<(n4 + 255) / 256, 256>>>(Wvup, wvh, n4);
    conv_kernel_h<<<(n2 + 255) / 256, 256>>>(Wproj, wph, n2);

    gemm_h_sp16<<<dim3(RANK / GBN, M_ROWS / GBM), 256, GSMEM_BYTES>>>(
        xhi, xlo, wdh, lhi, llo, M_ROWS, RANK, DIM);
    gemm_h<<<dim3(DIM / GBN, M_ROWS / GBM), 256, GSMEM_BYTES>>>(
        xhi, xlo, wqh, q, M_ROWS, DIM, DIM);
    gemm_h<<<dim3(RANK / GBN, M_ROWS / GBM), 256, GSMEM_BYTES>>>(
        lhi, llo, wkh, kt, M_ROWS, RANK, RANK);
    gemm_h<<<dim3(RANK / GBN, M_ROWS / GBM), 256, GSMEM_BYTES>>>(
        lhi, llo, wvh, vt, M_ROWS, RANK, RANK);

    rms_rope_kernel<<<dim3(M_ROWS, NHEADS), 128>>>(q, qah, qal, qgain, NHEADS);
    rms_rope_kernel<<<dim3(M_ROWS, NKVH), 128>>>(kt, kah, kal, (const float*)0, NKVH);
    split_kernel_bf<<<(n5 + 255) / 256, 256>>>(vt, vth, vtl, n5);

    flash_mma<<<dim3(T_SEQ / FBQ, NHEADS, BATCH), 256, FA3_SMEM>>>(qah, qal, kah, kal,
                                                                   vth, vtl, yhi, ylo);

    gemm_h<<<dim3(DIM / GBN, M_ROWS / GBM), 256, GSMEM_BYTES>>>(
        yhi, ylo, wph, out, M_ROWS, DIM, DIM);
}

// round 10
// speedup vs baseline: 3.1617x; 1.1083x over previous
#include <cuda_runtime.h>
#include <cuda_bf16.h>
#include <cuda_fp16.h>
#include <cuda_pipeline.h>
#include <mma.h>
#include <math.h>

// ---------------- Problem constants ----------------
#define T_SEQ  2048
#define BATCH  2
#define NHEADS 16
#define NKVH   4
#define HD     128
#define DIM    2048
#define RANK   512
#define M_ROWS (BATCH * T_SEQ)
#define EPS_F  1.1920928955078125e-07f
#define SCALE_F 0.08838834764831845f

#define NE_MD (M_ROWS * DIM)
#define NE_MR (M_ROWS * RANK)
#define NE_DD (DIM * DIM)
#define NE_RD (RANK * DIM)
#define NE_RR (RANK * RANK)

// ---------------- Scratch (static device globals; no allocation) ----------------
__device__ float g_q  [NE_MD];
__device__ float g_kt [NE_MR];
__device__ float g_vt [NE_MR];

// fp16 GEMM operands
__device__ __half g_xhi[NE_MD];
__device__ __half g_xlo[NE_MD];
__device__ __half g_lhi[NE_MR];
__device__ __half g_llo[NE_MR];
__device__ __half g_yhi[NE_MD];
__device__ __half g_ylo[NE_MD];
__device__ __half g_wqh[NE_DD];
__device__ __half g_wdh[NE_RD];
__device__ __half g_wkh[NE_RR];
__device__ __half g_wvh[NE_RR];
__device__ __half g_wph[NE_DD];

// flash operands: Q/K bf16 hi/lo, V fp16 hi/lo
__device__ __nv_bfloat16 g_qah[NE_MD];
__device__ __nv_bfloat16 g_qal[NE_MD];
__device__ __nv_bfloat16 g_kah[NE_MR];
__device__ __nv_bfloat16 g_kal[NE_MR];
__device__ __half g_vth[NE_MR];
__device__ __half g_vtl[NE_MR];

// ---------------- conversions ----------------
__global__ void split_kernel_h(const float* __restrict__ x,
                               __half* __restrict__ hi,
                               __half* __restrict__ lo, int n)
{
    int i = blockIdx.x * blockDim.x + threadIdx.x;
    if (i < n) {
        float v = x[i];
        __half h = __float2half(v);
        hi[i] = h;
        lo[i] = __float2half(v - __half2float(h));
    }
}

__global__ void conv_kernel_h(const float* __restrict__ x,
                              __half* __restrict__ hi, int n)
{
    int i = blockIdx.x * blockDim.x + threadIdx.x;
    if (i < n) {
        hi[i] = __float2half(x[i]);
    }
}

// ---------------- WMMA fp16x2 GEMM, cp.async 3-stage ----------------
#define GBM 128
#define GBN 128
#define GBK 32
#define GLDS 40
#define GTILE (GBM * GLDS)
#define GSTG (3 * GTILE)
#define GSMEM_BYTES (3 * GSTG * 2)          // 92160

__device__ __forceinline__ void gemm_stage_load_h(
    __half* s,
    const __half* Ah, const __half* Al, const __half* Bh,
    int bm, int bn, int K, int k0, int tid)
{
    __half* sAh = s;
    __half* sAl = s + GTILE;
    __half* sBh = s + 2 * GTILE;
    for (int i = 0; i < 2; i++) {
        int idx = tid + 256 * i;
        int row = idx >> 2;
        int c8  = (idx & 3) * 8;
        __pipeline_memcpy_async(sAh + row * GLDS + c8,
                                Ah + (size_t)(bm + row) * K + k0 + c8, 16);
        __pipeline_memcpy_async(sAl + row * GLDS + c8,
                                Al + (size_t)(bm + row) * K + k0 + c8, 16);
        __pipeline_memcpy_async(sBh + row * GLDS + c8,
                                Bh + (size_t)(bn + row) * K + k0 + c8, 16);
    }
}

__global__ __launch_bounds__(256) void gemm_h(
    const __half* __restrict__ Ah, const __half* __restrict__ Al,
    const __half* __restrict__ Bh,
    float* __restrict__ C, int M, int N, int K)
{
    extern __shared__ __half gsm[];

    const int tid  = threadIdx.x;
    const int warp = tid / 32;
    const int wm   = (warp % 2) * 64;
    const int wn   = (warp / 2) * 32;
    const int bm   = blockIdx.y * GBM;
    const int bn   = blockIdx.x * GBN;

    nvcuda::wmma::fragment<nvcuda::wmma::accumulator, 16, 16, 16, float> acc[4][2];
    for (int i = 0; i < 4; i++) {
        for (int j = 0; j < 2; j++) {
            nvcuda::wmma::fill_fragment(acc[i][j], 0.0f);
        }
    }

    const int nk = K / GBK;

    gemm_stage_load_h(gsm, Ah, Al, Bh, bm, bn, K, 0, tid);
    __pipeline_commit();
    gemm_stage_load_h(gsm + GSTG, Ah, Al, Bh, bm, bn, K, GBK, tid);
    __pipeline_commit();

    for (int it = 0; it < nk; it++) {
        if (it + 2 < nk) {
            int st = (it + 2) % 3;
            gemm_stage_load_h(gsm + st * GSTG, Ah, Al, Bh, bm, bn, K,
                              (it + 2) * GBK, tid);
            __pipeline_commit();
            __pipeline_wait_prior(2);
        } else if (it + 1 < nk) {
            __pipeline_wait_prior(1);
        } else {
            __pipeline_wait_prior(0);
        }
        __syncthreads();

        __half* sAh = gsm + (it % 3) * GSTG;
        __half* sAl = sAh + GTILE;
        __half* sBh = sAh + 2 * GTILE;

        for (int ks = 0; ks < GBK; ks += 16) {
            nvcuda::wmma::fragment<nvcuda::wmma::matrix_a, 16, 16, 16,
                                   __half, nvcuda::wmma::row_major> fah[4];
            nvcuda::wmma::fragment<nvcuda::wmma::matrix_a, 16, 16, 16,
                                   __half, nvcuda::wmma::row_major> fal[4];
            nvcuda::wmma::fragment<nvcuda::wmma::matrix_b, 16, 16, 16,
                                   __half, nvcuda::wmma::col_major> fbh[2];
            for (int i = 0; i < 4; i++) {
                nvcuda::wmma::load_matrix_sync(fah[i], sAh + (wm + i * 16) * GLDS + ks, GLDS);
                nvcuda::wmma::load_matrix_sync(fal[i], sAl + (wm + i * 16) * GLDS + ks, GLDS);
            }
            for (int j = 0; j < 2; j++) {
                nvcuda::wmma::load_matrix_sync(fbh[j], sBh + (wn + j * 16) * GLDS + ks, GLDS);
            }
            for (int i = 0; i < 4; i++) {
                for (int j = 0; j < 2; j++) {
                    nvcuda::wmma::mma_sync(acc[i][j], fah[i], fbh[j], acc[i][j]);
                    nvcuda::wmma::mma_sync(acc[i][j], fal[i], fbh[j], acc[i][j]);
                }
            }
        }
        __syncthreads();
    }

    for (int i = 0; i < 4; i++) {
        for (int j = 0; j < 2; j++) {
            float* cp = C + (size_t)(bm + wm + i * 16) * N + bn + wn + j * 16;
            nvcuda::wmma::store_matrix_sync(cp, acc[i][j], N, nvcuda::wmma::mem_row_major);
        }
    }
}

// same GEMM but epilogue writes fp16 hi/lo (for the latent path)
__global__ __launch_bounds__(256) void gemm_h_sp16(
    const __half* __restrict__ Ah, const __half* __restrict__ Al,
    const __half* __restrict__ Bh,
    __half* __restrict__ Chi, __half* __restrict__ Clo, int M, int N, int K)
{
    extern __shared__ __half gsm[];

    const int tid  = threadIdx.x;
    const int warp = tid / 32;
    const int wm   = (warp % 2) * 64;
    const int wn   = (warp / 2) * 32;
    const int bm   = blockIdx.y * GBM;
    const int bn   = blockIdx.x * GBN;

    nvcuda::wmma::fragment<nvcuda::wmma::accumulator, 16, 16, 16, float> acc[4][2];
    for (int i = 0; i < 4; i++) {
        for (int j = 0; j < 2; j++) {
            nvcuda::wmma::fill_fragment(acc[i][j], 0.0f);
        }
    }

    const int nk = K / GBK;

    gemm_stage_load_h(gsm, Ah, Al, Bh, bm, bn, K, 0, tid);
    __pipeline_commit();
    gemm_stage_load_h(gsm + GSTG, Ah, Al, Bh, bm, bn, K, GBK, tid);
    __pipeline_commit();

    for (int it = 0; it < nk; it++) {
        if (it + 2 < nk) {
            int st = (it + 2) % 3;
            gemm_stage_load_h(gsm + st * GSTG, Ah, Al, Bh, bm, bn, K,
                              (it + 2) * GBK, tid);
            __pipeline_commit();
            __pipeline_wait_prior(2);
        } else if (it + 1 < nk) {
            __pipeline_wait_prior(1);
        } else {
            __pipeline_wait_prior(0);
        }
        __syncthreads();

        __half* sAh = gsm + (it % 3) * GSTG;
        __half* sAl = sAh + GTILE;
        __half* sBh = sAh + 2 * GTILE;

        for (int ks = 0; ks < GBK; ks += 16) {
            nvcuda::wmma::fragment<nvcuda::wmma::matrix_a, 16, 16, 16,
                                   __half, nvcuda::wmma::row_major> fah[4];
            nvcuda::wmma::fragment<nvcuda::wmma::matrix_a, 16, 16, 16,
                                   __half, nvcuda::wmma::row_major> fal[4];
            nvcuda::wmma::fragment<nvcuda::wmma::matrix_b, 16, 16, 16,
                                   __half, nvcuda::wmma::col_major> fbh[2];
            for (int i = 0; i < 4; i++) {
                nvcuda::wmma::load_matrix_sync(fah[i], sAh + (wm + i * 16) * GLDS + ks, GLDS);
                nvcuda::wmma::load_matrix_sync(fal[i], sAl + (wm + i * 16) * GLDS + ks, GLDS);
            }
            for (int j = 0; j < 2; j++) {
                nvcuda::wmma::load_matrix_sync(fbh[j], sBh + (wn + j * 16) * GLDS + ks, GLDS);
            }
            for (int i = 0; i < 4; i++) {
                for (int j = 0; j < 2; j++) {
                    nvcuda::wmma::mma_sync(acc[i][j], fah[i], fbh[j], acc[i][j]);
                    nvcuda::wmma::mma_sync(acc[i][j], fal[i], fbh[j], acc[i][j]);
                }
            }
        }
        __syncthreads();
    }

    float* stage = (float*)gsm;
    for (int i = 0; i < 4; i++) {
        for (int j = 0; j < 2; j++) {
            nvcuda::wmma::store_matrix_sync(stage + (wm + i * 16) * 128 + wn + j * 16,
                                            acc[i][j], 128, nvcuda::wmma::mem_row_major);
        }
    }
    __syncthreads();
    for (int t = tid; t < GBM * GBN; t += 256) {
        int r = t >> 7;
        int c = t & 127;
        float v = stage[t];
        __half hv = __float2half(v);
        size_t gi = (size_t)(bm + r) * N + bn + c;
        Chi[gi] = hv;
        Clo[gi] = __float2half(v - __half2float(hv));
    }
}

// ---------------- RMSNorm + RoPE (+gain), output bf16 hi/lo ----------------
__global__ void rms_rope_kernel(const float* __restrict__ src,
                                __nv_bfloat16* __restrict__ dsth,
                                __nv_bfloat16* __restrict__ dstl,
                                const float* __restrict__ gain, int nheads)
{
    const int m = blockIdx.x;
    const int h = blockIdx.y;
    const int d = threadIdx.x;
    const int b = m / T_SEQ;
    const int t = m % T_SEQ;

    float x = src[(size_t)m * ((size_t)nheads * HD) + h * HD + d];
    float ss = x * x;
#pragma unroll
    for (int o = 16; o > 0; o >>= 1) ss += __shfl_xor_sync(0xffffffffu, ss, o);
    __shared__ float red[4];
    __shared__ float sv[HD];
    if ((d & 31) == 0) red[d >> 5] = ss;
    __syncthreads();
    float tot = red[0] + red[1] + red[2] + red[3];
    float r = rsqrtf(tot * (1.0f / HD) + EPS_F);
    sv[d] = x * r;
    __syncthreads();
    if (d < 64) {
        float x1 = sv[d];
        float x2 = sv[d + 64];
        float fr = powf(10000.0f, -(float)d * (1.0f / 64.0f));
        float ang = (float)t * fr;
        float sn, cs;
        sincosf(ang, &sn, &cs);
        float g = (gain != 0) ? gain[h] : 1.0f;
        float v1 = (x1 * cs + x2 * sn) * g;
        float v2 = (x2 * cs - x1 * sn) * g;
        size_t base = ((size_t)(b * nheads + h) * T_SEQ + t) * HD;
        __nv_bfloat16 h1 = __float2bfloat16(v1);
        __nv_bfloat16 h2 = __float2bfloat16(v2);
        dsth[base + d]      = h1;
        dsth[base + 64 + d] = h2;
        dstl[base + d]      = __float2bfloat16(v1 - __bfloat162float(h1));
        dstl[base + 64 + d] = __float2bfloat16(v2 - __bfloat162float(h2));
    }
}

// ---------------- Flash attention ----------------
// S = QK^T: bf16x3 (unchanged). P·V: fp16 2-pass (P single fp16, V fp16 hi/lo).
#define FBQ 64
#define FBK 64
#define QLD 136
#define PLD 72
#define SLD 68

#define OQH 0
#define OQL (OQH + FBQ * QLD * 2)
#define OKV (OQL + FBQ * QLD * 2)
#define KVTILE (FBK * QLD * 2)
#define KVSTG (4 * KVTILE)
#define OPH (OKV + 2 * KVSTG)
#define OSF (OPH + FBQ * PLD * 2)
#define OMR (OSF + FBQ * 128 * 4)
#define OLR (OMR + 256)
#define OAR (OLR + 256)
#define FA3_SMEM (OAR + 256)

__device__ __forceinline__ void fa_stage_load(
    char* smb, int s,
    const __nv_bfloat16* ksh, const __nv_bfloat16* ksl,
    const __half* vsh, const __half* vsl, int tid)
{
    char* st = smb + OKV + s * KVSTG;
    __nv_bfloat16* sKh = (__nv_bfloat16*)st;
    __nv_bfloat16* sKl = (__nv_bfloat16*)(st + KVTILE);
    __half* sVh = (__half*)(st + 2 * KVTILE);
    __half* sVl = (__half*)(st + 3 * KVTILE);
    for (int i = 0; i < 4; i++) {
        int idx = tid + 256 * i;
        int r = idx >> 4;
        int c = (idx & 15) * 8;
        __pipeline_memcpy_async(sKh + r * QLD + c, ksh + (size_t)r * HD + c, 16);
        __pipeline_memcpy_async(sKl + r * QLD + c, ksl + (size_t)r * HD + c, 16);
        __pipeline_memcpy_async(sVh + r * QLD + c, vsh + (size_t)r * RANK + c, 16);
        __pipeline_memcpy_async(sVl + r * QLD + c, vsl + (size_t)r * RANK + c, 16);
    }
}

__global__ __launch_bounds__(256) void flash_mma(
    const __nv_bfloat16* __restrict__ Qhi, const __nv_bfloat16* __restrict__ Qlo,
    const __nv_bfloat16* __restrict__ Khi, const __nv_bfloat16* __restrict__ Klo,
    const __half* __restrict__ Vhi, const __half* __restrict__ Vlo,
    __half* __restrict__ Yh, __half* __restrict__ Yl)
{
    extern __shared__ char smb[];
    __nv_bfloat16* sQh = (__nv_bfloat16*)(smb + OQH);
    __nv_bfloat16* sQl = (__nv_bfloat16*)(smb + OQL);
    __half* sPh = (__half*)(smb + OPH);
    float* sSf  = (float*)(smb + OSF);
    float* sOd  = (float*)(smb + OSF);
    float* mrow = (float*)(smb + OMR);
    float* lrow = (float*)(smb + OLR);
    float* arow = (float*)(smb + OAR);

    const int tid  = threadIdx.x;
    const int warp = tid / 32;
    const int qt = (int)(gridDim.x - 1 - blockIdx.x);   // longest CTAs first
    const int h  = blockIdx.y;
    const int b  = blockIdx.z;
    const int kh = h >> 2;
    const int q0 = qt * FBQ;

    const __nv_bfloat16* Kh0 = Khi + ((size_t)(b * NKVH + kh) * T_SEQ) * HD;
    const __nv_bfloat16* Kl0 = Klo + ((size_t)(b * NKVH + kh) * T_SEQ) * HD;
    const __half* Vh0 = Vhi + (size_t)b * T_SEQ * RANK + kh * HD;
    const __half* Vl0 = Vlo + (size_t)b * T_SEQ * RANK + kh * HD;

    const __nv_bfloat16* qsh = Qhi + ((size_t)(b * NHEADS + h) * T_SEQ + q0) * HD;
    const __nv_bfloat16* qsl = Qlo + ((size_t)(b * NHEADS + h) * T_SEQ + q0) * HD;
    for (int i = tid; i < FBQ * HD / 8; i += 256) {
        int r = i >> 4;
        int c = (i & 15) * 8;
        *(uint4*)(sQh + r * QLD + c) = *(const uint4*)(qsh + (size_t)r * HD + c);
        *(uint4*)(sQl + r * QLD + c) = *(const uint4*)(qsl + (size_t)r * HD + c);
    }
    if (tid < 64) {
        mrow[tid] = -1e30f;
        lrow[tid] = 0.f;
    }

    float o[32];
#pragma unroll
    for (int j = 0; j < 32; j++) o[j] = 0.f;

    const int ro = tid >> 2;
    const int cq = tid & 3;

    fa_stage_load(smb, 0, Kh0, Kl0, Vh0, Vl0, tid);
    __pipeline_commit();
    __syncthreads();

    for (int kt = 0; kt <= qt; kt++) {
        const int k0 = kt * FBK;
        if (kt < qt) {
            int k1 = (kt + 1) * FBK;
            fa_stage_load(smb, (kt + 1) & 1,
                          Kh0 + (size_t)k1 * HD, Kl0 + (size_t)k1 * HD,
                          Vh0 + (size_t)k1 * RANK, Vl0 + (size_t)k1 * RANK, tid);
            __pipeline_commit();
            __pipeline_wait_prior(1);
        } else {
            __pipeline_wait_prior(0);
        }
        __syncthreads();

        char* stg = smb + OKV + (size_t)(kt & 1) * KVSTG;
        __nv_bfloat16* sKh = (__nv_bfloat16*)stg;
        __nv_bfloat16* sKl = (__nv_bfloat16*)(stg + KVTILE);
        __half* sVh = (__half*)(stg + 2 * KVTILE);
        __half* sVl = (__half*)(stg + 3 * KVTILE);

        // ---- S = Q K^T (bf16x3) ----
        {
            const int wm  = warp % 4;
            const int wc0 = (warp / 4) * 2;
            nvcuda::wmma::fragment<nvcuda::wmma::accumulator, 16, 16, 16, float> accs[2];
            for (int j = 0; j < 2; j++) nvcuda::wmma::fill_fragment(accs[j], 0.0f);
            for (int ks = 0; ks < HD; ks += 16) {
                nvcuda::wmma::fragment<nvcuda::wmma::matrix_a, 16, 16, 16,
                                       __nv_bfloat16, nvcuda::wmma::row_major> fah;
                nvcuda::wmma::fragment<nvcuda::wmma::matrix_a, 16, 16, 16,
                                       __nv_bfloat16, nvcuda::wmma::row_major> fal;
                nvcuda::wmma::load_matrix_sync(fah, sQh + (wm * 16) * QLD + ks, QLD);
                nvcuda::wmma::load_matrix_sync(fal, sQl + (wm * 16) * QLD + ks, QLD);
                for (int j = 0; j < 2; j++) {
                    nvcuda::wmma::fragment<nvcuda::wmma::matrix_b, 16, 16, 16,
                                           __nv_bfloat16, nvcuda::wmma::col_major> fbh;
                    nvcuda::wmma::fragment<nvcuda::wmma::matrix_b, 16, 16, 16,
                                           __nv_bfloat16, nvcuda::wmma::col_major> fbl;
                    nvcuda::wmma::load_matrix_sync(fbh, sKh + ((wc0 + j) * 16) * QLD + ks, QLD);
                    nvcuda::wmma::load_matrix_sync(fbl, sKl + ((wc0 + j) * 16) * QLD + ks, QLD);
                    nvcuda::wmma::mma_sync(accs[j], fah, fbh, accs[j]);
                    nvcuda::wmma::mma_sync(accs[j], fah, fbl, accs[j]);
                    nvcuda::wmma::mma_sync(accs[j], fal, fbh, accs[j]);
                }
            }
            for (int j = 0; j < 2; j++) {
                nvcuda::wmma::store_matrix_sync(sSf + (wm * 16) * SLD + (wc0 + j) * 16,
                                                accs[j], SLD, nvcuda::wmma::mem_row_major);
            }
        }
        __syncthreads();

        // ---- online softmax (4 threads per row) ----
        {
            const int r  = tid >> 2;
            const int qq = tid & 3;
            const int qg = q0 + r;
            float mold = mrow[r];
            float vals[16];
            float rmax = mold;
#pragma unroll
            for (int j = 0; j < 16; j++) {
                int c = qq + 4 * j;
                float v = sSf[r * SLD + c] * SCALE_F;
                if (k0 + c > qg) v = -1e30f;
                vals[j] = v;
                rmax = fmaxf(rmax, v);
            }
            rmax = fmaxf(rmax, __shfl_xor_sync(0xffffffffu, rmax, 1));
            rmax = fmaxf(rmax, __shfl_xor_sync(0xffffffffu, rmax, 2));
            float alpha = __expf(mold - rmax);
            float rsum = 0.f;
#pragma unroll
            for (int j = 0; j < 16; j++) {
                int c = qq + 4 * j;
                float p = __expf(vals[j] - rmax);
                sPh[r * PLD + c] = __float2half(p);
                rsum += p;
            }
            rsum += __shfl_xor_sync(0xffffffffu, rsum, 1);
            rsum += __shfl_xor_sync(0xffffffffu, rsum, 2);
            if (qq == 0) {
                lrow[r] = lrow[r] * alpha + rsum;
                mrow[r] = rmax;
                arow[r] = alpha;
            }
        }
        __syncthreads();

        // ---- O_delta = P V (fp16, 2-pass: p*vh + p*vl) ----
        {
            const int wm  = warp % 4;
            const int wn0 = (warp / 4) * 4;
            nvcuda::wmma::fragment<nvcuda::wmma::accumulator, 16, 16, 16, float> accd[4];
            for (int j = 0; j < 4; j++) nvcuda::wmma::fill_fragment(accd[j], 0.0f);
            for (int kc = 0; kc < FBK; kc += 16) {
                nvcuda::wmma::fragment<nvcuda::wmma::matrix_a, 16, 16, 16,
                                       __half, nvcuda::wmma::row_major> pah;
                nvcuda::wmma::load_matrix_sync(pah, sPh + (wm * 16) * PLD + kc, PLD);
                for (int j = 0; j < 4; j++) {
                    nvcuda::wmma::fragment<nvcuda::wmma::matrix_b, 16, 16, 16,
                                           __half, nvcuda::wmma::row_major> vbh;
                    nvcuda::wmma::fragment<nvcuda::wmma::matrix_b, 16, 16, 16,
                                           __half, nvcuda::wmma::row_major> vbl;
                    nvcuda::wmma::load_matrix_sync(vbh, sVh + kc * QLD + (wn0 + j) * 16, QLD);
                    nvcuda::wmma::load_matrix_sync(vbl, sVl + kc * QLD + (wn0 + j) * 16, QLD);
                    nvcuda::wmma::mma_sync(accd[j], pah, vbh, accd[j]);
                    nvcuda::wmma::mma_sync(accd[j], pah, vbl, accd[j]);
                }
            }
            for (int j = 0; j < 4; j++) {
                nvcuda::wmma::store_matrix_sync(sOd + (wm * 16) * 128 + (wn0 + j) * 16,
                                                accd[j], 128, nvcuda::wmma::mem_row_major);
            }
        }
        __syncthreads();

        // ---- o = o * alpha + O_delta ----
        {
            float alpha = arow[ro];
            const float* od = sOd + ro * 128 + cq * 32;
#pragma unroll
            for (int j = 0; j < 32; j++) o[j] = o[j] * alpha + od[j];
        }
        __syncthreads();
    }

    float inv = 1.0f / lrow[ro];
    size_t yb = ((size_t)(b * T_SEQ) + q0 + ro) * DIM + h * HD + cq * 32;
#pragma unroll
    for (int j = 0; j < 32; j++) {
        float v = o[j] * inv;
        __half hv = __float2half(v);
        Yh[yb + j] = hv;
        Yl[yb + j] = __float2half(v - __half2float(hv));
    }
}

// ---------------- Launch ----------------
extern "C" void kernel_launch(void* const* d_in, const int* in_sizes, int n_in,
                              void* d_out, int out_size)
{
    (void)in_sizes;
    (void)n_in;
    (void)out_size;
    const float* x     = (const float*)d_in[0];
    const float* Wq    = (const float*)d_in[1];
    const float* Wdown = (const float*)d_in[2];
    const float* Wkup  = (const float*)d_in[3];
    const float* Wvup  = (const float*)d_in[4];
    const float* Wproj = (const float*)d_in[5];
    const float* qgain = (const float*)d_in[6];
    float* out = (float*)d_out;

    float* q;
    float* kt;
    float* vt;
    cudaGetSymbolAddress((void**)&q,  g_q);
    cudaGetSymbolAddress((void**)&kt, g_kt);
    cudaGetSymbolAddress((void**)&vt, g_vt);

    __half* xhi;
    __half* xlo;
    __half* lhi;
    __half* llo;
    __half* yhi;
    __half* ylo;
    __half* wqh;
    __half* wdh;
    __half* wkh;
    __half* wvh;
    __half* wph;
    cudaGetSymbolAddress((void**)&xhi, g_xhi);
    cudaGetSymbolAddress((void**)&xlo, g_xlo);
    cudaGetSymbolAddress((void**)&lhi, g_lhi);
    cudaGetSymbolAddress((void**)&llo, g_llo);
    cudaGetSymbolAddress((void**)&yhi, g_yhi);
    cudaGetSymbolAddress((void**)&ylo, g_ylo);
    cudaGetSymbolAddress((void**)&wqh, g_wqh);
    cudaGetSymbolAddress((void**)&wdh, g_wdh);
    cudaGetSymbolAddress((void**)&wkh, g_wkh);
    cudaGetSymbolAddress((void**)&wvh, g_wvh);
    cudaGetSymbolAddress((void**)&wph, g_wph);

    __nv_bfloat16* qah;
    __nv_bfloat16* qal;
    __nv_bfloat16* kah;
    __nv_bfloat16* kal;
    __half* vth;
    __half* vtl;
    cudaGetSymbolAddress((void**)&qah, g_qah);
    cudaGetSymbolAddress((void**)&qal, g_qal);
    cudaGetSymbolAddress((void**)&kah, g_kah);
    cudaGetSymbolAddress((void**)&kal, g_kal);
    cudaGetSymbolAddress((void**)&vth, g_vth);
    cudaGetSymbolAddress((void**)&vtl, g_vtl);

    cudaFuncSetAttribute(gemm_h, cudaFuncAttributeMaxDynamicSharedMemorySize,
                         GSMEM_BYTES);
    cudaFuncSetAttribute(gemm_h_sp16, cudaFuncAttributeMaxDynamicSharedMemorySize,
                         GSMEM_BYTES);
    cudaFuncSetAttribute(flash_mma, cudaFuncAttributeMaxDynamicSharedMemorySize,
                         FA3_SMEM);

    int n1 = NE_MD;
    int n2 = NE_DD;
    int n3 = NE_RD;
    int n4 = NE_RR;
    int n5 = NE_MR;
    split_kernel_h<<<(n1 + 255) / 256, 256>>>(x, xhi, xlo, n1);
    conv_kernel_h<<<(n2 + 255) / 256, 256>>>(Wq, wqh, n2);
    conv_kernel_h<<<(n3 + 255) / 256, 256>>>(Wdown, wdh, n3);
    conv_kernel_h<<<(n4 + 255) / 256, 256>>>(Wkup, wkh, n4);
    conv_kernel_h<<<(n4 + 255) / 256, 256>>>(Wvup, wvh, n4);
    conv_kernel_h<<<(n2 + 255) / 256, 256>>>(Wproj, wph, n2);

    gemm_h_sp16<<<dim3(RANK / GBN, M_ROWS / GBM), 256, GSMEM_BYTES>>>(
        xhi, xlo, wdh, lhi, llo, M_ROWS, RANK, DIM);
    gemm_h<<<dim3(DIM / GBN, M_ROWS / GBM), 256, GSMEM_BYTES>>>(
        xhi, xlo, wqh, q, M_ROWS, DIM, DIM);
    gemm_h<<<dim3(RANK / GBN, M_ROWS / GBM), 256, GSMEM_BYTES>>>(
        lhi, llo, wkh, kt, M_ROWS, RANK, RANK);
    gemm_h<<<dim3(RANK / GBN, M_ROWS / GBM), 256, GSMEM_BYTES>>>(
        lhi, llo, wvh, vt, M_ROWS, RANK, RANK);

    rms_rope_kernel<<<dim3(M_ROWS, NHEADS), 128>>>(q, qah, qal, qgain, NHEADS);
    rms_rope_kernel<<<dim3(M_ROWS, NKVH), 128>>>(kt, kah, kal, (const float*)0, NKVH);
    split_kernel_h<<<(n5 + 255) / 256, 256>>>(vt, vth, vtl, n5);

    flash_mma<<<dim3(T_SEQ / FBQ, NHEADS, BATCH), 256, FA3_SMEM>>>(qah, qal, kah, kal,
                                                                   vth, vtl, yhi, ylo);

    gemm_h<<<dim3(DIM / GBN, M_ROWS / GBM), 256, GSMEM_BYTES>>>(
        yhi, ylo, wph, out, M_ROWS, DIM, DIM);
}

// round 11
// speedup vs baseline: 3.4427x; 1.0889x over previous
#include <cuda_runtime.h>
#include <cuda_bf16.h>
#include <cuda_fp16.h>
#include <cuda_pipeline.h>
#include <mma.h>
#include <math.h>

// ---------------- Problem constants ----------------
#define T_SEQ  2048
#define BATCH  2
#define NHEADS 16
#define NKVH   4
#define HD     128
#define DIM    2048
#define RANK   512
#define M_ROWS (BATCH * T_SEQ)
#define EPS_F  1.1920928955078125e-07f
#define SCALE_F 0.08838834764831845f

#define NE_MD (M_ROWS * DIM)
#define NE_MR (M_ROWS * RANK)
#define NE_DD (DIM * DIM)
#define NE_RD (RANK * DIM)
#define NE_RR (RANK * RANK)

// ---------------- Scratch (static device globals; no allocation) ----------------
__device__ float g_q  [NE_MD];
__device__ float g_kt [NE_MR];
__device__ float g_vt [NE_MR];

// fp16 GEMM operands
__device__ __half g_xhi[NE_MD];
__device__ __half g_xlo[NE_MD];
__device__ __half g_lhi[NE_MR];
__device__ __half g_llo[NE_MR];
__device__ __half g_yhi[NE_MD];
__device__ __half g_ylo[NE_MD];
__device__ __half g_wqh[NE_DD];
__device__ __half g_wdh[NE_RD];
__device__ __half g_wkh[NE_RR];
__device__ __half g_wvh[NE_RR];
__device__ __half g_wph[NE_DD];

// flash operands: Q fp16 hi/lo, K fp16, V fp16 hi/lo
__device__ __half g_qah[NE_MD];
__device__ __half g_qal[NE_MD];
__device__ __half g_kah[NE_MR];
__device__ __half g_vth[NE_MR];
__device__ __half g_vtl[NE_MR];

// ---------------- conversions ----------------
__global__ void split_kernel_h(const float* __restrict__ x,
                               __half* __restrict__ hi,
                               __half* __restrict__ lo, int n)
{
    int i = blockIdx.x * blockDim.x + threadIdx.x;
    if (i < n) {
        float v = x[i];
        __half h = __float2half(v);
        hi[i] = h;
        lo[i] = __float2half(v - __half2float(h));
    }
}

__global__ void conv_kernel_h(const float* __restrict__ x,
                              __half* __restrict__ hi, int n)
{
    int i = blockIdx.x * blockDim.x + threadIdx.x;
    if (i < n) {
        hi[i] = __float2half(x[i]);
    }
}

// ---------------- WMMA fp16x2 GEMM, cp.async 3-stage ----------------
#define GBM 128
#define GBN 128
#define GBK 32
#define GLDS 40
#define GTILE (GBM * GLDS)
#define GSTG (3 * GTILE)
#define GSMEM_BYTES (3 * GSTG * 2)          // 92160

__device__ __forceinline__ void gemm_stage_load_h(
    __half* s,
    const __half* Ah, const __half* Al, const __half* Bh,
    int bm, int bn, int K, int k0, int tid)
{
    __half* sAh = s;
    __half* sAl = s + GTILE;
    __half* sBh = s + 2 * GTILE;
    for (int i = 0; i < 2; i++) {
        int idx = tid + 256 * i;
        int row = idx >> 2;
        int c8  = (idx & 3) * 8;
        __pipeline_memcpy_async(sAh + row * GLDS + c8,
                                Ah + (size_t)(bm + row) * K + k0 + c8, 16);
        __pipeline_memcpy_async(sAl + row * GLDS + c8,
                                Al + (size_t)(bm + row) * K + k0 + c8, 16);
        __pipeline_memcpy_async(sBh + row * GLDS + c8,
                                Bh + (size_t)(bn + row) * K + k0 + c8, 16);
    }
}

__global__ __launch_bounds__(256) void gemm_h(
    const __half* __restrict__ Ah, const __half* __restrict__ Al,
    const __half* __restrict__ Bh,
    float* __restrict__ C, int M, int N, int K)
{
    extern __shared__ __half gsm[];

    const int tid  = threadIdx.x;
    const int warp = tid / 32;
    const int wm   = (warp % 2) * 64;
    const int wn   = (warp / 2) * 32;
    const int bm   = blockIdx.y * GBM;
    const int bn   = blockIdx.x * GBN;

    nvcuda::wmma::fragment<nvcuda::wmma::accumulator, 16, 16, 16, float> acc[4][2];
    for (int i = 0; i < 4; i++) {
        for (int j = 0; j < 2; j++) {
            nvcuda::wmma::fill_fragment(acc[i][j], 0.0f);
        }
    }

    const int nk = K / GBK;

    gemm_stage_load_h(gsm, Ah, Al, Bh, bm, bn, K, 0, tid);
    __pipeline_commit();
    gemm_stage_load_h(gsm + GSTG, Ah, Al, Bh, bm, bn, K, GBK, tid);
    __pipeline_commit();

    for (int it = 0; it < nk; it++) {
        if (it + 2 < nk) {
            int st = (it + 2) % 3;
            gemm_stage_load_h(gsm + st * GSTG, Ah, Al, Bh, bm, bn, K,
                              (it + 2) * GBK, tid);
            __pipeline_commit();
            __pipeline_wait_prior(2);
        } else if (it + 1 < nk) {
            __pipeline_wait_prior(1);
        } else {
            __pipeline_wait_prior(0);
        }
        __syncthreads();

        __half* sAh = gsm + (it % 3) * GSTG;
        __half* sAl = sAh + GTILE;
        __half* sBh = sAh + 2 * GTILE;

        for (int ks = 0; ks < GBK; ks += 16) {
            nvcuda::wmma::fragment<nvcuda::wmma::matrix_a, 16, 16, 16,
                                   __half, nvcuda::wmma::row_major> fah[4];
            nvcuda::wmma::fragment<nvcuda::wmma::matrix_a, 16, 16, 16,
                                   __half, nvcuda::wmma::row_major> fal[4];
            nvcuda::wmma::fragment<nvcuda::wmma::matrix_b, 16, 16, 16,
                                   __half, nvcuda::wmma::col_major> fbh[2];
            for (int i = 0; i < 4; i++) {
                nvcuda::wmma::load_matrix_sync(fah[i], sAh + (wm + i * 16) * GLDS + ks, GLDS);
                nvcuda::wmma::load_matrix_sync(fal[i], sAl + (wm + i * 16) * GLDS + ks, GLDS);
            }
            for (int j = 0; j < 2; j++) {
                nvcuda::wmma::load_matrix_sync(fbh[j], sBh + (wn + j * 16) * GLDS + ks, GLDS);
            }
            for (int i = 0; i < 4; i++) {
                for (int j = 0; j < 2; j++) {
                    nvcuda::wmma::mma_sync(acc[i][j], fah[i], fbh[j], acc[i][j]);
                    nvcuda::wmma::mma_sync(acc[i][j], fal[i], fbh[j], acc[i][j]);
                }
            }
        }
        __syncthreads();
    }

    for (int i = 0; i < 4; i++) {
        for (int j = 0; j < 2; j++) {
            float* cp = C + (size_t)(bm + wm + i * 16) * N + bn + wn + j * 16;
            nvcuda::wmma::store_matrix_sync(cp, acc[i][j], N, nvcuda::wmma::mem_row_major);
        }
    }
}

// same GEMM but epilogue writes fp16 hi/lo (for the latent path)
__global__ __launch_bounds__(256) void gemm_h_sp16(
    const __half* __restrict__ Ah, const __half* __restrict__ Al,
    const __half* __restrict__ Bh,
    __half* __restrict__ Chi, __half* __restrict__ Clo, int M, int N, int K)
{
    extern __shared__ __half gsm[];

    const int tid  = threadIdx.x;
    const int warp = tid / 32;
    const int wm   = (warp % 2) * 64;
    const int wn   = (warp / 2) * 32;
    const int bm   = blockIdx.y * GBM;
    const int bn   = blockIdx.x * GBN;

    nvcuda::wmma::fragment<nvcuda::wmma::accumulator, 16, 16, 16, float> acc[4][2];
    for (int i = 0; i < 4; i++) {
        for (int j = 0; j < 2; j++) {
            nvcuda::wmma::fill_fragment(acc[i][j], 0.0f);
        }
    }

    const int nk = K / GBK;

    gemm_stage_load_h(gsm, Ah, Al, Bh, bm, bn, K, 0, tid);
    __pipeline_commit();
    gemm_stage_load_h(gsm + GSTG, Ah, Al, Bh, bm, bn, K, GBK, tid);
    __pipeline_commit();

    for (int it = 0; it < nk; it++) {
        if (it + 2 < nk) {
            int st = (it + 2) % 3;
            gemm_stage_load_h(gsm + st * GSTG, Ah, Al, Bh, bm, bn, K,
                              (it + 2) * GBK, tid);
            __pipeline_commit();
            __pipeline_wait_prior(2);
        } else if (it + 1 < nk) {
            __pipeline_wait_prior(1);
        } else {
            __pipeline_wait_prior(0);
        }
        __syncthreads();

        __half* sAh = gsm + (it % 3) * GSTG;
        __half* sAl = sAh + GTILE;
        __half* sBh = sAh + 2 * GTILE;

        for (int ks = 0; ks < GBK; ks += 16) {
            nvcuda::wmma::fragment<nvcuda::wmma::matrix_a, 16, 16, 16,
                                   __half, nvcuda::wmma::row_major> fah[4];
            nvcuda::wmma::fragment<nvcuda::wmma::matrix_a, 16, 16, 16,
                                   __half, nvcuda::wmma::row_major> fal[4];
            nvcuda::wmma::fragment<nvcuda::wmma::matrix_b, 16, 16, 16,
                                   __half, nvcuda::wmma::col_major> fbh[2];
            for (int i = 0; i < 4; i++) {
                nvcuda::wmma::load_matrix_sync(fah[i], sAh + (wm + i * 16) * GLDS + ks, GLDS);
                nvcuda::wmma::load_matrix_sync(fal[i], sAl + (wm + i * 16) * GLDS + ks, GLDS);
            }
            for (int j = 0; j < 2; j++) {
                nvcuda::wmma::load_matrix_sync(fbh[j], sBh + (wn + j * 16) * GLDS + ks, GLDS);
            }
            for (int i = 0; i < 4; i++) {
                for (int j = 0; j < 2; j++) {
                    nvcuda::wmma::mma_sync(acc[i][j], fah[i], fbh[j], acc[i][j]);
                    nvcuda::wmma::mma_sync(acc[i][j], fal[i], fbh[j], acc[i][j]);
                }
            }
        }
        __syncthreads();
    }

    float* stage = (float*)gsm;
    for (int i = 0; i < 4; i++) {
        for (int j = 0; j < 2; j++) {
            nvcuda::wmma::store_matrix_sync(stage + (wm + i * 16) * 128 + wn + j * 16,
                                            acc[i][j], 128, nvcuda::wmma::mem_row_major);
        }
    }
    __syncthreads();
    for (int t = tid; t < GBM * GBN; t += 256) {
        int r = t >> 7;
        int c = t & 127;
        float v = stage[t];
        __half hv = __float2half(v);
        size_t gi = (size_t)(bm + r) * N + bn + c;
        Chi[gi] = hv;
        Clo[gi] = __float2half(v - __half2float(hv));
    }
}

// ---------------- RMSNorm + RoPE (+gain), output fp16 hi (+ optional lo) ----------------
__global__ void rms_rope_kernel(const float* __restrict__ src,
                                __half* __restrict__ dsth,
                                __half* __restrict__ dstl,
                                const float* __restrict__ gain, int nheads)
{
    const int m = blockIdx.x;
    const int h = blockIdx.y;
    const int d = threadIdx.x;
    const int b = m / T_SEQ;
    const int t = m % T_SEQ;

    float x = src[(size_t)m * ((size_t)nheads * HD) + h * HD + d];
    float ss = x * x;
#pragma unroll
    for (int o = 16; o > 0; o >>= 1) ss += __shfl_xor_sync(0xffffffffu, ss, o);
    __shared__ float red[4];
    __shared__ float sv[HD];
    if ((d & 31) == 0) red[d >> 5] = ss;
    __syncthreads();
    float tot = red[0] + red[1] + red[2] + red[3];
    float r = rsqrtf(tot * (1.0f / HD) + EPS_F);
    sv[d] = x * r;
    __syncthreads();
    if (d < 64) {
        float x1 = sv[d];
        float x2 = sv[d + 64];
        float fr = powf(10000.0f, -(float)d * (1.0f / 64.0f));
        float ang = (float)t * fr;
        float sn, cs;
        sincosf(ang, &sn, &cs);
        float g = (gain != 0) ? gain[h] : 1.0f;
        float v1 = (x1 * cs + x2 * sn) * g;
        float v2 = (x2 * cs - x1 * sn) * g;
        size_t base = ((size_t)(b * nheads + h) * T_SEQ + t) * HD;
        __half h1 = __float2half(v1);
        __half h2 = __float2half(v2);
        dsth[base + d]      = h1;
        dsth[base + 64 + d] = h2;
        if (dstl != 0) {
            dstl[base + d]      = __float2half(v1 - __half2float(h1));
            dstl[base + 64 + d] = __float2half(v2 - __half2float(h2));
        }
    }
}

// ---------------- Flash attention (all fp16 2-pass, fp32 softmax) ----------------
// S = QK^T: Q fp16 hi/lo x K fp16 (2 passes). P·V: P fp16 x V fp16 hi/lo (2 passes).
#define FBQ 64
#define FBK 64
#define QLD 136
#define PLD 72
#define SLD 68

#define OQH 0
#define OQL (OQH + FBQ * QLD * 2)
#define OKV (OQL + FBQ * QLD * 2)
#define KVTILE (FBK * QLD * 2)
#define KVSTG (3 * KVTILE)
#define OPH (OKV + 2 * KVSTG)
#define OSF (OPH + FBQ * PLD * 2)
#define OMR (OSF + FBQ * 128 * 4)
#define OLR (OMR + 256)
#define OAR (OLR + 256)
#define FA3_SMEM (OAR + 256)

__device__ __forceinline__ void fa_stage_load(
    char* smb, int s,
    const __half* ksh, const __half* vsh, const __half* vsl, int tid)
{
    char* st = smb + OKV + s * KVSTG;
    __half* sKh = (__half*)st;
    __half* sVh = (__half*)(st + KVTILE);
    __half* sVl = (__half*)(st + 2 * KVTILE);
    for (int i = 0; i < 4; i++) {
        int idx = tid + 256 * i;
        int r = idx >> 4;
        int c = (idx & 15) * 8;
        __pipeline_memcpy_async(sKh + r * QLD + c, ksh + (size_t)r * HD + c, 16);
        __pipeline_memcpy_async(sVh + r * QLD + c, vsh + (size_t)r * RANK + c, 16);
        __pipeline_memcpy_async(sVl + r * QLD + c, vsl + (size_t)r * RANK + c, 16);
    }
}

__global__ __launch_bounds__(256) void flash_mma(
    const __half* __restrict__ Qhi, const __half* __restrict__ Qlo,
    const __half* __restrict__ Khi,
    const __half* __restrict__ Vhi, const __half* __restrict__ Vlo,
    __half* __restrict__ Yh, __half* __restrict__ Yl)
{
    extern __shared__ char smb[];
    __half* sQh = (__half*)(smb + OQH);
    __half* sQl = (__half*)(smb + OQL);
    __half* sPh = (__half*)(smb + OPH);
    float* sSf  = (float*)(smb + OSF);
    float* sOd  = (float*)(smb + OSF);
    float* mrow = (float*)(smb + OMR);
    float* lrow = (float*)(smb + OLR);
    float* arow = (float*)(smb + OAR);

    const int tid  = threadIdx.x;
    const int warp = tid / 32;
    const int qt = (int)(gridDim.x - 1 - blockIdx.x);   // longest CTAs first
    const int h  = blockIdx.y;
    const int b  = blockIdx.z;
    const int kh = h >> 2;
    const int q0 = qt * FBQ;

    const __half* Kh0 = Khi + ((size_t)(b * NKVH + kh) * T_SEQ) * HD;
    const __half* Vh0 = Vhi + (size_t)b * T_SEQ * RANK + kh * HD;
    const __half* Vl0 = Vlo + (size_t)b * T_SEQ * RANK + kh * HD;

    const __half* qsh = Qhi + ((size_t)(b * NHEADS + h) * T_SEQ + q0) * HD;
    const __half* qsl = Qlo + ((size_t)(b * NHEADS + h) * T_SEQ + q0) * HD;
    for (int i = tid; i < FBQ * HD / 8; i += 256) {
        int r = i >> 4;
        int c = (i & 15) * 8;
        *(uint4*)(sQh + r * QLD + c) = *(const uint4*)(qsh + (size_t)r * HD + c);
        *(uint4*)(sQl + r * QLD + c) = *(const uint4*)(qsl + (size_t)r * HD + c);
    }
    if (tid < 64) {
        mrow[tid] = -1e30f;
        lrow[tid] = 0.f;
    }

    float o[32];
#pragma unroll
    for (int j = 0; j < 32; j++) o[j] = 0.f;

    const int ro = tid >> 2;
    const int cq = tid & 3;

    fa_stage_load(smb, 0, Kh0, Vh0, Vl0, tid);
    __pipeline_commit();
    __syncthreads();

    for (int kt = 0; kt <= qt; kt++) {
        const int k0 = kt * FBK;
        if (kt < qt) {
            int k1 = (kt + 1) * FBK;
            fa_stage_load(smb, (kt + 1) & 1,
                          Kh0 + (size_t)k1 * HD,
                          Vh0 + (size_t)k1 * RANK, Vl0 + (size_t)k1 * RANK, tid);
            __pipeline_commit();
            __pipeline_wait_prior(1);
        } else {
            __pipeline_wait_prior(0);
        }
        __syncthreads();

        char* stg = smb + OKV + (size_t)(kt & 1) * KVSTG;
        __half* sKh = (__half*)stg;
        __half* sVh = (__half*)(stg + KVTILE);
        __half* sVl = (__half*)(stg + 2 * KVTILE);

        // ---- S = Q K^T (fp16 2-pass: qh*k + ql*k) ----
        {
            const int wm  = warp % 4;
            const int wc0 = (warp / 4) * 2;
            nvcuda::wmma::fragment<nvcuda::wmma::accumulator, 16, 16, 16, float> accs[2];
            for (int j = 0; j < 2; j++) nvcuda::wmma::fill_fragment(accs[j], 0.0f);
            for (int ks = 0; ks < HD; ks += 16) {
                nvcuda::wmma::fragment<nvcuda::wmma::matrix_a, 16, 16, 16,
                                       __half, nvcuda::wmma::row_major> fah;
                nvcuda::wmma::fragment<nvcuda::wmma::matrix_a, 16, 16, 16,
                                       __half, nvcuda::wmma::row_major> fal;
                nvcuda::wmma::load_matrix_sync(fah, sQh + (wm * 16) * QLD + ks, QLD);
                nvcuda::wmma::load_matrix_sync(fal, sQl + (wm * 16) * QLD + ks, QLD);
                for (int j = 0; j < 2; j++) {
                    nvcuda::wmma::fragment<nvcuda::wmma::matrix_b, 16, 16, 16,
                                           __half, nvcuda::wmma::col_major> fbh;
                    nvcuda::wmma::load_matrix_sync(fbh, sKh + ((wc0 + j) * 16) * QLD + ks, QLD);
                    nvcuda::wmma::mma_sync(accs[j], fah, fbh, accs[j]);
                    nvcuda::wmma::mma_sync(accs[j], fal, fbh, accs[j]);
                }
            }
            for (int j = 0; j < 2; j++) {
                nvcuda::wmma::store_matrix_sync(sSf + (wm * 16) * SLD + (wc0 + j) * 16,
                                                accs[j], SLD, nvcuda::wmma::mem_row_major);
            }
        }
        __syncthreads();

        // ---- online softmax (4 threads per row) ----
        {
            const int r  = tid >> 2;
            const int qq = tid & 3;
            const int qg = q0 + r;
            float mold = mrow[r];
            float vals[16];
            float rmax = mold;
#pragma unroll
            for (int j = 0; j < 16; j++) {
                int c = qq + 4 * j;
                float v = sSf[r * SLD + c] * SCALE_F;
                if (k0 + c > qg) v = -1e30f;
                vals[j] = v;
                rmax = fmaxf(rmax, v);
            }
            rmax = fmaxf(rmax, __shfl_xor_sync(0xffffffffu, rmax, 1));
            rmax = fmaxf(rmax, __shfl_xor_sync(0xffffffffu, rmax, 2));
            float alpha = __expf(mold - rmax);
            float rsum = 0.f;
#pragma unroll
            for (int j = 0; j < 16; j++) {
                int c = qq + 4 * j;
                float p = __expf(vals[j] - rmax);
                sPh[r * PLD + c] = __float2half(p);
                rsum += p;
            }
            rsum += __shfl_xor_sync(0xffffffffu, rsum, 1);
            rsum += __shfl_xor_sync(0xffffffffu, rsum, 2);
            if (qq == 0) {
                lrow[r] = lrow[r] * alpha + rsum;
                mrow[r] = rmax;
                arow[r] = alpha;
            }
        }
        __syncthreads();

        // ---- O_delta = P V (fp16 2-pass: p*vh + p*vl) ----
        {
            const int wm  = warp % 4;
            const int wn0 = (warp / 4) * 4;
            nvcuda::wmma::fragment<nvcuda::wmma::accumulator, 16, 16, 16, float> accd[4];
            for (int j = 0; j < 4; j++) nvcuda::wmma::fill_fragment(accd[j], 0.0f);
            for (int kc = 0; kc < FBK; kc += 16) {
                nvcuda::wmma::fragment<nvcuda::wmma::matrix_a, 16, 16, 16,
                                       __half, nvcuda::wmma::row_major> pah;
                nvcuda::wmma::load_matrix_sync(pah, sPh + (wm * 16) * PLD + kc, PLD);
                for (int j = 0; j < 4; j++) {
                    nvcuda::wmma::fragment<nvcuda::wmma::matrix_b, 16, 16, 16,
                                           __half, nvcuda::wmma::row_major> vbh;
                    nvcuda::wmma::fragment<nvcuda::wmma::matrix_b, 16, 16, 16,
                                           __half, nvcuda::wmma::row_major> vbl;
                    nvcuda::wmma::load_matrix_sync(vbh, sVh + kc * QLD + (wn0 + j) * 16, QLD);
                    nvcuda::wmma::load_matrix_sync(vbl, sVl + kc * QLD + (wn0 + j) * 16, QLD);
                    nvcuda::wmma::mma_sync(accd[j], pah, vbh, accd[j]);
                    nvcuda::wmma::mma_sync(accd[j], pah, vbl, accd[j]);
                }
            }
            for (int j = 0; j < 4; j++) {
                nvcuda::wmma::store_matrix_sync(sOd + (wm * 16) * 128 + (wn0 + j) * 16,
                                                accd[j], 128, nvcuda::wmma::mem_row_major);
            }
        }
        __syncthreads();

        // ---- o = o * alpha + O_delta ----
        {
            float alpha = arow[ro];
            const float* od = sOd + ro * 128 + cq * 32;
#pragma unroll
            for (int j = 0; j < 32; j++) o[j] = o[j] * alpha + od[j];
        }
        __syncthreads();
    }

    float inv = 1.0f / lrow[ro];
    size_t yb = ((size_t)(b * T_SEQ) + q0 + ro) * DIM + h * HD + cq * 32;
#pragma unroll
    for (int j = 0; j < 32; j++) {
        float v = o[j] * inv;
        __half hv = __float2half(v);
        Yh[yb + j] = hv;
        Yl[yb + j] = __float2half(v - __half2float(hv));
    }
}

// ---------------- Launch ----------------
extern "C" void kernel_launch(void* const* d_in, const int* in_sizes, int n_in,
                              void* d_out, int out_size)
{
    (void)in_sizes;
    (void)n_in;
    (void)out_size;
    const float* x     = (const float*)d_in[0];
    const float* Wq    = (const float*)d_in[1];
    const float* Wdown = (const float*)d_in[2];
    const float* Wkup  = (const float*)d_in[3];
    const float* Wvup  = (const float*)d_in[4];
    const float* Wproj = (const float*)d_in[5];
    const float* qgain = (const float*)d_in[6];
    float* out = (float*)d_out;

    float* q;
    float* kt;
    float* vt;
    cudaGetSymbolAddress((void**)&q,  g_q);
    cudaGetSymbolAddress((void**)&kt, g_kt);
    cudaGetSymbolAddress((void**)&vt, g_vt);

    __half* xhi;
    __half* xlo;
    __half* lhi;
    __half* llo;
    __half* yhi;
    __half* ylo;
    __half* wqh;
    __half* wdh;
    __half* wkh;
    __half* wvh;
    __half* wph;
    cudaGetSymbolAddress((void**)&xhi, g_xhi);
    cudaGetSymbolAddress((void**)&xlo, g_xlo);
    cudaGetSymbolAddress((void**)&lhi, g_lhi);
    cudaGetSymbolAddress((void**)&llo, g_llo);
    cudaGetSymbolAddress((void**)&yhi, g_yhi);
    cudaGetSymbolAddress((void**)&ylo, g_ylo);
    cudaGetSymbolAddress((void**)&wqh, g_wqh);
    cudaGetSymbolAddress((void**)&wdh, g_wdh);
    cudaGetSymbolAddress((void**)&wkh, g_wkh);
    cudaGetSymbolAddress((void**)&wvh, g_wvh);
    cudaGetSymbolAddress((void**)&wph, g_wph);

    __half* qah;
    __half* qal;
    __half* kah;
    __half* vth;
    __half* vtl;
    cudaGetSymbolAddress((void**)&qah, g_qah);
    cudaGetSymbolAddress((void**)&qal, g_qal);
    cudaGetSymbolAddress((void**)&kah, g_kah);
    cudaGetSymbolAddress((void**)&vth, g_vth);
    cudaGetSymbolAddress((void**)&vtl, g_vtl);

    cudaFuncSetAttribute(gemm_h, cudaFuncAttributeMaxDynamicSharedMemorySize,
                         GSMEM_BYTES);
    cudaFuncSetAttribute(gemm_h_sp16, cudaFuncAttributeMaxDynamicSharedMemorySize,
                         GSMEM_BYTES);
    cudaFuncSetAttribute(flash_mma, cudaFuncAttributeMaxDynamicSharedMemorySize,
                         FA3_SMEM);

    int n1 = NE_MD;
    int n2 = NE_DD;
    int n3 = NE_RD;
    int n4 = NE_RR;
    int n5 = NE_MR;
    split_kernel_h<<<(n1 + 255) / 256, 256>>>(x, xhi, xlo, n1);
    conv_kernel_h<<<(n2 + 255) / 256, 256>>>(Wq, wqh, n2);
    conv_kernel_h<<<(n3 + 255) / 256, 256>>>(Wdown, wdh, n3);
    conv_kernel_h<<<(n4 + 255) / 256, 256>>>(Wkup, wkh, n4);
    conv_kernel_h<<<(n4 + 255) / 256, 256>>>(Wvup, wvh, n4);
    conv_kernel_h<<<(n2 + 255) / 256, 256>>>(Wproj, wph, n2);

    gemm_h_sp16<<<dim3(RANK / GBN, M_ROWS / GBM), 256, GSMEM_BYTES>>>(
        xhi, xlo, wdh, lhi, llo, M_ROWS, RANK, DIM);
    gemm_h<<<dim3(DIM / GBN, M_ROWS / GBM), 256, GSMEM_BYTES>>>(
        xhi, xlo, wqh, q, M_ROWS, DIM, DIM);
    gemm_h<<<dim3(RANK / GBN, M_ROWS / GBM), 256, GSMEM_BYTES>>>(
        lhi, llo, wkh, kt, M_ROWS, RANK, RANK);
    gemm_h<<<dim3(RANK / GBN, M_ROWS / GBM), 256, GSMEM_BYTES>>>(
        lhi, llo, wvh, vt, M_ROWS, RANK, RANK);

    rms_rope_kernel<<<dim3(M_ROWS, NHEADS), 128>>>(q, qah, qal, qgain, NHEADS);
    rms_rope_kernel<<<dim3(M_ROWS, NKVH), 128>>>(kt, kah, (__half*)0, (const float*)0, NKVH);
    split_kernel_h<<<(n5 + 255) / 256, 256>>>(vt, vth, vtl, n5);

    flash_mma<<<dim3(T_SEQ / FBQ, NHEADS, BATCH), 256, FA3_SMEM>>>(qah, qal, kah,
                                                                   vth, vtl, yhi, ylo);

    gemm_h<<<dim3(DIM / GBN, M_ROWS / GBM), 256, GSMEM_BYTES>>>(
        yhi, ylo, wph, out, M_ROWS, DIM, DIM);
}